// round 3
// baseline (speedup 1.0000x reference)
#include <cuda_runtime.h>
#include <math.h>

// ---------------------------------------------------------------------------
// Problem constants
// ---------------------------------------------------------------------------
#define S_LEN 2048
#define HID   4096
#define NH    32
#define NG    8
#define DH    128
// H*D = 4096, G*D = 1024

// Scratch (device globals: allocation-free rule)
__device__ float g_q[S_LEN * NH * DH];   // 2048 x 4096
__device__ float g_k[S_LEN * NG * DH];   // 2048 x 1024
__device__ float g_v[S_LEN * NG * DH];   // 2048 x 1024
__device__ float g_ctx[S_LEN * NH * DH]; // 2048 x 4096

// ---------------------------------------------------------------------------
// SGEMM: C[M,N] = A[M,K] @ B[K,N] + bias[N]
// BM=BN=128, BK=16, 256 threads, 8x8 micro-tile per thread.
// M,N multiples of 128; K multiple of 16 (true for all 4 calls).
// ---------------------------------------------------------------------------
__global__ __launch_bounds__(256, 2)
void sgemm_bias(const float* __restrict__ A, const float* __restrict__ B,
                const float* __restrict__ bias, float* __restrict__ C,
                int M, int N, int K) {
    __shared__ float As[16][128];
    __shared__ float Bs[16][128];

    const int tid = threadIdx.x;
    const int tr  = tid >> 4;          // 0..15 (row group)
    const int tc  = tid & 15;          // 0..15 (col group)
    const int row0 = blockIdx.y * 128;
    const int col0 = blockIdx.x * 128;

    const int a_row = tid >> 2;        // 0..63
    const int a_col = (tid & 3) << 2;  // 0,4,8,12
    const int b_row = tid >> 5;        // 0..7
    const int b_col = (tid & 31) << 2; // 0..124

    const float* Ap  = A + (size_t)(row0 + a_row) * K + a_col;
    const float* Ap2 = Ap + (size_t)64 * K;
    const float* Bp  = B + (size_t)b_row * N + col0 + b_col;
    const float* Bp2 = Bp + (size_t)8 * N;

    float acc[8][8];
#pragma unroll
    for (int i = 0; i < 8; i++)
#pragma unroll
        for (int j = 0; j < 8; j++) acc[i][j] = 0.f;

    for (int k0 = 0; k0 < K; k0 += 16) {
        float4 a0 = *(const float4*)(Ap  + k0);
        float4 a1 = *(const float4*)(Ap2 + k0);
        float4 b0 = *(const float4*)(Bp  + (size_t)k0 * N);
        float4 b1 = *(const float4*)(Bp2 + (size_t)k0 * N);

        __syncthreads();  // previous iteration's smem reads complete
        As[a_col + 0][a_row] = a0.x;
        As[a_col + 1][a_row] = a0.y;
        As[a_col + 2][a_row] = a0.z;
        As[a_col + 3][a_row] = a0.w;
        As[a_col + 0][a_row + 64] = a1.x;
        As[a_col + 1][a_row + 64] = a1.y;
        As[a_col + 2][a_row + 64] = a1.z;
        As[a_col + 3][a_row + 64] = a1.w;
        *(float4*)&Bs[b_row][b_col]     = b0;
        *(float4*)&Bs[b_row + 8][b_col] = b1;
        __syncthreads();

#pragma unroll
        for (int kk = 0; kk < 16; kk++) {
            float ar[8], br[8];
            *(float4*)&ar[0] = *(const float4*)&As[kk][tr * 8];
            *(float4*)&ar[4] = *(const float4*)&As[kk][tr * 8 + 4];
            *(float4*)&br[0] = *(const float4*)&Bs[kk][tc * 8];
            *(float4*)&br[4] = *(const float4*)&Bs[kk][tc * 8 + 4];
#pragma unroll
            for (int i = 0; i < 8; i++)
#pragma unroll
                for (int j = 0; j < 8; j++)
                    acc[i][j] = fmaf(ar[i], br[j], acc[i][j]);
        }
    }

    float4 bias0 = *(const float4*)&bias[col0 + tc * 8];
    float4 bias1 = *(const float4*)&bias[col0 + tc * 8 + 4];
#pragma unroll
    for (int i = 0; i < 8; i++) {
        int r = row0 + tr * 8 + i;
        float4 o0 = make_float4(acc[i][0] + bias0.x, acc[i][1] + bias0.y,
                                acc[i][2] + bias0.z, acc[i][3] + bias0.w);
        float4 o1 = make_float4(acc[i][4] + bias1.x, acc[i][5] + bias1.y,
                                acc[i][6] + bias1.z, acc[i][7] + bias1.w);
        float* Crow = C + (size_t)r * N + col0 + tc * 8;
        *(float4*)(Crow)     = o0;
        *(float4*)(Crow + 4) = o1;
    }
}

// ---------------------------------------------------------------------------
// RoPE (in-place on q and k). One thread per (s, j), loops over all heads.
// inv_freq in double (correctly rounded), angle product in fp32 to match ref.
// ---------------------------------------------------------------------------
__global__ void rope_kernel(float* __restrict__ q, float* __restrict__ k) {
    int idx = blockIdx.x * blockDim.x + threadIdx.x;  // s*64 + j
    if (idx >= S_LEN * 64) return;
    int j = idx & 63;
    int s = idx >> 6;

    // inv_freq = 10000^{-j/64}, computed in double then rounded to float
    float inv = (float)exp(-(double)j * (9.210340371976184 / 64.0));
    float ang = (float)s * inv;
    float sn, cs;
    sincosf(ang, &sn, &cs);

    float* qb = q + (size_t)s * (NH * DH) + j;
#pragma unroll
    for (int h = 0; h < NH; h++) {
        float x1 = qb[h * DH];
        float x2 = qb[h * DH + 64];
        qb[h * DH]      = x1 * cs - x2 * sn;
        qb[h * DH + 64] = x1 * sn + x2 * cs;
    }
    float* kb = k + (size_t)s * (NG * DH) + j;
#pragma unroll
    for (int h = 0; h < NG; h++) {
        float x1 = kb[h * DH];
        float x2 = kb[h * DH + 64];
        kb[h * DH]      = x1 * cs - x2 * sn;
        kb[h * DH + 64] = x1 * sn + x2 * cs;
    }
}

// ---------------------------------------------------------------------------
// Flash attention, fp32, causal, GQA (4 query heads per kv head).
// Grid: (S/64, NH). Block: 256 threads.
// smem: Qs[128][68] (Q^T, pre-scaled), Ks[128][68] (K^T, aliased by Pt[64][65]
// after QK), Vs[64][128]. Total 102400 B -> 2 CTAs/SM.
// Thread map: ty = tid/8 (owns 2 query rows), tx = tid%8.
// QK micro-tile 2x8 (cols = keys), PV micro-tile 2x16 (cols = head dim).
// ---------------------------------------------------------------------------
#define ATT_SMEM_FLOATS (128 * 68 + 128 * 68 + 64 * 128)
#define ATT_SMEM_BYTES  (ATT_SMEM_FLOATS * 4)

__global__ __launch_bounds__(256, 2)
void attn_kernel(const float* __restrict__ q, const float* __restrict__ k,
                 const float* __restrict__ v, float* __restrict__ ctx) {
    const int qb = blockIdx.x;         // query tile (64 rows)
    const int h  = blockIdx.y;         // query head
    const int g  = h >> 2;             // kv head (R = 4)
    const int q0 = qb * 64;

    extern __shared__ float sm[];
    float* Qs = sm;                    // [128][68]  Q transposed
    float* Ks = sm + 128 * 68;         // [128][68]  K transposed
    float* Vs = sm + 2 * 128 * 68;     // [64][128]
    float* Pt = Ks;                    // [64][65]   alias (safe: synced)

    const int tid = threadIdx.x;
    const int tx = tid & 7;            // 0..7
    const int ty = tid >> 3;           // 0..31
    const float scale = 0.08838834764831845f;  // 1/sqrt(128)

    // Load Q tile transposed + pre-scaled: Qs[d][r]
    for (int idx = tid; idx < 64 * DH; idx += 256) {
        int r = idx >> 7;
        int d = idx & 127;
        Qs[d * 68 + r] = q[(size_t)(q0 + r) * (NH * DH) + h * DH + d] * scale;
    }

    float m_run[2] = {-1e30f, -1e30f};
    float l_run[2] = {0.f, 0.f};
    float acc[2][16];
#pragma unroll
    for (int i = 0; i < 2; i++)
#pragma unroll
        for (int j = 0; j < 16; j++) acc[i][j] = 0.f;

    const int ktiles = qb + 1;
    for (int kt = 0; kt < ktiles; kt++) {
        const int k0 = kt * 64;
        __syncthreads();  // prev PV reads (Pt,Vs) done; also covers Q load

        // Load K transposed and V natural
        for (int idx = tid; idx < 64 * DH; idx += 256) {
            int r = idx >> 7;
            int d = idx & 127;
            float kv = k[(size_t)(k0 + r) * (NG * DH) + g * DH + d];
            Ks[d * 68 + r] = kv;
            Vs[idx]        = v[(size_t)(k0 + r) * (NG * DH) + g * DH + d];
        }
        __syncthreads();

        // ---- QK^T: rows r = ty*2+{0,1}, cols c = tx*8+{0..7} ----
        float sreg[2][8];
#pragma unroll
        for (int i = 0; i < 2; i++)
#pragma unroll
            for (int j = 0; j < 8; j++) sreg[i][j] = 0.f;

#pragma unroll 4
        for (int kk = 0; kk < DH; kk++) {
            float q0v = Qs[kk * 68 + ty * 2];
            float q1v = Qs[kk * 68 + ty * 2 + 1];
            float kvv[8];
#pragma unroll
            for (int j = 0; j < 8; j++) kvv[j] = Ks[kk * 68 + tx * 8 + j];
#pragma unroll
            for (int j = 0; j < 8; j++) {
                sreg[0][j] = fmaf(q0v, kvv[j], sreg[0][j]);
                sreg[1][j] = fmaf(q1v, kvv[j], sreg[1][j]);
            }
        }

        // Causal mask
#pragma unroll
        for (int i = 0; i < 2; i++) {
            int qi = q0 + ty * 2 + i;
#pragma unroll
            for (int j = 0; j < 8; j++) {
                int kj = k0 + tx * 8 + j;
                if (kj > qi) sreg[i][j] = -1e30f;
            }
        }

        // Online softmax update (row group = 8 consecutive lanes, same ty)
#pragma unroll
        for (int i = 0; i < 2; i++) {
            float m = sreg[i][0];
#pragma unroll
            for (int j = 1; j < 8; j++) m = fmaxf(m, sreg[i][j]);
            m = fmaxf(m, __shfl_xor_sync(0xffffffffu, m, 1));
            m = fmaxf(m, __shfl_xor_sync(0xffffffffu, m, 2));
            m = fmaxf(m, __shfl_xor_sync(0xffffffffu, m, 4));
            float m_new = fmaxf(m_run[i], m);
            float corr  = __expf(m_run[i] - m_new);
            float rs = 0.f;
#pragma unroll
            for (int j = 0; j < 8; j++) {
                float p = __expf(sreg[i][j] - m_new);
                sreg[i][j] = p;
                rs += p;
            }
            rs += __shfl_xor_sync(0xffffffffu, rs, 1);
            rs += __shfl_xor_sync(0xffffffffu, rs, 2);
            rs += __shfl_xor_sync(0xffffffffu, rs, 4);
            l_run[i] = l_run[i] * corr + rs;
            m_run[i] = m_new;
#pragma unroll
            for (int j = 0; j < 16; j++) acc[i][j] *= corr;
        }

        __syncthreads();  // all Ks reads done before overwriting with Pt

        // Write P transposed: Pt[key][row]
#pragma unroll
        for (int i = 0; i < 2; i++)
#pragma unroll
            for (int j = 0; j < 8; j++)
                Pt[(tx * 8 + j) * 65 + ty * 2 + i] = sreg[i][j];
        __syncthreads();

        // ---- PV: acc[r][c] += sum_t P[r][t] * V[t][c], c = tx*16+{0..15} ----
#pragma unroll 2
        for (int t = 0; t < 64; t++) {
            float p0 = Pt[t * 65 + ty * 2];
            float p1 = Pt[t * 65 + ty * 2 + 1];
            float vv[16];
#pragma unroll
            for (int j = 0; j < 4; j++)
                *(float4*)&vv[j * 4] = *(const float4*)&Vs[t * 128 + tx * 16 + j * 4];
#pragma unroll
            for (int j = 0; j < 16; j++) {
                acc[0][j] = fmaf(p0, vv[j], acc[0][j]);
                acc[1][j] = fmaf(p1, vv[j], acc[1][j]);
            }
        }
    }

    // Epilogue: normalize, write ctx[s, h*128 + d]
#pragma unroll
    for (int i = 0; i < 2; i++) {
        float inv = 1.f / l_run[i];
        int r = q0 + ty * 2 + i;
        float* crow = ctx + (size_t)r * (NH * DH) + h * DH + tx * 16;
#pragma unroll
        for (int j = 0; j < 16; j++) crow[j] = acc[i][j] * inv;
    }
}

// ---------------------------------------------------------------------------
// Launch
// ---------------------------------------------------------------------------
extern "C" void kernel_launch(void* const* d_in, const int* in_sizes, int n_in,
                              void* d_out, int out_size) {
    const float* X  = (const float*)d_in[0];
    const float* Wq = (const float*)d_in[1];
    const float* bq = (const float*)d_in[2];
    const float* Wk = (const float*)d_in[3];
    const float* bk = (const float*)d_in[4];
    const float* Wv = (const float*)d_in[5];
    const float* bv = (const float*)d_in[6];
    const float* Wo = (const float*)d_in[7];
    const float* bo = (const float*)d_in[8];
    float* out = (float*)d_out;

    void *qv, *kv, *vv, *cv;
    cudaGetSymbolAddress(&qv, g_q);
    cudaGetSymbolAddress(&kv, g_k);
    cudaGetSymbolAddress(&vv, g_v);
    cudaGetSymbolAddress(&cv, g_ctx);
    float* qp = (float*)qv;
    float* kp = (float*)kv;
    float* vp = (float*)vv;
    float* cp = (float*)cv;

    // QKV projections
    sgemm_bias<<<dim3(NH * DH / 128, S_LEN / 128), 256>>>(X, Wq, bq, qp, S_LEN, NH * DH, HID);
    sgemm_bias<<<dim3(NG * DH / 128, S_LEN / 128), 256>>>(X, Wk, bk, kp, S_LEN, NG * DH, HID);
    sgemm_bias<<<dim3(NG * DH / 128, S_LEN / 128), 256>>>(X, Wv, bv, vp, S_LEN, NG * DH, HID);

    // RoPE on q and k
    rope_kernel<<<(S_LEN * 64 + 255) / 256, 256>>>(qp, kp);

    // Attention
    cudaFuncSetAttribute(attn_kernel, cudaFuncAttributeMaxDynamicSharedMemorySize,
                         ATT_SMEM_BYTES);
    attn_kernel<<<dim3(S_LEN / 64, NH), 256, ATT_SMEM_BYTES>>>(qp, kp, vp, cp);

    // Output projection
    sgemm_bias<<<dim3(HID / 128, S_LEN / 128), 256>>>(cp, Wo, bo, out, S_LEN, HID, HID);
}

// round 6
// speedup vs baseline: 1.3673x; 1.3673x over previous
#include <cuda.h>
#include <cuda_runtime.h>
#include <cuda_bf16.h>
#include <math.h>

// ---------------------------------------------------------------------------
// Problem constants
// ---------------------------------------------------------------------------
#define S_LEN 2048
#define HID   4096
#define NH    32
#define NG    8
#define DH    128

// ---------------------------------------------------------------------------
// Device-global scratch (allocation-free rule)
// ---------------------------------------------------------------------------
__device__ __align__(16) float g_q[S_LEN * NH * DH];
__device__ __align__(16) float g_k[S_LEN * NG * DH];
__device__ __align__(16) float g_v[S_LEN * NG * DH];
__device__ __align__(16) float g_ctx[S_LEN * NH * DH];

__device__ __align__(16) __nv_bfloat16 g_xhi[S_LEN * HID];
__device__ __align__(16) __nv_bfloat16 g_xlo[S_LEN * HID];
__device__ __align__(16) __nv_bfloat16 g_chi[S_LEN * HID];
__device__ __align__(16) __nv_bfloat16 g_clo[S_LEN * HID];
__device__ __align__(16) __nv_bfloat16 g_wqh[HID * HID];        // Wq^T [4096,4096]
__device__ __align__(16) __nv_bfloat16 g_wql[HID * HID];
__device__ __align__(16) __nv_bfloat16 g_wkh[NG * DH * HID];    // Wk^T [1024,4096]
__device__ __align__(16) __nv_bfloat16 g_wkl[NG * DH * HID];
__device__ __align__(16) __nv_bfloat16 g_wvh[NG * DH * HID];
__device__ __align__(16) __nv_bfloat16 g_wvl[NG * DH * HID];
__device__ __align__(16) __nv_bfloat16 g_woh[HID * HID];        // Wo^T [4096,4096]
__device__ __align__(16) __nv_bfloat16 g_wol[HID * HID];

// ---------------------------------------------------------------------------
// PTX helpers (sm_80-baseline only: ldmatrix / mma.sync / cp.async)
// ---------------------------------------------------------------------------
__device__ __forceinline__ uint32_t smem_u32(const void* p) {
    uint32_t a;
    asm("{ .reg .u64 t; cvta.to.shared.u64 t, %1; cvt.u32.u64 %0, t; }"
        : "=r"(a) : "l"(p));
    return a;
}

__device__ __forceinline__ void ldsm4(uint32_t& r0, uint32_t& r1, uint32_t& r2,
                                      uint32_t& r3, uint32_t addr) {
    asm volatile("ldmatrix.sync.aligned.m8n8.x4.shared.b16 {%0,%1,%2,%3}, [%4];"
                 : "=r"(r0), "=r"(r1), "=r"(r2), "=r"(r3) : "r"(addr));
}

__device__ __forceinline__ void mma16816(float* d, uint32_t a0, uint32_t a1,
                                         uint32_t a2, uint32_t a3,
                                         uint32_t b0, uint32_t b1) {
    asm volatile(
        "mma.sync.aligned.m16n8k16.row.col.f32.bf16.bf16.f32 "
        "{%0,%1,%2,%3}, {%4,%5,%6,%7}, {%8,%9}, {%0,%1,%2,%3};"
        : "+f"(d[0]), "+f"(d[1]), "+f"(d[2]), "+f"(d[3])
        : "r"(a0), "r"(a1), "r"(a2), "r"(a3), "r"(b0), "r"(b1));
}

#define CP_ASYNC16(smem_addr, gptr) \
    asm volatile("cp.async.cg.shared.global [%0], [%1], 16;" \
                 :: "r"(smem_addr), "l"(gptr))
#define CP_COMMIT() asm volatile("cp.async.commit_group;" ::: "memory")
#define CP_WAIT0()  asm volatile("cp.async.wait_group 0;" ::: "memory")
#define CP_WAIT1()  asm volatile("cp.async.wait_group 1;" ::: "memory")

// ---------------------------------------------------------------------------
// Split fp32 -> (hi, lo) bf16, same layout. n4 = n/4 float4s.
// ---------------------------------------------------------------------------
__global__ void split2(const float4* __restrict__ src, __nv_bfloat162* __restrict__ hi,
                       __nv_bfloat162* __restrict__ lo, int n4) {
    int i = blockIdx.x * blockDim.x + threadIdx.x;
    if (i >= n4) return;
    float4 v = src[i];
    __nv_bfloat16 h0 = __float2bfloat16(v.x), h1 = __float2bfloat16(v.y);
    __nv_bfloat16 h2 = __float2bfloat16(v.z), h3 = __float2bfloat16(v.w);
    hi[2 * i]     = __halves2bfloat162(h0, h1);
    hi[2 * i + 1] = __halves2bfloat162(h2, h3);
    lo[2 * i]     = __halves2bfloat162(__float2bfloat16(v.x - __bfloat162float(h0)),
                                       __float2bfloat16(v.y - __bfloat162float(h1)));
    lo[2 * i + 1] = __halves2bfloat162(__float2bfloat16(v.z - __bfloat162float(h2)),
                                       __float2bfloat16(v.w - __bfloat162float(h3)));
}

// ---------------------------------------------------------------------------
// Split + transpose: W[K,N] fp32 -> Th,Tl [N,K] bf16. Block 32x8, tile 32x32.
// ---------------------------------------------------------------------------
__global__ void split_transpose(const float* __restrict__ W, __nv_bfloat16* __restrict__ Th,
                                __nv_bfloat16* __restrict__ Tl, int K, int N) {
    __shared__ float t[32][33];
    int x = blockIdx.x * 32;   // N offset
    int y = blockIdx.y * 32;   // K offset
    int tx = threadIdx.x, ty = threadIdx.y;
#pragma unroll
    for (int j = 0; j < 4; j++)
        t[ty + j * 8][tx] = W[(size_t)(y + ty + j * 8) * N + x + tx];
    __syncthreads();
#pragma unroll
    for (int j = 0; j < 4; j++) {
        float v = t[tx][ty + j * 8];
        __nv_bfloat16 h = __float2bfloat16(v);
        float r = v - __bfloat162float(h);
        size_t o = (size_t)(x + ty + j * 8) * K + y + tx;
        Th[o] = h;
        Tl[o] = __float2bfloat16(r);
    }
}

// ---------------------------------------------------------------------------
// HMMA bf16 GEMM (3xBF16 split): C[M,N] = (Ahi+Alo) @ (Bhi+Blo)^T + bias
//   A: [M,K] bf16 hi/lo (row-major, K contiguous)
//   B: [N,K] bf16 hi/lo (row-major, K contiguous) == col-major k x n for mma
// CTA tile 128x128, 8 warps (2x4), warp tile 64x32, BK=32.
// Double-buffered smem via cp.async. Padded rows: 32+8 bf16 = 80 B.
// smem stage: sAh 10240 | sAl 10240 | sBh 10240 | sBl 10240  = 40960 B
// total 81920 B (dynamic) -> 2 CTAs/SM.
// ---------------------------------------------------------------------------
#define ROWB 80                      // bytes per padded smem row (32 bf16 + 8 pad)
#define STAGE_BYTES (4 * 128 * ROWB) // 40960
#define GEMM_SMEM_BYTES (2 * STAGE_BYTES)

__global__ __launch_bounds__(256, 2)
void mma_gemm(const __nv_bfloat16* __restrict__ Ahi, const __nv_bfloat16* __restrict__ Alo,
              const __nv_bfloat16* __restrict__ Bhi, const __nv_bfloat16* __restrict__ Blo,
              const float* __restrict__ bias, float* __restrict__ C,
              int M, int N, int K) {
    extern __shared__ char smc[];
    const uint32_t sb = smem_u32(smc);
    const int tid  = threadIdx.x;
    const int w    = tid >> 5, lane = tid & 31;
    const int wm   = w >> 2;          // 0..1  -> m offset wm*64
    const int wn   = w & 3;           // 0..3  -> n offset wn*32
    const int m0   = blockIdx.y * 128;
    const int n0   = blockIdx.x * 128;

    // cp.async geometry: 128 rows x 32 bf16 = 512 x 16B per matrix; 2 per thread.
    // i = tid + t*256 : row = i>>2 (0..127), u = i&3 (16B unit within row)
    size_t ga[2], gb[2];
    uint32_t so[2];
#pragma unroll
    for (int t = 0; t < 2; t++) {
        int i = tid + t * 256;
        int row = i >> 2, u = i & 3;
        ga[t] = (size_t)(m0 + row) * K + u * 8;
        gb[t] = (size_t)(n0 + row) * K + u * 8;
        so[t] = (uint32_t)(row * ROWB + u * 16);
    }

    const int NC = K >> 5;            // 32-wide K chunks

    // Prologue: stage chunk 0 into buffer 0
    {
#pragma unroll
        for (int t = 0; t < 2; t++) {
            CP_ASYNC16(sb + so[t],              (const char*)(Ahi + ga[t]));
            CP_ASYNC16(sb + 10240 + so[t],      (const char*)(Alo + ga[t]));
            CP_ASYNC16(sb + 20480 + so[t],      (const char*)(Bhi + gb[t]));
            CP_ASYNC16(sb + 30720 + so[t],      (const char*)(Blo + gb[t]));
        }
        CP_COMMIT();
    }

    float acc[4][4][4];
#pragma unroll
    for (int mi = 0; mi < 4; mi++)
#pragma unroll
        for (int ni = 0; ni < 4; ni++)
#pragma unroll
            for (int j = 0; j < 4; j++) acc[mi][ni][j] = 0.f;

    // ldmatrix lane addressing: lr = lane&15 (row within 16), lc = lane>>4 (k-block)
    const int lr = lane & 15, lc = lane >> 4;
    // A tile (mi, ks): row = wm*64 + mi*16 + lr, byte = row*ROWB + ks*32 + lc*16
    // B tile (ni16, ks): row = wn*32 + ni16*16 + lr
    const uint32_t a_lane_off = (uint32_t)((wm * 64 + lr) * ROWB + lc * 16);
    const uint32_t b_lane_off = (uint32_t)((wn * 32 + lr) * ROWB + lc * 16);

    for (int c = 0; c < NC; c++) {
        const int buf = c & 1;
        if (c + 1 < NC) {
            const size_t kc = (size_t)(c + 1) << 5;
            const uint32_t dst = sb + (uint32_t)((c + 1) & 1) * STAGE_BYTES;
#pragma unroll
            for (int t = 0; t < 2; t++) {
                CP_ASYNC16(dst + so[t],         (const char*)(Ahi + ga[t] + kc));
                CP_ASYNC16(dst + 10240 + so[t], (const char*)(Alo + ga[t] + kc));
                CP_ASYNC16(dst + 20480 + so[t], (const char*)(Bhi + gb[t] + kc));
                CP_ASYNC16(dst + 30720 + so[t], (const char*)(Blo + gb[t] + kc));
            }
            CP_COMMIT();
            CP_WAIT1();
        } else {
            CP_WAIT0();
        }
        __syncthreads();

        const uint32_t base = sb + (uint32_t)buf * STAGE_BYTES;
#pragma unroll
        for (int ks = 0; ks < 2; ks++) {
            const uint32_t koff = (uint32_t)(ks * 32);
            // B fragments: bh/bl[ni][2]
            uint32_t bh[4][2], bl[4][2];
#pragma unroll
            for (int ni16 = 0; ni16 < 2; ni16++) {
                uint32_t addr = base + 20480 + b_lane_off + (uint32_t)(ni16 * 16 * ROWB) + koff;
                uint32_t r0, r1, r2, r3;
                ldsm4(r0, r1, r2, r3, addr);
                bh[ni16 * 2][0] = r0; bh[ni16 * 2][1] = r2;
                bh[ni16 * 2 + 1][0] = r1; bh[ni16 * 2 + 1][1] = r3;
                ldsm4(r0, r1, r2, r3, addr + 10240);
                bl[ni16 * 2][0] = r0; bl[ni16 * 2][1] = r2;
                bl[ni16 * 2 + 1][0] = r1; bl[ni16 * 2 + 1][1] = r3;
            }
#pragma unroll
            for (int mi = 0; mi < 4; mi++) {
                uint32_t addr = base + a_lane_off + (uint32_t)(mi * 16 * ROWB) + koff;
                uint32_t ah0, ah1, ah2, ah3, al0, al1, al2, al3;
                ldsm4(ah0, ah1, ah2, ah3, addr);
                ldsm4(al0, al1, al2, al3, addr + 10240);
#pragma unroll
                for (int ni = 0; ni < 4; ni++) {
                    mma16816(acc[mi][ni], ah0, ah1, ah2, ah3, bh[ni][0], bh[ni][1]);
                    mma16816(acc[mi][ni], ah0, ah1, ah2, ah3, bl[ni][0], bl[ni][1]);
                    mma16816(acc[mi][ni], al0, al1, al2, al3, bh[ni][0], bh[ni][1]);
                }
            }
        }
        __syncthreads();
    }

    // Epilogue: d0,d1 -> row lane>>2, cols 2*(lane&3)+{0,1}; d2,d3 -> row+8
#pragma unroll
    for (int mi = 0; mi < 4; mi++) {
#pragma unroll
        for (int ni = 0; ni < 4; ni++) {
            int m = m0 + wm * 64 + mi * 16 + (lane >> 2);
            int n = n0 + wn * 32 + ni * 8 + 2 * (lane & 3);
            float2 bv = *(const float2*)&bias[n];
            float2 o0 = make_float2(acc[mi][ni][0] + bv.x, acc[mi][ni][1] + bv.y);
            float2 o1 = make_float2(acc[mi][ni][2] + bv.x, acc[mi][ni][3] + bv.y);
            *(float2*)&C[(size_t)m * N + n]       = o0;
            *(float2*)&C[(size_t)(m + 8) * N + n] = o1;
        }
    }
}

// ---------------------------------------------------------------------------
// RoPE (in-place on q and k).
// ---------------------------------------------------------------------------
__global__ void rope_kernel(float* __restrict__ q, float* __restrict__ k) {
    int idx = blockIdx.x * blockDim.x + threadIdx.x;
    if (idx >= S_LEN * 64) return;
    int j = idx & 63;
    int s = idx >> 6;
    float inv = (float)exp(-(double)j * (9.210340371976184 / 64.0));
    float ang = (float)s * inv;
    float sn, cs;
    sincosf(ang, &sn, &cs);
    float* qb = q + (size_t)s * (NH * DH) + j;
#pragma unroll
    for (int h = 0; h < NH; h++) {
        float x1 = qb[h * DH];
        float x2 = qb[h * DH + 64];
        qb[h * DH]      = x1 * cs - x2 * sn;
        qb[h * DH + 64] = x1 * sn + x2 * cs;
    }
    float* kb = k + (size_t)s * (NG * DH) + j;
#pragma unroll
    for (int h = 0; h < NG; h++) {
        float x1 = kb[h * DH];
        float x2 = kb[h * DH + 64];
        kb[h * DH]      = x1 * cs - x2 * sn;
        kb[h * DH + 64] = x1 * sn + x2 * cs;
    }
}

// ---------------------------------------------------------------------------
// Flash attention fp32, causal, GQA — proven in round 2 (rel_err 4.9e-6).
// ---------------------------------------------------------------------------
#define ATT_SMEM_FLOATS (128 * 68 + 128 * 68 + 64 * 128)
#define ATT_SMEM_BYTES  (ATT_SMEM_FLOATS * 4)

__global__ __launch_bounds__(256, 2)
void attn_kernel(const float* __restrict__ q, const float* __restrict__ k,
                 const float* __restrict__ v, float* __restrict__ ctx) {
    const int qb = blockIdx.x;
    const int h  = blockIdx.y;
    const int g  = h >> 2;
    const int q0 = qb * 64;

    extern __shared__ float sm[];
    float* Qs = sm;
    float* Ks = sm + 128 * 68;
    float* Vs = sm + 2 * 128 * 68;
    float* Pt = Ks;

    const int tid = threadIdx.x;
    const int tx = tid & 7;
    const int ty = tid >> 3;
    const float scale = 0.08838834764831845f;

    for (int idx = tid; idx < 64 * DH; idx += 256) {
        int r = idx >> 7;
        int d = idx & 127;
        Qs[d * 68 + r] = q[(size_t)(q0 + r) * (NH * DH) + h * DH + d] * scale;
    }

    float m_run[2] = {-1e30f, -1e30f};
    float l_run[2] = {0.f, 0.f};
    float acc[2][16];
#pragma unroll
    for (int i = 0; i < 2; i++)
#pragma unroll
        for (int j = 0; j < 16; j++) acc[i][j] = 0.f;

    const int ktiles = qb + 1;
    for (int kt = 0; kt < ktiles; kt++) {
        const int k0 = kt * 64;
        __syncthreads();

        for (int idx = tid; idx < 64 * DH; idx += 256) {
            int r = idx >> 7;
            int d = idx & 127;
            float kv = k[(size_t)(k0 + r) * (NG * DH) + g * DH + d];
            Ks[d * 68 + r] = kv;
            Vs[idx]        = v[(size_t)(k0 + r) * (NG * DH) + g * DH + d];
        }
        __syncthreads();

        float sreg[2][8];
#pragma unroll
        for (int i = 0; i < 2; i++)
#pragma unroll
            for (int j = 0; j < 8; j++) sreg[i][j] = 0.f;

#pragma unroll 4
        for (int kk = 0; kk < DH; kk++) {
            float q0v = Qs[kk * 68 + ty * 2];
            float q1v = Qs[kk * 68 + ty * 2 + 1];
            float kvv[8];
#pragma unroll
            for (int j = 0; j < 8; j++) kvv[j] = Ks[kk * 68 + tx * 8 + j];
#pragma unroll
            for (int j = 0; j < 8; j++) {
                sreg[0][j] = fmaf(q0v, kvv[j], sreg[0][j]);
                sreg[1][j] = fmaf(q1v, kvv[j], sreg[1][j]);
            }
        }

#pragma unroll
        for (int i = 0; i < 2; i++) {
            int qi = q0 + ty * 2 + i;
#pragma unroll
            for (int j = 0; j < 8; j++) {
                int kj = k0 + tx * 8 + j;
                if (kj > qi) sreg[i][j] = -1e30f;
            }
        }

#pragma unroll
        for (int i = 0; i < 2; i++) {
            float m = sreg[i][0];
#pragma unroll
            for (int j = 1; j < 8; j++) m = fmaxf(m, sreg[i][j]);
            m = fmaxf(m, __shfl_xor_sync(0xffffffffu, m, 1));
            m = fmaxf(m, __shfl_xor_sync(0xffffffffu, m, 2));
            m = fmaxf(m, __shfl_xor_sync(0xffffffffu, m, 4));
            float m_new = fmaxf(m_run[i], m);
            float corr  = __expf(m_run[i] - m_new);
            float rs = 0.f;
#pragma unroll
            for (int j = 0; j < 8; j++) {
                float p = __expf(sreg[i][j] - m_new);
                sreg[i][j] = p;
                rs += p;
            }
            rs += __shfl_xor_sync(0xffffffffu, rs, 1);
            rs += __shfl_xor_sync(0xffffffffu, rs, 2);
            rs += __shfl_xor_sync(0xffffffffu, rs, 4);
            l_run[i] = l_run[i] * corr + rs;
            m_run[i] = m_new;
#pragma unroll
            for (int j = 0; j < 16; j++) acc[i][j] *= corr;
        }

        __syncthreads();

#pragma unroll
        for (int i = 0; i < 2; i++)
#pragma unroll
            for (int j = 0; j < 8; j++)
                Pt[(tx * 8 + j) * 65 + ty * 2 + i] = sreg[i][j];
        __syncthreads();

#pragma unroll 2
        for (int t = 0; t < 64; t++) {
            float p0 = Pt[t * 65 + ty * 2];
            float p1 = Pt[t * 65 + ty * 2 + 1];
            float vv[16];
#pragma unroll
            for (int j = 0; j < 4; j++)
                *(float4*)&vv[j * 4] = *(const float4*)&Vs[t * 128 + tx * 16 + j * 4];
#pragma unroll
            for (int j = 0; j < 16; j++) {
                acc[0][j] = fmaf(p0, vv[j], acc[0][j]);
                acc[1][j] = fmaf(p1, vv[j], acc[1][j]);
            }
        }
    }

#pragma unroll
    for (int i = 0; i < 2; i++) {
        float inv = 1.f / l_run[i];
        int r = q0 + ty * 2 + i;
        float* crow = ctx + (size_t)r * (NH * DH) + h * DH + tx * 16;
#pragma unroll
        for (int j = 0; j < 16; j++) crow[j] = acc[i][j] * inv;
    }
}

// ---------------------------------------------------------------------------
// Launch
// ---------------------------------------------------------------------------
extern "C" void kernel_launch(void* const* d_in, const int* in_sizes, int n_in,
                              void* d_out, int out_size) {
    const float* X  = (const float*)d_in[0];
    const float* Wq = (const float*)d_in[1];
    const float* bq = (const float*)d_in[2];
    const float* Wk = (const float*)d_in[3];
    const float* bk = (const float*)d_in[4];
    const float* Wv = (const float*)d_in[5];
    const float* bv = (const float*)d_in[6];
    const float* Wo = (const float*)d_in[7];
    const float* bo = (const float*)d_in[8];
    float* out = (float*)d_out;

    void *p;
    cudaGetSymbolAddress(&p, g_q);   float* qp = (float*)p;
    cudaGetSymbolAddress(&p, g_k);   float* kp = (float*)p;
    cudaGetSymbolAddress(&p, g_v);   float* vp = (float*)p;
    cudaGetSymbolAddress(&p, g_ctx); float* cp = (float*)p;
    cudaGetSymbolAddress(&p, g_xhi); __nv_bfloat16* xhi = (__nv_bfloat16*)p;
    cudaGetSymbolAddress(&p, g_xlo); __nv_bfloat16* xlo = (__nv_bfloat16*)p;
    cudaGetSymbolAddress(&p, g_chi); __nv_bfloat16* chi = (__nv_bfloat16*)p;
    cudaGetSymbolAddress(&p, g_clo); __nv_bfloat16* clo = (__nv_bfloat16*)p;
    cudaGetSymbolAddress(&p, g_wqh); __nv_bfloat16* wqh = (__nv_bfloat16*)p;
    cudaGetSymbolAddress(&p, g_wql); __nv_bfloat16* wql = (__nv_bfloat16*)p;
    cudaGetSymbolAddress(&p, g_wkh); __nv_bfloat16* wkh = (__nv_bfloat16*)p;
    cudaGetSymbolAddress(&p, g_wkl); __nv_bfloat16* wkl = (__nv_bfloat16*)p;
    cudaGetSymbolAddress(&p, g_wvh); __nv_bfloat16* wvh = (__nv_bfloat16*)p;
    cudaGetSymbolAddress(&p, g_wvl); __nv_bfloat16* wvl = (__nv_bfloat16*)p;
    cudaGetSymbolAddress(&p, g_woh); __nv_bfloat16* woh = (__nv_bfloat16*)p;
    cudaGetSymbolAddress(&p, g_wol); __nv_bfloat16* wol = (__nv_bfloat16*)p;

    cudaFuncSetAttribute(mma_gemm, cudaFuncAttributeMaxDynamicSharedMemorySize,
                         GEMM_SMEM_BYTES);
    cudaFuncSetAttribute(attn_kernel, cudaFuncAttributeMaxDynamicSharedMemorySize,
                         ATT_SMEM_BYTES);

    // Split X and weights to bf16 hi/lo (weights also transposed to [N,K])
    {
        int n4 = S_LEN * HID / 4;
        split2<<<(n4 + 255) / 256, 256>>>((const float4*)X,
                                          (__nv_bfloat162*)xhi, (__nv_bfloat162*)xlo, n4);
    }
    split_transpose<<<dim3(HID / 32, HID / 32), dim3(32, 8)>>>(Wq, wqh, wql, HID, HID);
    split_transpose<<<dim3(NG * DH / 32, HID / 32), dim3(32, 8)>>>(Wk, wkh, wkl, HID, NG * DH);
    split_transpose<<<dim3(NG * DH / 32, HID / 32), dim3(32, 8)>>>(Wv, wvh, wvl, HID, NG * DH);
    split_transpose<<<dim3(HID / 32, HID / 32), dim3(32, 8)>>>(Wo, woh, wol, NH * DH, HID);

    // QKV projections (HMMA bf16, 3x split)
    mma_gemm<<<dim3(HID / 128, S_LEN / 128), 256, GEMM_SMEM_BYTES>>>(
        xhi, xlo, wqh, wql, bq, qp, S_LEN, HID, HID);
    mma_gemm<<<dim3(NG * DH / 128, S_LEN / 128), 256, GEMM_SMEM_BYTES>>>(
        xhi, xlo, wkh, wkl, bk, kp, S_LEN, NG * DH, HID);
    mma_gemm<<<dim3(NG * DH / 128, S_LEN / 128), 256, GEMM_SMEM_BYTES>>>(
        xhi, xlo, wvh, wvl, bv, vp, S_LEN, NG * DH, HID);

    // RoPE
    rope_kernel<<<(S_LEN * 64 + 255) / 256, 256>>>(qp, kp);

    // Attention
    attn_kernel<<<dim3(S_LEN / 64, NH), 256, ATT_SMEM_BYTES>>>(qp, kp, vp, cp);

    // Split ctx, output projection
    {
        int n4 = S_LEN * HID / 4;
        split2<<<(n4 + 255) / 256, 256>>>((const float4*)cp,
                                          (__nv_bfloat162*)chi, (__nv_bfloat162*)clo, n4);
    }
    mma_gemm<<<dim3(HID / 128, S_LEN / 128), 256, GEMM_SMEM_BYTES>>>(
        chi, clo, woh, wol, bo, out, S_LEN, HID, NH * DH);
}

// round 7
// speedup vs baseline: 2.2297x; 1.6308x over previous
#include <cuda.h>
#include <cuda_runtime.h>
#include <cuda_bf16.h>
#include <math.h>

// ---------------------------------------------------------------------------
// Problem constants
// ---------------------------------------------------------------------------
#define S_LEN 2048
#define HID   4096
#define NH    32
#define NG    8
#define DH    128

// ---------------------------------------------------------------------------
// Device-global scratch (allocation-free rule)
// ---------------------------------------------------------------------------
__device__ __align__(16) float g_q[S_LEN * NH * DH];
__device__ __align__(16) float g_k[S_LEN * NG * DH];
__device__ __align__(16) float g_v[S_LEN * NG * DH];

__device__ __align__(16) __nv_bfloat16 g_xhi[S_LEN * HID];
__device__ __align__(16) __nv_bfloat16 g_xlo[S_LEN * HID];
__device__ __align__(16) __nv_bfloat16 g_chi[S_LEN * HID];
__device__ __align__(16) __nv_bfloat16 g_clo[S_LEN * HID];
__device__ __align__(16) __nv_bfloat16 g_qhi[S_LEN * NH * DH];
__device__ __align__(16) __nv_bfloat16 g_qlo[S_LEN * NH * DH];
__device__ __align__(16) __nv_bfloat16 g_khi[S_LEN * NG * DH];
__device__ __align__(16) __nv_bfloat16 g_klo[S_LEN * NG * DH];
__device__ __align__(16) __nv_bfloat16 g_vhi[S_LEN * NG * DH];
__device__ __align__(16) __nv_bfloat16 g_vlo[S_LEN * NG * DH];
__device__ __align__(16) __nv_bfloat16 g_wqh[HID * HID];
__device__ __align__(16) __nv_bfloat16 g_wql[HID * HID];
__device__ __align__(16) __nv_bfloat16 g_wkh[NG * DH * HID];
__device__ __align__(16) __nv_bfloat16 g_wkl[NG * DH * HID];
__device__ __align__(16) __nv_bfloat16 g_wvh[NG * DH * HID];
__device__ __align__(16) __nv_bfloat16 g_wvl[NG * DH * HID];
__device__ __align__(16) __nv_bfloat16 g_woh[HID * HID];
__device__ __align__(16) __nv_bfloat16 g_wol[HID * HID];

// ---------------------------------------------------------------------------
// PTX helpers (sm_80-baseline: ldmatrix / mma.sync / cp.async)
// ---------------------------------------------------------------------------
__device__ __forceinline__ uint32_t smem_u32(const void* p) {
    uint32_t a;
    asm("{ .reg .u64 t; cvta.to.shared.u64 t, %1; cvt.u32.u64 %0, t; }"
        : "=r"(a) : "l"(p));
    return a;
}

__device__ __forceinline__ void ldsm4(uint32_t& r0, uint32_t& r1, uint32_t& r2,
                                      uint32_t& r3, uint32_t addr) {
    asm volatile("ldmatrix.sync.aligned.m8n8.x4.shared.b16 {%0,%1,%2,%3}, [%4];"
                 : "=r"(r0), "=r"(r1), "=r"(r2), "=r"(r3) : "r"(addr));
}

__device__ __forceinline__ void ldsm4t(uint32_t& r0, uint32_t& r1, uint32_t& r2,
                                       uint32_t& r3, uint32_t addr) {
    asm volatile("ldmatrix.sync.aligned.m8n8.x4.trans.shared.b16 {%0,%1,%2,%3}, [%4];"
                 : "=r"(r0), "=r"(r1), "=r"(r2), "=r"(r3) : "r"(addr));
}

__device__ __forceinline__ void mma16816(float* d, uint32_t a0, uint32_t a1,
                                         uint32_t a2, uint32_t a3,
                                         uint32_t b0, uint32_t b1) {
    asm volatile(
        "mma.sync.aligned.m16n8k16.row.col.f32.bf16.bf16.f32 "
        "{%0,%1,%2,%3}, {%4,%5,%6,%7}, {%8,%9}, {%0,%1,%2,%3};"
        : "+f"(d[0]), "+f"(d[1]), "+f"(d[2]), "+f"(d[3])
        : "r"(a0), "r"(a1), "r"(a2), "r"(a3), "r"(b0), "r"(b1));
}

__device__ __forceinline__ float ex2f(float x) {
    float r;
    asm("ex2.approx.ftz.f32 %0, %1;" : "=f"(r) : "f"(x));
    return r;
}

__device__ __forceinline__ void bsplit2pack(float v0, float v1,
                                            uint32_t& hi, uint32_t& lo) {
    __nv_bfloat16 h0 = __float2bfloat16(v0), h1 = __float2bfloat16(v1);
    float r0 = v0 - __bfloat162float(h0), r1 = v1 - __bfloat162float(h1);
    __nv_bfloat16 l0 = __float2bfloat16(r0), l1 = __float2bfloat16(r1);
    hi = ((uint32_t)__bfloat16_as_ushort(h1) << 16) | __bfloat16_as_ushort(h0);
    lo = ((uint32_t)__bfloat16_as_ushort(l1) << 16) | __bfloat16_as_ushort(l0);
}

#define CP_ASYNC16(smem_addr, gptr) \
    asm volatile("cp.async.cg.shared.global [%0], [%1], 16;" \
                 :: "r"(smem_addr), "l"(gptr))
#define CP_COMMIT() asm volatile("cp.async.commit_group;" ::: "memory")
#define CP_WAIT0()  asm volatile("cp.async.wait_group 0;" ::: "memory")
#define CP_WAIT1()  asm volatile("cp.async.wait_group 1;" ::: "memory")

// ---------------------------------------------------------------------------
// Split fp32 -> (hi, lo) bf16, same layout. n4 = n/4 float4s.
// ---------------------------------------------------------------------------
__global__ void split2(const float4* __restrict__ src, __nv_bfloat162* __restrict__ hi,
                       __nv_bfloat162* __restrict__ lo, int n4) {
    int i = blockIdx.x * blockDim.x + threadIdx.x;
    if (i >= n4) return;
    float4 v = src[i];
    __nv_bfloat16 h0 = __float2bfloat16(v.x), h1 = __float2bfloat16(v.y);
    __nv_bfloat16 h2 = __float2bfloat16(v.z), h3 = __float2bfloat16(v.w);
    hi[2 * i]     = __halves2bfloat162(h0, h1);
    hi[2 * i + 1] = __halves2bfloat162(h2, h3);
    lo[2 * i]     = __halves2bfloat162(__float2bfloat16(v.x - __bfloat162float(h0)),
                                       __float2bfloat16(v.y - __bfloat162float(h1)));
    lo[2 * i + 1] = __halves2bfloat162(__float2bfloat16(v.z - __bfloat162float(h2)),
                                       __float2bfloat16(v.w - __bfloat162float(h3)));
}

// ---------------------------------------------------------------------------
// Split + transpose: W[K,N] fp32 -> Th,Tl [N,K] bf16. Block 32x8, tile 32x32.
// ---------------------------------------------------------------------------
__global__ void split_transpose(const float* __restrict__ W, __nv_bfloat16* __restrict__ Th,
                                __nv_bfloat16* __restrict__ Tl, int K, int N) {
    __shared__ float t[32][33];
    int x = blockIdx.x * 32;
    int y = blockIdx.y * 32;
    int tx = threadIdx.x, ty = threadIdx.y;
#pragma unroll
    for (int j = 0; j < 4; j++)
        t[ty + j * 8][tx] = W[(size_t)(y + ty + j * 8) * N + x + tx];
    __syncthreads();
#pragma unroll
    for (int j = 0; j < 4; j++) {
        float v = t[tx][ty + j * 8];
        __nv_bfloat16 h = __float2bfloat16(v);
        float r = v - __bfloat162float(h);
        size_t o = (size_t)(x + ty + j * 8) * K + y + tx;
        Th[o] = h;
        Tl[o] = __float2bfloat16(r);
    }
}

// ---------------------------------------------------------------------------
// HMMA bf16 GEMM (3xBF16 split) — unchanged from round 6 (proven).
// ---------------------------------------------------------------------------
#define ROWB 80
#define STAGE_BYTES (4 * 128 * ROWB)
#define GEMM_SMEM_BYTES (2 * STAGE_BYTES)

__global__ __launch_bounds__(256, 2)
void mma_gemm(const __nv_bfloat16* __restrict__ Ahi, const __nv_bfloat16* __restrict__ Alo,
              const __nv_bfloat16* __restrict__ Bhi, const __nv_bfloat16* __restrict__ Blo,
              const float* __restrict__ bias, float* __restrict__ C,
              int M, int N, int K) {
    extern __shared__ char smc[];
    const uint32_t sb = smem_u32(smc);
    const int tid = threadIdx.x;
    const int w = tid >> 5, lane = tid & 31;
    const int wm = w >> 2;
    const int wn = w & 3;
    const int m0 = blockIdx.y * 128;
    const int n0 = blockIdx.x * 128;

    size_t ga[2], gb[2];
    uint32_t so[2];
#pragma unroll
    for (int t = 0; t < 2; t++) {
        int i = tid + t * 256;
        int row = i >> 2, u = i & 3;
        ga[t] = (size_t)(m0 + row) * K + u * 8;
        gb[t] = (size_t)(n0 + row) * K + u * 8;
        so[t] = (uint32_t)(row * ROWB + u * 16);
    }

    const int NC = K >> 5;
    {
#pragma unroll
        for (int t = 0; t < 2; t++) {
            CP_ASYNC16(sb + so[t],         (const char*)(Ahi + ga[t]));
            CP_ASYNC16(sb + 10240 + so[t], (const char*)(Alo + ga[t]));
            CP_ASYNC16(sb + 20480 + so[t], (const char*)(Bhi + gb[t]));
            CP_ASYNC16(sb + 30720 + so[t], (const char*)(Blo + gb[t]));
        }
        CP_COMMIT();
    }

    float acc[4][4][4];
#pragma unroll
    for (int mi = 0; mi < 4; mi++)
#pragma unroll
        for (int ni = 0; ni < 4; ni++)
#pragma unroll
            for (int j = 0; j < 4; j++) acc[mi][ni][j] = 0.f;

    const int lr = lane & 15, lc = lane >> 4;
    const uint32_t a_lane_off = (uint32_t)((wm * 64 + lr) * ROWB + lc * 16);
    const uint32_t b_lane_off = (uint32_t)((wn * 32 + lr) * ROWB + lc * 16);

    for (int c = 0; c < NC; c++) {
        const int buf = c & 1;
        if (c + 1 < NC) {
            const size_t kc = (size_t)(c + 1) << 5;
            const uint32_t dst = sb + (uint32_t)((c + 1) & 1) * STAGE_BYTES;
#pragma unroll
            for (int t = 0; t < 2; t++) {
                CP_ASYNC16(dst + so[t],         (const char*)(Ahi + ga[t] + kc));
                CP_ASYNC16(dst + 10240 + so[t], (const char*)(Alo + ga[t] + kc));
                CP_ASYNC16(dst + 20480 + so[t], (const char*)(Bhi + gb[t] + kc));
                CP_ASYNC16(dst + 30720 + so[t], (const char*)(Blo + gb[t] + kc));
            }
            CP_COMMIT();
            CP_WAIT1();
        } else {
            CP_WAIT0();
        }
        __syncthreads();

        const uint32_t base = sb + (uint32_t)buf * STAGE_BYTES;
#pragma unroll
        for (int ks = 0; ks < 2; ks++) {
            const uint32_t koff = (uint32_t)(ks * 32);
            uint32_t bh[4][2], bl[4][2];
#pragma unroll
            for (int ni16 = 0; ni16 < 2; ni16++) {
                uint32_t addr = base + 20480 + b_lane_off + (uint32_t)(ni16 * 16 * ROWB) + koff;
                uint32_t r0, r1, r2, r3;
                ldsm4(r0, r1, r2, r3, addr);
                bh[ni16 * 2][0] = r0; bh[ni16 * 2][1] = r2;
                bh[ni16 * 2 + 1][0] = r1; bh[ni16 * 2 + 1][1] = r3;
                ldsm4(r0, r1, r2, r3, addr + 10240);
                bl[ni16 * 2][0] = r0; bl[ni16 * 2][1] = r2;
                bl[ni16 * 2 + 1][0] = r1; bl[ni16 * 2 + 1][1] = r3;
            }
#pragma unroll
            for (int mi = 0; mi < 4; mi++) {
                uint32_t addr = base + a_lane_off + (uint32_t)(mi * 16 * ROWB) + koff;
                uint32_t ah0, ah1, ah2, ah3, al0, al1, al2, al3;
                ldsm4(ah0, ah1, ah2, ah3, addr);
                ldsm4(al0, al1, al2, al3, addr + 10240);
#pragma unroll
                for (int ni = 0; ni < 4; ni++) {
                    mma16816(acc[mi][ni], ah0, ah1, ah2, ah3, bh[ni][0], bh[ni][1]);
                    mma16816(acc[mi][ni], ah0, ah1, ah2, ah3, bl[ni][0], bl[ni][1]);
                    mma16816(acc[mi][ni], al0, al1, al2, al3, bh[ni][0], bh[ni][1]);
                }
            }
        }
        __syncthreads();
    }

#pragma unroll
    for (int mi = 0; mi < 4; mi++) {
#pragma unroll
        for (int ni = 0; ni < 4; ni++) {
            int m = m0 + wm * 64 + mi * 16 + (lane >> 2);
            int n = n0 + wn * 32 + ni * 8 + 2 * (lane & 3);
            float2 bv = *(const float2*)&bias[n];
            float2 o0 = make_float2(acc[mi][ni][0] + bv.x, acc[mi][ni][1] + bv.y);
            float2 o1 = make_float2(acc[mi][ni][2] + bv.x, acc[mi][ni][3] + bv.y);
            *(float2*)&C[(size_t)m * N + n]       = o0;
            *(float2*)&C[(size_t)(m + 8) * N + n] = o1;
        }
    }
}

// ---------------------------------------------------------------------------
// RoPE (in-place on q and k).
// ---------------------------------------------------------------------------
__global__ void rope_kernel(float* __restrict__ q, float* __restrict__ k) {
    int idx = blockIdx.x * blockDim.x + threadIdx.x;
    if (idx >= S_LEN * 64) return;
    int j = idx & 63;
    int s = idx >> 6;
    float inv = (float)exp(-(double)j * (9.210340371976184 / 64.0));
    float ang = (float)s * inv;
    float sn, cs;
    sincosf(ang, &sn, &cs);
    float* qb = q + (size_t)s * (NH * DH) + j;
#pragma unroll
    for (int h = 0; h < NH; h++) {
        float x1 = qb[h * DH];
        float x2 = qb[h * DH + 64];
        qb[h * DH]      = x1 * cs - x2 * sn;
        qb[h * DH + 64] = x1 * sn + x2 * cs;
    }
    float* kb = k + (size_t)s * (NG * DH) + j;
#pragma unroll
    for (int h = 0; h < NG; h++) {
        float x1 = kb[h * DH];
        float x2 = kb[h * DH + 64];
        kb[h * DH]      = x1 * cs - x2 * sn;
        kb[h * DH + 64] = x1 * sn + x2 * cs;
    }
}

// ---------------------------------------------------------------------------
// Tensorized flash attention (HMMA bf16 3x split, causal, GQA).
// Grid (S/128, NH). 256 threads = 8 warps; warp w owns rows w*16..w*16+15.
// BN = 64 keys per iteration; K/V double-buffered via cp.async.
// Softmax in exp2 space (scale*log2e folded). Epilogue writes bf16 hi/lo ctx.
// smem rows padded to 136 bf16 (272 B) -> conflict-free ldmatrix.
// ---------------------------------------------------------------------------
#define AP 272
#define ATTN_QH 0
#define ATTN_QL (128 * AP)
#define ATTN_KV (256 * AP)
#define ATTN_KVBUF (256 * AP)
#define ATTN_SMEM (ATTN_KV + 2 * ATTN_KVBUF)   // 208896 B

__global__ __launch_bounds__(256, 1)
void attn_mma(const __nv_bfloat16* __restrict__ qhi, const __nv_bfloat16* __restrict__ qlo,
              const __nv_bfloat16* __restrict__ khi, const __nv_bfloat16* __restrict__ klo,
              const __nv_bfloat16* __restrict__ vhi, const __nv_bfloat16* __restrict__ vlo,
              __nv_bfloat16* __restrict__ chi, __nv_bfloat16* __restrict__ clo) {
    extern __shared__ char smc[];
    const uint32_t sb = smem_u32(smc);
    const int tid = threadIdx.x, w = tid >> 5, lane = tid & 31;
    const int qb = blockIdx.x, h = blockIdx.y, g = h >> 2;
    const int q0 = qb * 128;
    const int R = q0 + w * 16;

    // Load Q tile (hi+lo): 128 rows x 16 chunks of 16B each
    for (int c = tid; c < 2048; c += 256) {
        int row = c >> 4, u = c & 15;
        size_t go = (size_t)(q0 + row) * (NH * DH) + h * DH + u * 8;
        uint32_t s = sb + ATTN_QH + row * AP + u * 16;
        CP_ASYNC16(s,           (const char*)(qhi + go));
        CP_ASYNC16(s + ATTN_QL, (const char*)(qlo + go));
    }
    CP_COMMIT();

    const int ntiles = 2 * qb + 2;

    // Prologue: KV tile 0 into buffer 0
    {
        uint32_t b0 = sb + ATTN_KV;
        for (int c = tid; c < 1024; c += 256) {
            int row = c >> 4, u = c & 15;
            size_t go = (size_t)row * (NG * DH) + g * DH + u * 8;
            uint32_t s = b0 + row * AP + u * 16;
            CP_ASYNC16(s,            (const char*)(khi + go));
            CP_ASYNC16(s + 64 * AP,  (const char*)(klo + go));
            CP_ASYNC16(s + 128 * AP, (const char*)(vhi + go));
            CP_ASYNC16(s + 192 * AP, (const char*)(vlo + go));
        }
        CP_COMMIT();
    }

    float o[16][4];
#pragma unroll
    for (int t = 0; t < 16; t++)
#pragma unroll
        for (int j = 0; j < 4; j++) o[t][j] = 0.f;
    float m_run[2] = {-1e30f, -1e30f};
    float l_run[2] = {0.f, 0.f};

    const float SC = 0.12751879523171918f;   // (1/sqrt(128)) * log2(e)

    for (int kt = 0; kt < ntiles; kt++) {
        const int k0 = kt * 64;
        const int buf = kt & 1;
        if (kt + 1 < ntiles) {
            uint32_t b0 = sb + ATTN_KV + (uint32_t)(buf ^ 1) * ATTN_KVBUF;
            const int kn = (kt + 1) * 64;
            for (int c = tid; c < 1024; c += 256) {
                int row = c >> 4, u = c & 15;
                size_t go = (size_t)(kn + row) * (NG * DH) + g * DH + u * 8;
                uint32_t s = b0 + row * AP + u * 16;
                CP_ASYNC16(s,            (const char*)(khi + go));
                CP_ASYNC16(s + 64 * AP,  (const char*)(klo + go));
                CP_ASYNC16(s + 128 * AP, (const char*)(vhi + go));
                CP_ASYNC16(s + 192 * AP, (const char*)(vlo + go));
            }
            CP_COMMIT();
            CP_WAIT1();
        } else {
            CP_WAIT0();
        }
        __syncthreads();

        if (k0 <= R + 15) {   // skip fully-masked tiles for this warp
            const uint32_t kb = sb + ATTN_KV + (uint32_t)buf * ATTN_KVBUF;

            // ---- S = Q K^T (3-term split) ----
            float sS[8][4];
#pragma unroll
            for (int t = 0; t < 8; t++)
#pragma unroll
                for (int j = 0; j < 4; j++) sS[t][j] = 0.f;

            const uint32_t q_lane = (uint32_t)((w * 16 + (lane & 7) + ((lane >> 3) & 1) * 8) * AP);
            const uint32_t q_col  = (uint32_t)((lane >> 4) * 16);   // *8 elems *2B
#pragma unroll
            for (int kc8 = 0; kc8 < 8; kc8++) {
                uint32_t qa = sb + ATTN_QH + q_lane + (uint32_t)(kc8 * 32) + q_col;
                uint32_t ah0, ah1, ah2, ah3, al0, al1, al2, al3;
                ldsm4(ah0, ah1, ah2, ah3, qa);
                ldsm4(al0, al1, al2, al3, qa + ATTN_QL);
#pragma unroll
                for (int kg = 0; kg < 4; kg++) {
                    uint32_t ka = kb
                        + (uint32_t)((kg * 16 + ((lane >> 4) & 1) * 8 + (lane & 7)) * AP)
                        + (uint32_t)(kc8 * 32 + ((lane >> 3) & 1) * 16);
                    uint32_t bh0, bh1, bh2, bh3, bl0, bl1, bl2, bl3;
                    ldsm4(bh0, bh1, bh2, bh3, ka);
                    ldsm4(bl0, bl1, bl2, bl3, ka + 64 * AP);
                    mma16816(sS[2 * kg],     ah0, ah1, ah2, ah3, bh0, bh1);
                    mma16816(sS[2 * kg],     ah0, ah1, ah2, ah3, bl0, bl1);
                    mma16816(sS[2 * kg],     al0, al1, al2, al3, bh0, bh1);
                    mma16816(sS[2 * kg + 1], ah0, ah1, ah2, ah3, bh2, bh3);
                    mma16816(sS[2 * kg + 1], ah0, ah1, ah2, ah3, bl2, bl3);
                    mma16816(sS[2 * kg + 1], al0, al1, al2, al3, bh2, bh3);
                }
            }

            // ---- softmax (exp2 space) ----
            const int r0 = R + (lane >> 2), r1 = r0 + 8;
            const bool diag = (k0 + 63 > R);
            float mt0 = -1e30f, mt1 = -1e30f;
#pragma unroll
            for (int t = 0; t < 8; t++) {
                int cb = k0 + t * 8 + 2 * (lane & 3);
                float s0 = sS[t][0] * SC, s1 = sS[t][1] * SC;
                float s2 = sS[t][2] * SC, s3 = sS[t][3] * SC;
                if (diag) {
                    if (cb     > r0) s0 = -1e30f;
                    if (cb + 1 > r0) s1 = -1e30f;
                    if (cb     > r1) s2 = -1e30f;
                    if (cb + 1 > r1) s3 = -1e30f;
                }
                sS[t][0] = s0; sS[t][1] = s1; sS[t][2] = s2; sS[t][3] = s3;
                mt0 = fmaxf(mt0, fmaxf(s0, s1));
                mt1 = fmaxf(mt1, fmaxf(s2, s3));
            }
            mt0 = fmaxf(mt0, __shfl_xor_sync(0xffffffffu, mt0, 1));
            mt0 = fmaxf(mt0, __shfl_xor_sync(0xffffffffu, mt0, 2));
            mt1 = fmaxf(mt1, __shfl_xor_sync(0xffffffffu, mt1, 1));
            mt1 = fmaxf(mt1, __shfl_xor_sync(0xffffffffu, mt1, 2));
            float mn0 = fmaxf(m_run[0], mt0), mn1 = fmaxf(m_run[1], mt1);
            float corr0 = ex2f(m_run[0] - mn0), corr1 = ex2f(m_run[1] - mn1);
            m_run[0] = mn0; m_run[1] = mn1;
            float ls0 = 0.f, ls1 = 0.f;
#pragma unroll
            for (int t = 0; t < 8; t++) {
                float p0 = ex2f(sS[t][0] - mn0), p1 = ex2f(sS[t][1] - mn0);
                float p2 = ex2f(sS[t][2] - mn1), p3 = ex2f(sS[t][3] - mn1);
                ls0 += p0 + p1; ls1 += p2 + p3;
                sS[t][0] = p0; sS[t][1] = p1; sS[t][2] = p2; sS[t][3] = p3;
            }
            ls0 += __shfl_xor_sync(0xffffffffu, ls0, 1);
            ls0 += __shfl_xor_sync(0xffffffffu, ls0, 2);
            ls1 += __shfl_xor_sync(0xffffffffu, ls1, 1);
            ls1 += __shfl_xor_sync(0xffffffffu, ls1, 2);
            l_run[0] = l_run[0] * corr0 + ls0;
            l_run[1] = l_run[1] * corr1 + ls1;
#pragma unroll
            for (int t = 0; t < 16; t++) {
                o[t][0] *= corr0; o[t][1] *= corr0;
                o[t][2] *= corr1; o[t][3] *= corr1;
            }

            // ---- pack P into A fragments (hi/lo) ----
            uint32_t pah[4][4], pal[4][4];
#pragma unroll
            for (int kc = 0; kc < 4; kc++) {
                bsplit2pack(sS[2 * kc][0],     sS[2 * kc][1],     pah[kc][0], pal[kc][0]);
                bsplit2pack(sS[2 * kc][2],     sS[2 * kc][3],     pah[kc][1], pal[kc][1]);
                bsplit2pack(sS[2 * kc + 1][0], sS[2 * kc + 1][1], pah[kc][2], pal[kc][2]);
                bsplit2pack(sS[2 * kc + 1][2], sS[2 * kc + 1][3], pah[kc][3], pal[kc][3]);
            }

            // ---- O += P V (3-term split) ----
#pragma unroll
            for (int kc = 0; kc < 4; kc++) {
#pragma unroll
                for (int dp = 0; dp < 8; dp++) {
                    uint32_t va = kb + 128 * AP
                        + (uint32_t)((kc * 16 + ((lane >> 3) & 1) * 8 + (lane & 7)) * AP)
                        + (uint32_t)(dp * 32 + ((lane >> 4) & 1) * 16);
                    uint32_t vh0, vh1, vh2, vh3, vl0, vl1, vl2, vl3;
                    ldsm4t(vh0, vh1, vh2, vh3, va);
                    ldsm4t(vl0, vl1, vl2, vl3, va + 64 * AP);
                    mma16816(o[2 * dp],     pah[kc][0], pah[kc][1], pah[kc][2], pah[kc][3], vh0, vh1);
                    mma16816(o[2 * dp],     pah[kc][0], pah[kc][1], pah[kc][2], pah[kc][3], vl0, vl1);
                    mma16816(o[2 * dp],     pal[kc][0], pal[kc][1], pal[kc][2], pal[kc][3], vh0, vh1);
                    mma16816(o[2 * dp + 1], pah[kc][0], pah[kc][1], pah[kc][2], pah[kc][3], vh2, vh3);
                    mma16816(o[2 * dp + 1], pah[kc][0], pah[kc][1], pah[kc][2], pah[kc][3], vl2, vl3);
                    mma16816(o[2 * dp + 1], pal[kc][0], pal[kc][1], pal[kc][2], pal[kc][3], vh2, vh3);
                }
            }
        }
        __syncthreads();
    }

    // ---- epilogue: normalize + fused bf16 hi/lo split of ctx ----
    float inv0 = 1.f / l_run[0], inv1 = 1.f / l_run[1];
    int r0 = R + (lane >> 2);
#pragma unroll
    for (int t = 0; t < 16; t++) {
        int col = t * 8 + 2 * (lane & 3);
        size_t o0 = (size_t)r0 * (NH * DH) + h * DH + col;
        size_t o1 = (size_t)(r0 + 8) * (NH * DH) + h * DH + col;
        uint32_t hi, lo;
        bsplit2pack(o[t][0] * inv0, o[t][1] * inv0, hi, lo);
        *(uint32_t*)(chi + o0) = hi;
        *(uint32_t*)(clo + o0) = lo;
        bsplit2pack(o[t][2] * inv1, o[t][3] * inv1, hi, lo);
        *(uint32_t*)(chi + o1) = hi;
        *(uint32_t*)(clo + o1) = lo;
    }
}

// ---------------------------------------------------------------------------
// Launch  (order chosen so launch index 5 = mma_gemm Q for ncu -s 5 -c 1)
// ---------------------------------------------------------------------------
extern "C" void kernel_launch(void* const* d_in, const int* in_sizes, int n_in,
                              void* d_out, int out_size) {
    const float* X  = (const float*)d_in[0];
    const float* Wq = (const float*)d_in[1];
    const float* bq = (const float*)d_in[2];
    const float* Wk = (const float*)d_in[3];
    const float* bk = (const float*)d_in[4];
    const float* Wv = (const float*)d_in[5];
    const float* bv = (const float*)d_in[6];
    const float* Wo = (const float*)d_in[7];
    const float* bo = (const float*)d_in[8];
    float* out = (float*)d_out;

    void* p;
    cudaGetSymbolAddress(&p, g_q);   float* qp = (float*)p;
    cudaGetSymbolAddress(&p, g_k);   float* kp = (float*)p;
    cudaGetSymbolAddress(&p, g_v);   float* vp = (float*)p;
    cudaGetSymbolAddress(&p, g_xhi); __nv_bfloat16* xhi = (__nv_bfloat16*)p;
    cudaGetSymbolAddress(&p, g_xlo); __nv_bfloat16* xlo = (__nv_bfloat16*)p;
    cudaGetSymbolAddress(&p, g_chi); __nv_bfloat16* chi = (__nv_bfloat16*)p;
    cudaGetSymbolAddress(&p, g_clo); __nv_bfloat16* clo = (__nv_bfloat16*)p;
    cudaGetSymbolAddress(&p, g_qhi); __nv_bfloat16* qhi = (__nv_bfloat16*)p;
    cudaGetSymbolAddress(&p, g_qlo); __nv_bfloat16* qlo = (__nv_bfloat16*)p;
    cudaGetSymbolAddress(&p, g_khi); __nv_bfloat16* khi = (__nv_bfloat16*)p;
    cudaGetSymbolAddress(&p, g_klo); __nv_bfloat16* klo = (__nv_bfloat16*)p;
    cudaGetSymbolAddress(&p, g_vhi); __nv_bfloat16* vhi = (__nv_bfloat16*)p;
    cudaGetSymbolAddress(&p, g_vlo); __nv_bfloat16* vlo = (__nv_bfloat16*)p;
    cudaGetSymbolAddress(&p, g_wqh); __nv_bfloat16* wqh = (__nv_bfloat16*)p;
    cudaGetSymbolAddress(&p, g_wql); __nv_bfloat16* wql = (__nv_bfloat16*)p;
    cudaGetSymbolAddress(&p, g_wkh); __nv_bfloat16* wkh = (__nv_bfloat16*)p;
    cudaGetSymbolAddress(&p, g_wkl); __nv_bfloat16* wkl = (__nv_bfloat16*)p;
    cudaGetSymbolAddress(&p, g_wvh); __nv_bfloat16* wvh = (__nv_bfloat16*)p;
    cudaGetSymbolAddress(&p, g_wvl); __nv_bfloat16* wvl = (__nv_bfloat16*)p;
    cudaGetSymbolAddress(&p, g_woh); __nv_bfloat16* woh = (__nv_bfloat16*)p;
    cudaGetSymbolAddress(&p, g_wol); __nv_bfloat16* wol = (__nv_bfloat16*)p;

    cudaFuncSetAttribute(mma_gemm, cudaFuncAttributeMaxDynamicSharedMemorySize,
                         GEMM_SMEM_BYTES);
    cudaFuncSetAttribute(attn_mma, cudaFuncAttributeMaxDynamicSharedMemorySize,
                         ATTN_SMEM);

    // Launches 0-3: weight split+transpose
    split_transpose<<<dim3(HID / 32, HID / 32), dim3(32, 8)>>>(Wq, wqh, wql, HID, HID);
    split_transpose<<<dim3(NG * DH / 32, HID / 32), dim3(32, 8)>>>(Wk, wkh, wkl, HID, NG * DH);
    split_transpose<<<dim3(NG * DH / 32, HID / 32), dim3(32, 8)>>>(Wv, wvh, wvl, HID, NG * DH);
    split_transpose<<<dim3(HID / 32, HID / 32), dim3(32, 8)>>>(Wo, woh, wol, NH * DH, HID);

    // Launch 4: split X
    {
        int n4 = S_LEN * HID / 4;
        split2<<<(n4 + 255) / 256, 256>>>((const float4*)X,
                                          (__nv_bfloat162*)xhi, (__nv_bfloat162*)xlo, n4);
    }

    // Launch 5 (ncu capture target): QKV projections
    mma_gemm<<<dim3(HID / 128, S_LEN / 128), 256, GEMM_SMEM_BYTES>>>(
        xhi, xlo, wqh, wql, bq, qp, S_LEN, HID, HID);
    mma_gemm<<<dim3(NG * DH / 128, S_LEN / 128), 256, GEMM_SMEM_BYTES>>>(
        xhi, xlo, wkh, wkl, bk, kp, S_LEN, NG * DH, HID);
    mma_gemm<<<dim3(NG * DH / 128, S_LEN / 128), 256, GEMM_SMEM_BYTES>>>(
        xhi, xlo, wvh, wvl, bv, vp, S_LEN, NG * DH, HID);

    // RoPE then split q/k/v to bf16 hi/lo
    rope_kernel<<<(S_LEN * 64 + 255) / 256, 256>>>(qp, kp);
    {
        int n4 = S_LEN * NH * DH / 4;
        split2<<<(n4 + 255) / 256, 256>>>((const float4*)qp,
                                          (__nv_bfloat162*)qhi, (__nv_bfloat162*)qlo, n4);
    }
    {
        int n4 = S_LEN * NG * DH / 4;
        split2<<<(n4 + 255) / 256, 256>>>((const float4*)kp,
                                          (__nv_bfloat162*)khi, (__nv_bfloat162*)klo, n4);
        split2<<<(n4 + 255) / 256, 256>>>((const float4*)vp,
                                          (__nv_bfloat162*)vhi, (__nv_bfloat162*)vlo, n4);
    }

    // Tensorized attention (writes bf16 hi/lo ctx directly)
    attn_mma<<<dim3(S_LEN / 128, NH), 256, ATTN_SMEM>>>(
        qhi, qlo, khi, klo, vhi, vlo, chi, clo);

    // Output projection
    mma_gemm<<<dim3(HID / 128, S_LEN / 128), 256, GEMM_SMEM_BYTES>>>(
        chi, clo, woh, wol, bo, out, S_LEN, HID, NH * DH);
}

// round 8
// speedup vs baseline: 9.0738x; 4.0694x over previous
#include <cuda.h>
#include <cuda_runtime.h>
#include <cuda_fp16.h>
#include <math.h>

// ---------------------------------------------------------------------------
// Problem constants
// ---------------------------------------------------------------------------
#define S_LEN 2048
#define HID   4096
#define NH    32
#define NG    8
#define DH    128

// ---------------------------------------------------------------------------
// Device-global scratch (allocation-free rule)
// ---------------------------------------------------------------------------
__device__ __align__(16) float g_q[S_LEN * NH * DH];
__device__ __align__(16) float g_k[S_LEN * NG * DH];
__device__ __align__(16) float g_v[S_LEN * NG * DH];

__device__ __align__(16) __half g_xh[S_LEN * HID];
__device__ __align__(16) __half g_ch[S_LEN * HID];          // ctx (fp16, from attention)
__device__ __align__(16) __half g_qh[S_LEN * NH * DH];
__device__ __align__(16) __half g_kh[S_LEN * NG * DH];
__device__ __align__(16) __half g_vh[S_LEN * NG * DH];
__device__ __align__(16) __half g_wqt[HID * HID];           // Wq^T [N,K] fp16
__device__ __align__(16) __half g_wkt[NG * DH * HID];
__device__ __align__(16) __half g_wvt[NG * DH * HID];
__device__ __align__(16) __half g_wot[HID * HID];

// ---------------------------------------------------------------------------
// PTX helpers (sm_80-baseline: ldmatrix / mma.sync / cp.async)
// ---------------------------------------------------------------------------
__device__ __forceinline__ uint32_t smem_u32(const void* p) {
    uint32_t a;
    asm("{ .reg .u64 t; cvta.to.shared.u64 t, %1; cvt.u32.u64 %0, t; }"
        : "=r"(a) : "l"(p));
    return a;
}

__device__ __forceinline__ void ldsm4(uint32_t& r0, uint32_t& r1, uint32_t& r2,
                                      uint32_t& r3, uint32_t addr) {
    asm volatile("ldmatrix.sync.aligned.m8n8.x4.shared.b16 {%0,%1,%2,%3}, [%4];"
                 : "=r"(r0), "=r"(r1), "=r"(r2), "=r"(r3) : "r"(addr));
}

__device__ __forceinline__ void ldsm4t(uint32_t& r0, uint32_t& r1, uint32_t& r2,
                                       uint32_t& r3, uint32_t addr) {
    asm volatile("ldmatrix.sync.aligned.m8n8.x4.trans.shared.b16 {%0,%1,%2,%3}, [%4];"
                 : "=r"(r0), "=r"(r1), "=r"(r2), "=r"(r3) : "r"(addr));
}

__device__ __forceinline__ void mma16816(float* d, uint32_t a0, uint32_t a1,
                                         uint32_t a2, uint32_t a3,
                                         uint32_t b0, uint32_t b1) {
    asm volatile(
        "mma.sync.aligned.m16n8k16.row.col.f32.f16.f16.f32 "
        "{%0,%1,%2,%3}, {%4,%5,%6,%7}, {%8,%9}, {%0,%1,%2,%3};"
        : "+f"(d[0]), "+f"(d[1]), "+f"(d[2]), "+f"(d[3])
        : "r"(a0), "r"(a1), "r"(a2), "r"(a3), "r"(b0), "r"(b1));
}

__device__ __forceinline__ float ex2f(float x) {
    float r;
    asm("ex2.approx.ftz.f32 %0, %1;" : "=f"(r) : "f"(x));
    return r;
}

__device__ __forceinline__ uint32_t pack_half2(float a, float b) {
    __half2 h = __floats2half2_rn(a, b);
    return *(uint32_t*)&h;
}

#define CP_ASYNC16(smem_addr, gptr) \
    asm volatile("cp.async.cg.shared.global [%0], [%1], 16;" \
                 :: "r"(smem_addr), "l"(gptr))
#define CP_COMMIT() asm volatile("cp.async.commit_group;" ::: "memory")
#define CP_WAIT0()  asm volatile("cp.async.wait_group 0;" ::: "memory")
#define CP_WAIT1()  asm volatile("cp.async.wait_group 1;" ::: "memory")

// ---------------------------------------------------------------------------
// fp32 -> fp16, same layout. n4 = n/4 float4s.
// ---------------------------------------------------------------------------
__global__ void cvt_half(const float4* __restrict__ src, __half2* __restrict__ dst, int n4) {
    int i = blockIdx.x * blockDim.x + threadIdx.x;
    if (i >= n4) return;
    float4 v = src[i];
    dst[2 * i]     = __floats2half2_rn(v.x, v.y);
    dst[2 * i + 1] = __floats2half2_rn(v.z, v.w);
}

// ---------------------------------------------------------------------------
// Transpose + fp16: W[K,N] fp32 -> T[N,K] fp16. Block 32x8, tile 32x32.
// ---------------------------------------------------------------------------
__global__ void cvt_transpose(const float* __restrict__ W, __half* __restrict__ T,
                              int K, int N) {
    __shared__ float t[32][33];
    int x = blockIdx.x * 32;
    int y = blockIdx.y * 32;
    int tx = threadIdx.x, ty = threadIdx.y;
#pragma unroll
    for (int j = 0; j < 4; j++)
        t[ty + j * 8][tx] = W[(size_t)(y + ty + j * 8) * N + x + tx];
    __syncthreads();
#pragma unroll
    for (int j = 0; j < 4; j++)
        T[(size_t)(x + ty + j * 8) * K + y + tx] = __float2half_rn(t[tx][ty + j * 8]);
}

// ---------------------------------------------------------------------------
// HMMA fp16 GEMM: C[M,N] = A[M,K] @ B[N,K]^T + bias
// CTA tile 128x128, 8 warps (2x4), warp tile 64x32, BK=64.
// Double-buffered smem via cp.async. Padded rows: 64+8 fp16 = 144 B.
// Stage: sA 18432 | sB 18432 = 36864 B; total 73728 B -> 2 CTAs/SM.
// ---------------------------------------------------------------------------
#define ROWB 144
#define STAGE_BYTES (2 * 128 * ROWB)
#define GEMM_SMEM_BYTES (2 * STAGE_BYTES)

__global__ __launch_bounds__(256, 2)
void mma_gemm(const __half* __restrict__ A, const __half* __restrict__ B,
              const float* __restrict__ bias, float* __restrict__ C,
              int M, int N, int K) {
    extern __shared__ char smc[];
    const uint32_t sb = smem_u32(smc);
    const int tid = threadIdx.x;
    const int w = tid >> 5, lane = tid & 31;
    const int wm = w >> 2;            // 0..1
    const int wn = w & 3;             // 0..3
    const int m0 = blockIdx.y * 128;
    const int n0 = blockIdx.x * 128;

    // cp.async: 128 rows x 64 fp16 = 8 x 16B units per row; 1024 units per mat.
    size_t ga[4], gb[4];
    uint32_t so[4];
#pragma unroll
    for (int t = 0; t < 4; t++) {
        int i = tid + t * 256;
        int row = i >> 3, u = i & 7;
        ga[t] = (size_t)(m0 + row) * K + u * 8;
        gb[t] = (size_t)(n0 + row) * K + u * 8;
        so[t] = (uint32_t)(row * ROWB + u * 16);
    }

    const int NC = K >> 6;
    {
#pragma unroll
        for (int t = 0; t < 4; t++) {
            CP_ASYNC16(sb + so[t],              (const char*)(A + ga[t]));
            CP_ASYNC16(sb + 128 * ROWB + so[t], (const char*)(B + gb[t]));
        }
        CP_COMMIT();
    }

    float acc[4][4][4];
#pragma unroll
    for (int mi = 0; mi < 4; mi++)
#pragma unroll
        for (int ni = 0; ni < 4; ni++)
#pragma unroll
            for (int j = 0; j < 4; j++) acc[mi][ni][j] = 0.f;

    const int lr = lane & 15, lc = lane >> 4;
    const uint32_t a_lane_off = (uint32_t)((wm * 64 + lr) * ROWB + lc * 16);
    const uint32_t b_lane_off = (uint32_t)((wn * 32 + lr) * ROWB + lc * 16);

    for (int c = 0; c < NC; c++) {
        const int buf = c & 1;
        if (c + 1 < NC) {
            const size_t kc = (size_t)(c + 1) << 6;
            const uint32_t dst = sb + (uint32_t)((c + 1) & 1) * STAGE_BYTES;
#pragma unroll
            for (int t = 0; t < 4; t++) {
                CP_ASYNC16(dst + so[t],              (const char*)(A + ga[t] + kc));
                CP_ASYNC16(dst + 128 * ROWB + so[t], (const char*)(B + gb[t] + kc));
            }
            CP_COMMIT();
            CP_WAIT1();
        } else {
            CP_WAIT0();
        }
        __syncthreads();

        const uint32_t base = sb + (uint32_t)buf * STAGE_BYTES;
#pragma unroll
        for (int ks = 0; ks < 4; ks++) {
            const uint32_t koff = (uint32_t)(ks * 32);
            uint32_t bfr[4][2];
#pragma unroll
            for (int ni16 = 0; ni16 < 2; ni16++) {
                uint32_t r0, r1, r2, r3;
                ldsm4(r0, r1, r2, r3,
                      base + 128 * ROWB + b_lane_off + (uint32_t)(ni16 * 16 * ROWB) + koff);
                bfr[ni16 * 2][0] = r0; bfr[ni16 * 2][1] = r2;
                bfr[ni16 * 2 + 1][0] = r1; bfr[ni16 * 2 + 1][1] = r3;
            }
#pragma unroll
            for (int mi = 0; mi < 4; mi++) {
                uint32_t a0, a1, a2, a3;
                ldsm4(a0, a1, a2, a3,
                      base + a_lane_off + (uint32_t)(mi * 16 * ROWB) + koff);
#pragma unroll
                for (int ni = 0; ni < 4; ni++)
                    mma16816(acc[mi][ni], a0, a1, a2, a3, bfr[ni][0], bfr[ni][1]);
            }
        }
        __syncthreads();
    }

#pragma unroll
    for (int mi = 0; mi < 4; mi++) {
#pragma unroll
        for (int ni = 0; ni < 4; ni++) {
            int m = m0 + wm * 64 + mi * 16 + (lane >> 2);
            int n = n0 + wn * 32 + ni * 8 + 2 * (lane & 3);
            float2 bv = *(const float2*)&bias[n];
            float2 o0 = make_float2(acc[mi][ni][0] + bv.x, acc[mi][ni][1] + bv.y);
            float2 o1 = make_float2(acc[mi][ni][2] + bv.x, acc[mi][ni][3] + bv.y);
            *(float2*)&C[(size_t)m * N + n]       = o0;
            *(float2*)&C[(size_t)(m + 8) * N + n] = o1;
        }
    }
}

// ---------------------------------------------------------------------------
// RoPE + convert to fp16 (reads fp32 q/k, writes fp16 qh/kh).
// ---------------------------------------------------------------------------
__global__ void rope_cvt(const float* __restrict__ q, const float* __restrict__ k,
                         __half* __restrict__ qh, __half* __restrict__ kh) {
    int idx = blockIdx.x * blockDim.x + threadIdx.x;
    if (idx >= S_LEN * 64) return;
    int j = idx & 63;
    int s = idx >> 6;
    float inv = (float)exp(-(double)j * (9.210340371976184 / 64.0));
    float ang = (float)s * inv;
    float sn, cs;
    sincosf(ang, &sn, &cs);
    const float* qb = q + (size_t)s * (NH * DH) + j;
    __half* qo = qh + (size_t)s * (NH * DH) + j;
#pragma unroll
    for (int h = 0; h < NH; h++) {
        float x1 = qb[h * DH];
        float x2 = qb[h * DH + 64];
        qo[h * DH]      = __float2half_rn(x1 * cs - x2 * sn);
        qo[h * DH + 64] = __float2half_rn(x1 * sn + x2 * cs);
    }
    const float* kb = k + (size_t)s * (NG * DH) + j;
    __half* ko = kh + (size_t)s * (NG * DH) + j;
#pragma unroll
    for (int h = 0; h < NG; h++) {
        float x1 = kb[h * DH];
        float x2 = kb[h * DH + 64];
        ko[h * DH]      = __float2half_rn(x1 * cs - x2 * sn);
        ko[h * DH + 64] = __float2half_rn(x1 * sn + x2 * cs);
    }
}

// ---------------------------------------------------------------------------
// Tensorized flash attention (single fp16 HMMA, causal, GQA).
// Grid (S/128, NH). 256 threads = 8 warps; warp w owns rows w*16..w*16+15.
// BN = 64 keys/iter; K/V double-buffered via cp.async.
// Softmax in exp2 space. Writes ctx directly as fp16.
// smem rows padded to 136 fp16 (272 B).
// ---------------------------------------------------------------------------
#define AP 272
#define ATTN_KV (128 * AP)             // Q region size (128 rows)
#define ATTN_KVBUF (128 * AP)          // per buffer: K 64 rows + V 64 rows
#define ATTN_SMEM (ATTN_KV + 2 * ATTN_KVBUF)   // 104448 B

__global__ __launch_bounds__(256, 1)
void attn_mma(const __half* __restrict__ qh, const __half* __restrict__ kh,
              const __half* __restrict__ vh, __half* __restrict__ ch) {
    extern __shared__ char smc[];
    const uint32_t sb = smem_u32(smc);
    const int tid = threadIdx.x, w = tid >> 5, lane = tid & 31;
    const int qb = blockIdx.x, h = blockIdx.y, g = h >> 2;
    const int q0 = qb * 128;
    const int R = q0 + w * 16;

    // Load Q tile: 128 rows x 16 chunks of 16B
    for (int c = tid; c < 2048; c += 256) {
        int row = c >> 4, u = c & 15;
        size_t go = (size_t)(q0 + row) * (NH * DH) + h * DH + u * 8;
        CP_ASYNC16(sb + row * AP + u * 16, (const char*)(qh + go));
    }
    CP_COMMIT();

    const int ntiles = 2 * qb + 2;

    // Prologue: KV tile 0 into buffer 0
    {
        uint32_t b0 = sb + ATTN_KV;
        for (int c = tid; c < 1024; c += 256) {
            int row = c >> 4, u = c & 15;
            size_t go = (size_t)row * (NG * DH) + g * DH + u * 8;
            uint32_t s = b0 + row * AP + u * 16;
            CP_ASYNC16(s,           (const char*)(kh + go));
            CP_ASYNC16(s + 64 * AP, (const char*)(vh + go));
        }
        CP_COMMIT();
    }

    float o[16][4];
#pragma unroll
    for (int t = 0; t < 16; t++)
#pragma unroll
        for (int j = 0; j < 4; j++) o[t][j] = 0.f;
    float m_run[2] = {-1e30f, -1e30f};
    float l_run[2] = {0.f, 0.f};

    const float SC = 0.12751879523171918f;   // (1/sqrt(128)) * log2(e)

    for (int kt = 0; kt < ntiles; kt++) {
        const int k0 = kt * 64;
        const int buf = kt & 1;
        if (kt + 1 < ntiles) {
            uint32_t b0 = sb + ATTN_KV + (uint32_t)(buf ^ 1) * ATTN_KVBUF;
            const int kn = (kt + 1) * 64;
            for (int c = tid; c < 1024; c += 256) {
                int row = c >> 4, u = c & 15;
                size_t go = (size_t)(kn + row) * (NG * DH) + g * DH + u * 8;
                uint32_t s = b0 + row * AP + u * 16;
                CP_ASYNC16(s,           (const char*)(kh + go));
                CP_ASYNC16(s + 64 * AP, (const char*)(vh + go));
            }
            CP_COMMIT();
            CP_WAIT1();
        } else {
            CP_WAIT0();
        }
        __syncthreads();

        if (k0 <= R + 15) {
            const uint32_t kb = sb + ATTN_KV + (uint32_t)buf * ATTN_KVBUF;

            // ---- S = Q K^T ----
            float sS[8][4];
#pragma unroll
            for (int t = 0; t < 8; t++)
#pragma unroll
                for (int j = 0; j < 4; j++) sS[t][j] = 0.f;

            const uint32_t q_lane = (uint32_t)((w * 16 + (lane & 7) + ((lane >> 3) & 1) * 8) * AP);
            const uint32_t q_col  = (uint32_t)((lane >> 4) * 16);
#pragma unroll
            for (int kc8 = 0; kc8 < 8; kc8++) {
                uint32_t a0, a1, a2, a3;
                ldsm4(a0, a1, a2, a3, sb + q_lane + (uint32_t)(kc8 * 32) + q_col);
#pragma unroll
                for (int kg = 0; kg < 4; kg++) {
                    uint32_t ka = kb
                        + (uint32_t)((kg * 16 + ((lane >> 4) & 1) * 8 + (lane & 7)) * AP)
                        + (uint32_t)(kc8 * 32 + ((lane >> 3) & 1) * 16);
                    uint32_t b0, b1, b2, b3;
                    ldsm4(b0, b1, b2, b3, ka);
                    mma16816(sS[2 * kg],     a0, a1, a2, a3, b0, b1);
                    mma16816(sS[2 * kg + 1], a0, a1, a2, a3, b2, b3);
                }
            }

            // ---- softmax (exp2 space) ----
            const int r0 = R + (lane >> 2), r1 = r0 + 8;
            const bool diag = (k0 + 63 > R);
            float mt0 = -1e30f, mt1 = -1e30f;
#pragma unroll
            for (int t = 0; t < 8; t++) {
                int cb = k0 + t * 8 + 2 * (lane & 3);
                float s0 = sS[t][0] * SC, s1 = sS[t][1] * SC;
                float s2 = sS[t][2] * SC, s3 = sS[t][3] * SC;
                if (diag) {
                    if (cb     > r0) s0 = -1e30f;
                    if (cb + 1 > r0) s1 = -1e30f;
                    if (cb     > r1) s2 = -1e30f;
                    if (cb + 1 > r1) s3 = -1e30f;
                }
                sS[t][0] = s0; sS[t][1] = s1; sS[t][2] = s2; sS[t][3] = s3;
                mt0 = fmaxf(mt0, fmaxf(s0, s1));
                mt1 = fmaxf(mt1, fmaxf(s2, s3));
            }
            mt0 = fmaxf(mt0, __shfl_xor_sync(0xffffffffu, mt0, 1));
            mt0 = fmaxf(mt0, __shfl_xor_sync(0xffffffffu, mt0, 2));
            mt1 = fmaxf(mt1, __shfl_xor_sync(0xffffffffu, mt1, 1));
            mt1 = fmaxf(mt1, __shfl_xor_sync(0xffffffffu, mt1, 2));
            float mn0 = fmaxf(m_run[0], mt0), mn1 = fmaxf(m_run[1], mt1);
            float corr0 = ex2f(m_run[0] - mn0), corr1 = ex2f(m_run[1] - mn1);
            m_run[0] = mn0; m_run[1] = mn1;
            float ls0 = 0.f, ls1 = 0.f;
#pragma unroll
            for (int t = 0; t < 8; t++) {
                float p0 = ex2f(sS[t][0] - mn0), p1 = ex2f(sS[t][1] - mn0);
                float p2 = ex2f(sS[t][2] - mn1), p3 = ex2f(sS[t][3] - mn1);
                ls0 += p0 + p1; ls1 += p2 + p3;
                sS[t][0] = p0; sS[t][1] = p1; sS[t][2] = p2; sS[t][3] = p3;
            }
            ls0 += __shfl_xor_sync(0xffffffffu, ls0, 1);
            ls0 += __shfl_xor_sync(0xffffffffu, ls0, 2);
            ls1 += __shfl_xor_sync(0xffffffffu, ls1, 1);
            ls1 += __shfl_xor_sync(0xffffffffu, ls1, 2);
            l_run[0] = l_run[0] * corr0 + ls0;
            l_run[1] = l_run[1] * corr1 + ls1;
#pragma unroll
            for (int t = 0; t < 16; t++) {
                o[t][0] *= corr0; o[t][1] *= corr0;
                o[t][2] *= corr1; o[t][3] *= corr1;
            }

            // ---- pack P into fp16 A fragments ----
            uint32_t pa[4][4];
#pragma unroll
            for (int kc = 0; kc < 4; kc++) {
                pa[kc][0] = pack_half2(sS[2 * kc][0],     sS[2 * kc][1]);
                pa[kc][1] = pack_half2(sS[2 * kc][2],     sS[2 * kc][3]);
                pa[kc][2] = pack_half2(sS[2 * kc + 1][0], sS[2 * kc + 1][1]);
                pa[kc][3] = pack_half2(sS[2 * kc + 1][2], sS[2 * kc + 1][3]);
            }

            // ---- O += P V ----
#pragma unroll
            for (int kc = 0; kc < 4; kc++) {
#pragma unroll
                for (int dp = 0; dp < 8; dp++) {
                    uint32_t va = kb + 64 * AP
                        + (uint32_t)((kc * 16 + ((lane >> 3) & 1) * 8 + (lane & 7)) * AP)
                        + (uint32_t)(dp * 32 + ((lane >> 4) & 1) * 16);
                    uint32_t v0, v1, v2, v3;
                    ldsm4t(v0, v1, v2, v3, va);
                    mma16816(o[2 * dp],     pa[kc][0], pa[kc][1], pa[kc][2], pa[kc][3], v0, v1);
                    mma16816(o[2 * dp + 1], pa[kc][0], pa[kc][1], pa[kc][2], pa[kc][3], v2, v3);
                }
            }
        }
        __syncthreads();
    }

    // ---- epilogue: normalize + write fp16 ctx ----
    float inv0 = 1.f / l_run[0], inv1 = 1.f / l_run[1];
    int r0 = R + (lane >> 2);
#pragma unroll
    for (int t = 0; t < 16; t++) {
        int col = t * 8 + 2 * (lane & 3);
        size_t o0 = (size_t)r0 * (NH * DH) + h * DH + col;
        size_t o1 = (size_t)(r0 + 8) * (NH * DH) + h * DH + col;
        *(uint32_t*)(ch + o0) = pack_half2(o[t][0] * inv0, o[t][1] * inv0);
        *(uint32_t*)(ch + o1) = pack_half2(o[t][2] * inv1, o[t][3] * inv1);
    }
}

// ---------------------------------------------------------------------------
// Launch
// ---------------------------------------------------------------------------
extern "C" void kernel_launch(void* const* d_in, const int* in_sizes, int n_in,
                              void* d_out, int out_size) {
    const float* X  = (const float*)d_in[0];
    const float* Wq = (const float*)d_in[1];
    const float* bq = (const float*)d_in[2];
    const float* Wk = (const float*)d_in[3];
    const float* bk = (const float*)d_in[4];
    const float* Wv = (const float*)d_in[5];
    const float* bv = (const float*)d_in[6];
    const float* Wo = (const float*)d_in[7];
    const float* bo = (const float*)d_in[8];
    float* out = (float*)d_out;

    void* p;
    cudaGetSymbolAddress(&p, g_q);   float* qp = (float*)p;
    cudaGetSymbolAddress(&p, g_k);   float* kp = (float*)p;
    cudaGetSymbolAddress(&p, g_v);   float* vp = (float*)p;
    cudaGetSymbolAddress(&p, g_xh);  __half* xh = (__half*)p;
    cudaGetSymbolAddress(&p, g_ch);  __half* chp = (__half*)p;
    cudaGetSymbolAddress(&p, g_qh);  __half* qhp = (__half*)p;
    cudaGetSymbolAddress(&p, g_kh);  __half* khp = (__half*)p;
    cudaGetSymbolAddress(&p, g_vh);  __half* vhp = (__half*)p;
    cudaGetSymbolAddress(&p, g_wqt); __half* wqt = (__half*)p;
    cudaGetSymbolAddress(&p, g_wkt); __half* wkt = (__half*)p;
    cudaGetSymbolAddress(&p, g_wvt); __half* wvt = (__half*)p;
    cudaGetSymbolAddress(&p, g_wot); __half* wot = (__half*)p;

    cudaFuncSetAttribute(mma_gemm, cudaFuncAttributeMaxDynamicSharedMemorySize,
                         GEMM_SMEM_BYTES);
    cudaFuncSetAttribute(attn_mma, cudaFuncAttributeMaxDynamicSharedMemorySize,
                         ATTN_SMEM);

    // Weight transposes + X convert
    cvt_transpose<<<dim3(HID / 32, HID / 32), dim3(32, 8)>>>(Wq, wqt, HID, HID);
    cvt_transpose<<<dim3(NG * DH / 32, HID / 32), dim3(32, 8)>>>(Wk, wkt, HID, NG * DH);
    cvt_transpose<<<dim3(NG * DH / 32, HID / 32), dim3(32, 8)>>>(Wv, wvt, HID, NG * DH);
    cvt_transpose<<<dim3(HID / 32, HID / 32), dim3(32, 8)>>>(Wo, wot, NH * DH, HID);
    {
        int n4 = S_LEN * HID / 4;
        cvt_half<<<(n4 + 255) / 256, 256>>>((const float4*)X, (__half2*)xh, n4);
    }

    // QKV projections (single fp16 HMMA)
    mma_gemm<<<dim3(HID / 128, S_LEN / 128), 256, GEMM_SMEM_BYTES>>>(
        xh, wqt, bq, qp, S_LEN, HID, HID);
    mma_gemm<<<dim3(NG * DH / 128, S_LEN / 128), 256, GEMM_SMEM_BYTES>>>(
        xh, wkt, bk, kp, S_LEN, NG * DH, HID);
    mma_gemm<<<dim3(NG * DH / 128, S_LEN / 128), 256, GEMM_SMEM_BYTES>>>(
        xh, wvt, bv, vp, S_LEN, NG * DH, HID);

    // RoPE (+fp16 convert) on q,k; plain convert for v
    rope_cvt<<<(S_LEN * 64 + 255) / 256, 256>>>(qp, kp, qhp, khp);
    {
        int n4 = S_LEN * NG * DH / 4;
        cvt_half<<<(n4 + 255) / 256, 256>>>((const float4*)vp, (__half2*)vhp, n4);
    }

    // Attention (writes fp16 ctx directly)
    attn_mma<<<dim3(S_LEN / 128, NH), 256, ATTN_SMEM>>>(qhp, khp, vhp, chp);

    // Output projection
    mma_gemm<<<dim3(HID / 128, S_LEN / 128), 256, GEMM_SMEM_BYTES>>>(
        chp, wot, bo, out, S_LEN, HID, NH * DH);
}

// round 10
// speedup vs baseline: 9.3705x; 1.0327x over previous
#include <cuda.h>
#include <cuda_runtime.h>
#include <cuda_fp16.h>
#include <math.h>

// ---------------------------------------------------------------------------
// Problem constants
// ---------------------------------------------------------------------------
#define S_LEN 2048
#define HID   4096
#define NH    32
#define NG    8
#define DH    128
#define NQKV  6144   // HID + 2*NG*DH

// ---------------------------------------------------------------------------
// Device-global scratch (allocation-free rule)
// ---------------------------------------------------------------------------
__device__ __align__(16) float g_qkv[S_LEN * NQKV];     // fused QKV output (fp32)
__device__ __align__(16) float g_bqkv[NQKV];            // concat bias

__device__ __align__(16) __half g_xh[S_LEN * HID];
__device__ __align__(16) __half g_ch[S_LEN * HID];      // ctx (fp16, from attention)
__device__ __align__(16) __half g_qh[S_LEN * NH * DH];
__device__ __align__(16) __half g_kh[S_LEN * NG * DH];
__device__ __align__(16) __half g_vh[S_LEN * NG * DH];
__device__ __align__(16) __half g_wqkvt[NQKV * HID];    // [Wq;Wk;Wv]^T [6144,4096] fp16
__device__ __align__(16) __half g_wot[HID * HID];       // Wo^T

// ---------------------------------------------------------------------------
// PTX helpers (sm_80-baseline: ldmatrix / mma.sync / cp.async)
// ---------------------------------------------------------------------------
__device__ __forceinline__ uint32_t smem_u32(const void* p) {
    uint32_t a;
    asm("{ .reg .u64 t; cvta.to.shared.u64 t, %1; cvt.u32.u64 %0, t; }"
        : "=r"(a) : "l"(p));
    return a;
}

__device__ __forceinline__ void ldsm4(uint32_t& r0, uint32_t& r1, uint32_t& r2,
                                      uint32_t& r3, uint32_t addr) {
    asm volatile("ldmatrix.sync.aligned.m8n8.x4.shared.b16 {%0,%1,%2,%3}, [%4];"
                 : "=r"(r0), "=r"(r1), "=r"(r2), "=r"(r3) : "r"(addr));
}

__device__ __forceinline__ void ldsm4t(uint32_t& r0, uint32_t& r1, uint32_t& r2,
                                       uint32_t& r3, uint32_t addr) {
    asm volatile("ldmatrix.sync.aligned.m8n8.x4.trans.shared.b16 {%0,%1,%2,%3}, [%4];"
                 : "=r"(r0), "=r"(r1), "=r"(r2), "=r"(r3) : "r"(addr));
}

__device__ __forceinline__ void mma16816(float* d, uint32_t a0, uint32_t a1,
                                         uint32_t a2, uint32_t a3,
                                         uint32_t b0, uint32_t b1) {
    asm volatile(
        "mma.sync.aligned.m16n8k16.row.col.f32.f16.f16.f32 "
        "{%0,%1,%2,%3}, {%4,%5,%6,%7}, {%8,%9}, {%0,%1,%2,%3};"
        : "+f"(d[0]), "+f"(d[1]), "+f"(d[2]), "+f"(d[3])
        : "r"(a0), "r"(a1), "r"(a2), "r"(a3), "r"(b0), "r"(b1));
}

__device__ __forceinline__ float ex2f(float x) {
    float r;
    asm("ex2.approx.ftz.f32 %0, %1;" : "=f"(r) : "f"(x));
    return r;
}

__device__ __forceinline__ uint32_t pack_half2(float a, float b) {
    __half2 h = __floats2half2_rn(a, b);
    return *(uint32_t*)&h;
}

#define CP_ASYNC16(smem_addr, gptr) \
    asm volatile("cp.async.cg.shared.global [%0], [%1], 16;" \
                 :: "r"(smem_addr), "l"(gptr))
#define CP_COMMIT() asm volatile("cp.async.commit_group;" ::: "memory")
#define CP_WAIT0()  asm volatile("cp.async.wait_group 0;" ::: "memory")
#define CP_WAIT1()  asm volatile("cp.async.wait_group 1;" ::: "memory")

// ---------------------------------------------------------------------------
// fp32 -> fp16, same layout. n4 = n/4 float4s.
// ---------------------------------------------------------------------------
__global__ void cvt_half(const float4* __restrict__ src, __half2* __restrict__ dst, int n4) {
    int i = blockIdx.x * blockDim.x + threadIdx.x;
    if (i >= n4) return;
    float4 v = src[i];
    dst[2 * i]     = __floats2half2_rn(v.x, v.y);
    dst[2 * i + 1] = __floats2half2_rn(v.z, v.w);
}

// ---------------------------------------------------------------------------
// Transpose + fp16: W[K,N] fp32 -> T[N,K] fp16. Block 32x8, tile 32x32.
// ---------------------------------------------------------------------------
__global__ void cvt_transpose(const float* __restrict__ W, __half* __restrict__ T,
                              int K, int N) {
    __shared__ float t[32][33];
    int x = blockIdx.x * 32;
    int y = blockIdx.y * 32;
    int tx = threadIdx.x, ty = threadIdx.y;
#pragma unroll
    for (int j = 0; j < 4; j++)
        t[ty + j * 8][tx] = W[(size_t)(y + ty + j * 8) * N + x + tx];
    __syncthreads();
#pragma unroll
    for (int j = 0; j < 4; j++)
        T[(size_t)(x + ty + j * 8) * K + y + tx] = __float2half_rn(t[tx][ty + j * 8]);
}

// ---------------------------------------------------------------------------
// Concat biases [bq | bk | bv] -> g_bqkv[6144]
// ---------------------------------------------------------------------------
__global__ void bias_concat(const float* __restrict__ bq, const float* __restrict__ bk,
                            const float* __restrict__ bv, float* __restrict__ b) {
    int i = blockIdx.x * blockDim.x + threadIdx.x;
    if (i >= NQKV) return;
    if (i < HID)             b[i] = bq[i];
    else if (i < HID + 1024) b[i] = bk[i - HID];
    else                     b[i] = bv[i - HID - 1024];
}

// ---------------------------------------------------------------------------
// HMMA fp16 GEMM: C[M,N] = A[M,K] @ B[N,K]^T + bias
// CTA tile 128x128, 8 warps (2x4), warp tile 64x32, BK=64, double-buffered.
// ---------------------------------------------------------------------------
#define ROWB 144
#define STAGE_BYTES (2 * 128 * ROWB)
#define GEMM_SMEM_BYTES (2 * STAGE_BYTES)

__global__ __launch_bounds__(256, 2)
void mma_gemm(const __half* __restrict__ A, const __half* __restrict__ B,
              const float* __restrict__ bias, float* __restrict__ C,
              int M, int N, int K) {
    extern __shared__ char smc[];
    const uint32_t sb = smem_u32(smc);
    const int tid = threadIdx.x;
    const int w = tid >> 5, lane = tid & 31;
    const int wm = w >> 2;
    const int wn = w & 3;
    const int m0 = blockIdx.y * 128;
    const int n0 = blockIdx.x * 128;

    size_t ga[4], gb[4];
    uint32_t so[4];
#pragma unroll
    for (int t = 0; t < 4; t++) {
        int i = tid + t * 256;
        int row = i >> 3, u = i & 7;
        ga[t] = (size_t)(m0 + row) * K + u * 8;
        gb[t] = (size_t)(n0 + row) * K + u * 8;
        so[t] = (uint32_t)(row * ROWB + u * 16);
    }

    const int NC = K >> 6;
    {
#pragma unroll
        for (int t = 0; t < 4; t++) {
            CP_ASYNC16(sb + so[t],              (const char*)(A + ga[t]));
            CP_ASYNC16(sb + 128 * ROWB + so[t], (const char*)(B + gb[t]));
        }
        CP_COMMIT();
    }

    float acc[4][4][4];
#pragma unroll
    for (int mi = 0; mi < 4; mi++)
#pragma unroll
        for (int ni = 0; ni < 4; ni++)
#pragma unroll
            for (int j = 0; j < 4; j++) acc[mi][ni][j] = 0.f;

    const int lr = lane & 15, lc = lane >> 4;
    const uint32_t a_lane_off = (uint32_t)((wm * 64 + lr) * ROWB + lc * 16);
    const uint32_t b_lane_off = (uint32_t)((wn * 32 + lr) * ROWB + lc * 16);

    for (int c = 0; c < NC; c++) {
        const int buf = c & 1;
        if (c + 1 < NC) {
            const size_t kc = (size_t)(c + 1) << 6;
            const uint32_t dst = sb + (uint32_t)((c + 1) & 1) * STAGE_BYTES;
#pragma unroll
            for (int t = 0; t < 4; t++) {
                CP_ASYNC16(dst + so[t],              (const char*)(A + ga[t] + kc));
                CP_ASYNC16(dst + 128 * ROWB + so[t], (const char*)(B + gb[t] + kc));
            }
            CP_COMMIT();
            CP_WAIT1();
        } else {
            CP_WAIT0();
        }
        __syncthreads();

        const uint32_t base = sb + (uint32_t)buf * STAGE_BYTES;
#pragma unroll
        for (int ks = 0; ks < 4; ks++) {
            const uint32_t koff = (uint32_t)(ks * 32);
            uint32_t bfr[4][2];
#pragma unroll
            for (int ni16 = 0; ni16 < 2; ni16++) {
                uint32_t r0, r1, r2, r3;
                ldsm4(r0, r1, r2, r3,
                      base + 128 * ROWB + b_lane_off + (uint32_t)(ni16 * 16 * ROWB) + koff);
                bfr[ni16 * 2][0] = r0; bfr[ni16 * 2][1] = r2;
                bfr[ni16 * 2 + 1][0] = r1; bfr[ni16 * 2 + 1][1] = r3;
            }
#pragma unroll
            for (int mi = 0; mi < 4; mi++) {
                uint32_t a0, a1, a2, a3;
                ldsm4(a0, a1, a2, a3,
                      base + a_lane_off + (uint32_t)(mi * 16 * ROWB) + koff);
#pragma unroll
                for (int ni = 0; ni < 4; ni++)
                    mma16816(acc[mi][ni], a0, a1, a2, a3, bfr[ni][0], bfr[ni][1]);
            }
        }
        __syncthreads();
    }

#pragma unroll
    for (int mi = 0; mi < 4; mi++) {
#pragma unroll
        for (int ni = 0; ni < 4; ni++) {
            int m = m0 + wm * 64 + mi * 16 + (lane >> 2);
            int n = n0 + wn * 32 + ni * 8 + 2 * (lane & 3);
            float2 bv = *(const float2*)&bias[n];
            float2 o0 = make_float2(acc[mi][ni][0] + bv.x, acc[mi][ni][1] + bv.y);
            float2 o1 = make_float2(acc[mi][ni][2] + bv.x, acc[mi][ni][3] + bv.y);
            *(float2*)&C[(size_t)m * N + n]       = o0;
            *(float2*)&C[(size_t)(m + 8) * N + n] = o1;
        }
    }
}

// ---------------------------------------------------------------------------
// RoPE + fp16 convert, fused for q, k AND v. Reads fused qkv (stride 6144):
//   q cols [0,4096), k cols [4096,5120), v cols [5120,6144).
// ---------------------------------------------------------------------------
__global__ void rope_cvt(const float* __restrict__ qkv,
                         __half* __restrict__ qh, __half* __restrict__ kh,
                         __half* __restrict__ vh) {
    int idx = blockIdx.x * blockDim.x + threadIdx.x;
    if (idx >= S_LEN * 64) return;
    int j = idx & 63;
    int s = idx >> 6;
    float inv = (float)exp(-(double)j * (9.210340371976184 / 64.0));
    float ang = (float)s * inv;
    float sn, cs;
    sincosf(ang, &sn, &cs);
    const float* row = qkv + (size_t)s * NQKV;

    __half* qo = qh + (size_t)s * (NH * DH) + j;
#pragma unroll
    for (int h = 0; h < NH; h++) {
        float x1 = row[h * DH + j];
        float x2 = row[h * DH + j + 64];
        qo[h * DH]      = __float2half_rn(x1 * cs - x2 * sn);
        qo[h * DH + 64] = __float2half_rn(x1 * sn + x2 * cs);
    }
    const float* krow = row + HID;
    __half* ko = kh + (size_t)s * (NG * DH) + j;
#pragma unroll
    for (int g = 0; g < NG; g++) {
        float x1 = krow[g * DH + j];
        float x2 = krow[g * DH + j + 64];
        ko[g * DH]      = __float2half_rn(x1 * cs - x2 * sn);
        ko[g * DH + 64] = __float2half_rn(x1 * sn + x2 * cs);
    }
    const float* vrow = row + HID + 1024;
    __half* vo = vh + (size_t)s * (NG * DH) + j;
#pragma unroll
    for (int g = 0; g < NG; g++) {
        vo[g * DH]      = __float2half_rn(vrow[g * DH + j]);
        vo[g * DH + 64] = __float2half_rn(vrow[g * DH + j + 64]);
    }
}

// ---------------------------------------------------------------------------
// Tensorized flash attention (fp16 HMMA, causal, GQA) — round 8 math,
// with REVERSED qb mapping (heavy CTAs launch first for wave packing).
// ---------------------------------------------------------------------------
#define AP 272
#define ATTN_KV (128 * AP)
#define ATTN_KVBUF (128 * AP)
#define ATTN_SMEM (ATTN_KV + 2 * ATTN_KVBUF)   // 104448 B

__global__ __launch_bounds__(256, 1)
void attn_mma(const __half* __restrict__ qh, const __half* __restrict__ kh,
              const __half* __restrict__ vh, __half* __restrict__ ch) {
    extern __shared__ char smc[];
    const uint32_t sb = smem_u32(smc);
    const int tid = threadIdx.x, w = tid >> 5, lane = tid & 31;
    const int qb = (int)gridDim.x - 1 - (int)blockIdx.x;   // heavy tiles first
    const int h = blockIdx.y, g = h >> 2;
    const int q0 = qb * 128;
    const int R = q0 + w * 16;

    for (int c = tid; c < 2048; c += 256) {
        int row = c >> 4, u = c & 15;
        size_t go = (size_t)(q0 + row) * (NH * DH) + h * DH + u * 8;
        CP_ASYNC16(sb + row * AP + u * 16, (const char*)(qh + go));
    }
    CP_COMMIT();

    const int ntiles = 2 * qb + 2;

    {
        uint32_t b0 = sb + ATTN_KV;
        for (int c = tid; c < 1024; c += 256) {
            int row = c >> 4, u = c & 15;
            size_t go = (size_t)row * (NG * DH) + g * DH + u * 8;
            uint32_t s = b0 + row * AP + u * 16;
            CP_ASYNC16(s,           (const char*)(kh + go));
            CP_ASYNC16(s + 64 * AP, (const char*)(vh + go));
        }
        CP_COMMIT();
    }

    float o[16][4];
#pragma unroll
    for (int t = 0; t < 16; t++)
#pragma unroll
        for (int j = 0; j < 4; j++) o[t][j] = 0.f;
    float m_run[2] = {-1e30f, -1e30f};
    float l_run[2] = {0.f, 0.f};

    const float SC = 0.12751879523171918f;   // (1/sqrt(128)) * log2(e)

    for (int kt = 0; kt < ntiles; kt++) {
        const int k0 = kt * 64;
        const int buf = kt & 1;
        if (kt + 1 < ntiles) {
            uint32_t b0 = sb + ATTN_KV + (uint32_t)(buf ^ 1) * ATTN_KVBUF;
            const int kn = (kt + 1) * 64;
            for (int c = tid; c < 1024; c += 256) {
                int row = c >> 4, u = c & 15;
                size_t go = (size_t)(kn + row) * (NG * DH) + g * DH + u * 8;
                uint32_t s = b0 + row * AP + u * 16;
                CP_ASYNC16(s,           (const char*)(kh + go));
                CP_ASYNC16(s + 64 * AP, (const char*)(vh + go));
            }
            CP_COMMIT();
            CP_WAIT1();
        } else {
            CP_WAIT0();
        }
        __syncthreads();

        if (k0 <= R + 15) {
            const uint32_t kb = sb + ATTN_KV + (uint32_t)buf * ATTN_KVBUF;

            // ---- S = Q K^T ----
            float sS[8][4];
#pragma unroll
            for (int t = 0; t < 8; t++)
#pragma unroll
                for (int j = 0; j < 4; j++) sS[t][j] = 0.f;

            const uint32_t q_lane = (uint32_t)((w * 16 + (lane & 7) + ((lane >> 3) & 1) * 8) * AP);
            const uint32_t q_col  = (uint32_t)((lane >> 4) * 16);
#pragma unroll
            for (int kc8 = 0; kc8 < 8; kc8++) {
                uint32_t a0, a1, a2, a3;
                ldsm4(a0, a1, a2, a3, sb + q_lane + (uint32_t)(kc8 * 32) + q_col);
#pragma unroll
                for (int kg = 0; kg < 4; kg++) {
                    uint32_t ka = kb
                        + (uint32_t)((kg * 16 + ((lane >> 4) & 1) * 8 + (lane & 7)) * AP)
                        + (uint32_t)(kc8 * 32 + ((lane >> 3) & 1) * 16);
                    uint32_t b0, b1, b2, b3;
                    ldsm4(b0, b1, b2, b3, ka);
                    mma16816(sS[2 * kg],     a0, a1, a2, a3, b0, b1);
                    mma16816(sS[2 * kg + 1], a0, a1, a2, a3, b2, b3);
                }
            }

            // ---- softmax (exp2 space) ----
            const int r0 = R + (lane >> 2), r1 = r0 + 8;
            const bool diag = (k0 + 63 > R);
            float mt0 = -1e30f, mt1 = -1e30f;
#pragma unroll
            for (int t = 0; t < 8; t++) {
                int cb = k0 + t * 8 + 2 * (lane & 3);
                float s0 = sS[t][0] * SC, s1 = sS[t][1] * SC;
                float s2 = sS[t][2] * SC, s3 = sS[t][3] * SC;
                if (diag) {
                    if (cb     > r0) s0 = -1e30f;
                    if (cb + 1 > r0) s1 = -1e30f;
                    if (cb     > r1) s2 = -1e30f;
                    if (cb + 1 > r1) s3 = -1e30f;
                }
                sS[t][0] = s0; sS[t][1] = s1; sS[t][2] = s2; sS[t][3] = s3;
                mt0 = fmaxf(mt0, fmaxf(s0, s1));
                mt1 = fmaxf(mt1, fmaxf(s2, s3));
            }
            mt0 = fmaxf(mt0, __shfl_xor_sync(0xffffffffu, mt0, 1));
            mt0 = fmaxf(mt0, __shfl_xor_sync(0xffffffffu, mt0, 2));
            mt1 = fmaxf(mt1, __shfl_xor_sync(0xffffffffu, mt1, 1));
            mt1 = fmaxf(mt1, __shfl_xor_sync(0xffffffffu, mt1, 2));
            float mn0 = fmaxf(m_run[0], mt0), mn1 = fmaxf(m_run[1], mt1);
            float corr0 = ex2f(m_run[0] - mn0), corr1 = ex2f(m_run[1] - mn1);
            m_run[0] = mn0; m_run[1] = mn1;
            float ls0 = 0.f, ls1 = 0.f;
#pragma unroll
            for (int t = 0; t < 8; t++) {
                float p0 = ex2f(sS[t][0] - mn0), p1 = ex2f(sS[t][1] - mn0);
                float p2 = ex2f(sS[t][2] - mn1), p3 = ex2f(sS[t][3] - mn1);
                ls0 += p0 + p1; ls1 += p2 + p3;
                sS[t][0] = p0; sS[t][1] = p1; sS[t][2] = p2; sS[t][3] = p3;
            }
            ls0 += __shfl_xor_sync(0xffffffffu, ls0, 1);
            ls0 += __shfl_xor_sync(0xffffffffu, ls0, 2);
            ls1 += __shfl_xor_sync(0xffffffffu, ls1, 1);
            ls1 += __shfl_xor_sync(0xffffffffu, ls1, 2);
            l_run[0] = l_run[0] * corr0 + ls0;
            l_run[1] = l_run[1] * corr1 + ls1;
#pragma unroll
            for (int t = 0; t < 16; t++) {
                o[t][0] *= corr0; o[t][1] *= corr0;
                o[t][2] *= corr1; o[t][3] *= corr1;
            }

            // ---- pack P into fp16 A fragments ----
            uint32_t pa[4][4];
#pragma unroll
            for (int kc = 0; kc < 4; kc++) {
                pa[kc][0] = pack_half2(sS[2 * kc][0],     sS[2 * kc][1]);
                pa[kc][1] = pack_half2(sS[2 * kc][2],     sS[2 * kc][3]);
                pa[kc][2] = pack_half2(sS[2 * kc + 1][0], sS[2 * kc + 1][1]);
                pa[kc][3] = pack_half2(sS[2 * kc + 1][2], sS[2 * kc + 1][3]);
            }

            // ---- O += P V ----
#pragma unroll
            for (int kc = 0; kc < 4; kc++) {
#pragma unroll
                for (int dp = 0; dp < 8; dp++) {
                    uint32_t va = kb + 64 * AP
                        + (uint32_t)((kc * 16 + ((lane >> 3) & 1) * 8 + (lane & 7)) * AP)
                        + (uint32_t)(dp * 32 + ((lane >> 4) & 1) * 16);
                    uint32_t v0, v1, v2, v3;
                    ldsm4t(v0, v1, v2, v3, va);
                    mma16816(o[2 * dp],     pa[kc][0], pa[kc][1], pa[kc][2], pa[kc][3], v0, v1);
                    mma16816(o[2 * dp + 1], pa[kc][0], pa[kc][1], pa[kc][2], pa[kc][3], v2, v3);
                }
            }
        }
        __syncthreads();
    }

    // ---- epilogue: normalize + write fp16 ctx ----
    float inv0 = 1.f / l_run[0], inv1 = 1.f / l_run[1];
    int r0 = R + (lane >> 2);
#pragma unroll
    for (int t = 0; t < 16; t++) {
        int col = t * 8 + 2 * (lane & 3);
        size_t o0 = (size_t)r0 * (NH * DH) + h * DH + col;
        size_t o1 = (size_t)(r0 + 8) * (NH * DH) + h * DH + col;
        *(uint32_t*)(ch + o0) = pack_half2(o[t][0] * inv0, o[t][1] * inv0);
        *(uint32_t*)(ch + o1) = pack_half2(o[t][2] * inv1, o[t][3] * inv1);
    }
}

// ---------------------------------------------------------------------------
// Launch
// ---------------------------------------------------------------------------
extern "C" void kernel_launch(void* const* d_in, const int* in_sizes, int n_in,
                              void* d_out, int out_size) {
    const float* X  = (const float*)d_in[0];
    const float* Wq = (const float*)d_in[1];
    const float* bq = (const float*)d_in[2];
    const float* Wk = (const float*)d_in[3];
    const float* bk = (const float*)d_in[4];
    const float* Wv = (const float*)d_in[5];
    const float* bv = (const float*)d_in[6];
    const float* Wo = (const float*)d_in[7];
    const float* bo = (const float*)d_in[8];
    float* out = (float*)d_out;

    void* p;
    cudaGetSymbolAddress(&p, g_qkv);   float* qkv = (float*)p;
    cudaGetSymbolAddress(&p, g_bqkv);  float* bqkv = (float*)p;
    cudaGetSymbolAddress(&p, g_xh);    __half* xh = (__half*)p;
    cudaGetSymbolAddress(&p, g_ch);    __half* chp = (__half*)p;
    cudaGetSymbolAddress(&p, g_qh);    __half* qhp = (__half*)p;
    cudaGetSymbolAddress(&p, g_kh);    __half* khp = (__half*)p;
    cudaGetSymbolAddress(&p, g_vh);    __half* vhp = (__half*)p;
    cudaGetSymbolAddress(&p, g_wqkvt); __half* wqkvt = (__half*)p;
    cudaGetSymbolAddress(&p, g_wot);   __half* wot = (__half*)p;

    cudaFuncSetAttribute(mma_gemm, cudaFuncAttributeMaxDynamicSharedMemorySize,
                         GEMM_SMEM_BYTES);
    cudaFuncSetAttribute(attn_mma, cudaFuncAttributeMaxDynamicSharedMemorySize,
                         ATTN_SMEM);

    // Weight transposes into the fused [6144,4096] buffer + Wo + X convert
    cvt_transpose<<<dim3(HID / 32, HID / 32), dim3(32, 8)>>>(
        Wq, wqkvt, HID, HID);
    cvt_transpose<<<dim3(NG * DH / 32, HID / 32), dim3(32, 8)>>>(
        Wk, wqkvt + (size_t)HID * HID, HID, NG * DH);
    cvt_transpose<<<dim3(NG * DH / 32, HID / 32), dim3(32, 8)>>>(
        Wv, wqkvt + (size_t)(HID + 1024) * HID, HID, NG * DH);
    cvt_transpose<<<dim3(HID / 32, HID / 32), dim3(32, 8)>>>(
        Wo, wot, NH * DH, HID);
    {
        int n4 = S_LEN * HID / 4;
        cvt_half<<<(n4 + 255) / 256, 256>>>((const float4*)X, (__half2*)xh, n4);
    }
    bias_concat<<<(NQKV + 255) / 256, 256>>>(bq, bk, bv, bqkv);

    // Fused QKV projection: one GEMM, N=6144 (full occupancy)
    mma_gemm<<<dim3(NQKV / 128, S_LEN / 128), 256, GEMM_SMEM_BYTES>>>(
        xh, wqkvt, bqkv, qkv, S_LEN, NQKV, HID);

    // RoPE + fp16 convert for q, k, v (single fused pass)
    rope_cvt<<<(S_LEN * 64 + 255) / 256, 256>>>(qkv, qhp, khp, vhp);

    // Attention (heavy-first scheduling; writes fp16 ctx directly)
    attn_mma<<<dim3(S_LEN / 128, NH), 256, ATTN_SMEM>>>(qhp, khp, vhp, chp);

    // Output projection
    mma_gemm<<<dim3(HID / 128, S_LEN / 128), 256, GEMM_SMEM_BYTES>>>(
        chp, wot, bo, out, S_LEN, HID, NH * DH);
}

// round 11
// speedup vs baseline: 9.4861x; 1.0123x over previous
#include <cuda.h>
#include <cuda_runtime.h>
#include <cuda_fp16.h>
#include <math.h>

// ---------------------------------------------------------------------------
// Problem constants
// ---------------------------------------------------------------------------
#define S_LEN 2048
#define HID   4096
#define NH    32
#define NG    8
#define DH    128
#define NQKV  6144   // HID + 2*NG*DH

// ---------------------------------------------------------------------------
// Device-global scratch (allocation-free rule)
// ---------------------------------------------------------------------------
__device__ __align__(16) float g_qkv[S_LEN * NQKV];     // fused QKV output (fp32)
__device__ __align__(16) float g_bqkv[NQKV];            // concat bias

__device__ __align__(16) __half g_xh[S_LEN * HID];
__device__ __align__(16) __half g_ch[S_LEN * HID];      // ctx (fp16, from attention)
__device__ __align__(16) __half g_qh[S_LEN * NH * DH];
__device__ __align__(16) __half g_kh[S_LEN * NG * DH];
__device__ __align__(16) __half g_vh[S_LEN * NG * DH];
__device__ __align__(16) __half g_wqkvt[NQKV * HID];    // [Wq;Wk;Wv]^T [6144,4096] fp16
__device__ __align__(16) __half g_wot[HID * HID];       // Wo^T

// ---------------------------------------------------------------------------
// PTX helpers (sm_80-baseline: ldmatrix / mma.sync / cp.async)
// ---------------------------------------------------------------------------
__device__ __forceinline__ uint32_t smem_u32(const void* p) {
    uint32_t a;
    asm("{ .reg .u64 t; cvta.to.shared.u64 t, %1; cvt.u32.u64 %0, t; }"
        : "=r"(a) : "l"(p));
    return a;
}

__device__ __forceinline__ void ldsm4(uint32_t& r0, uint32_t& r1, uint32_t& r2,
                                      uint32_t& r3, uint32_t addr) {
    asm volatile("ldmatrix.sync.aligned.m8n8.x4.shared.b16 {%0,%1,%2,%3}, [%4];"
                 : "=r"(r0), "=r"(r1), "=r"(r2), "=r"(r3) : "r"(addr));
}

__device__ __forceinline__ void ldsm4t(uint32_t& r0, uint32_t& r1, uint32_t& r2,
                                       uint32_t& r3, uint32_t addr) {
    asm volatile("ldmatrix.sync.aligned.m8n8.x4.trans.shared.b16 {%0,%1,%2,%3}, [%4];"
                 : "=r"(r0), "=r"(r1), "=r"(r2), "=r"(r3) : "r"(addr));
}

__device__ __forceinline__ void mma16816(float* d, uint32_t a0, uint32_t a1,
                                         uint32_t a2, uint32_t a3,
                                         uint32_t b0, uint32_t b1) {
    asm volatile(
        "mma.sync.aligned.m16n8k16.row.col.f32.f16.f16.f32 "
        "{%0,%1,%2,%3}, {%4,%5,%6,%7}, {%8,%9}, {%0,%1,%2,%3};"
        : "+f"(d[0]), "+f"(d[1]), "+f"(d[2]), "+f"(d[3])
        : "r"(a0), "r"(a1), "r"(a2), "r"(a3), "r"(b0), "r"(b1));
}

__device__ __forceinline__ float ex2f(float x) {
    float r;
    asm("ex2.approx.ftz.f32 %0, %1;" : "=f"(r) : "f"(x));
    return r;
}

__device__ __forceinline__ uint32_t pack_half2(float a, float b) {
    __half2 h = __floats2half2_rn(a, b);
    return *(uint32_t*)&h;
}

#define CP_ASYNC16(smem_addr, gptr) \
    asm volatile("cp.async.cg.shared.global [%0], [%1], 16;" \
                 :: "r"(smem_addr), "l"(gptr))
#define CP_COMMIT() asm volatile("cp.async.commit_group;" ::: "memory")
#define CP_WAIT0()  asm volatile("cp.async.wait_group 0;" ::: "memory")
#define CP_WAIT1()  asm volatile("cp.async.wait_group 1;" ::: "memory")

// ---------------------------------------------------------------------------
// fp32 -> fp16, same layout. n4 = n/4 float4s.
// ---------------------------------------------------------------------------
__global__ void cvt_half(const float4* __restrict__ src, __half2* __restrict__ dst, int n4) {
    int i = blockIdx.x * blockDim.x + threadIdx.x;
    if (i >= n4) return;
    float4 v = src[i];
    dst[2 * i]     = __floats2half2_rn(v.x, v.y);
    dst[2 * i + 1] = __floats2half2_rn(v.z, v.w);
}

// ---------------------------------------------------------------------------
// Transpose + fp16: W[K,N] fp32 -> T[N,K] fp16. Block 32x8, tile 32x32.
// ---------------------------------------------------------------------------
__global__ void cvt_transpose(const float* __restrict__ W, __half* __restrict__ T,
                              int K, int N) {
    __shared__ float t[32][33];
    int x = blockIdx.x * 32;
    int y = blockIdx.y * 32;
    int tx = threadIdx.x, ty = threadIdx.y;
#pragma unroll
    for (int j = 0; j < 4; j++)
        t[ty + j * 8][tx] = W[(size_t)(y + ty + j * 8) * N + x + tx];
    __syncthreads();
#pragma unroll
    for (int j = 0; j < 4; j++)
        T[(size_t)(x + ty + j * 8) * K + y + tx] = __float2half_rn(t[tx][ty + j * 8]);
}

// ---------------------------------------------------------------------------
// Concat biases [bq | bk | bv] -> g_bqkv[6144]
// ---------------------------------------------------------------------------
__global__ void bias_concat(const float* __restrict__ bq, const float* __restrict__ bk,
                            const float* __restrict__ bv, float* __restrict__ b) {
    int i = blockIdx.x * blockDim.x + threadIdx.x;
    if (i >= NQKV) return;
    if (i < HID)             b[i] = bq[i];
    else if (i < HID + 1024) b[i] = bk[i - HID];
    else                     b[i] = bv[i - HID - 1024];
}

// ---------------------------------------------------------------------------
// HMMA fp16 GEMM: C[M,N] = A[M,K] @ B[N,K]^T + bias  (unchanged, round 8/10)
// CTA tile 128x128, 8 warps (2x4), warp tile 64x32, BK=64, double-buffered.
// ---------------------------------------------------------------------------
#define ROWB 144
#define STAGE_BYTES (2 * 128 * ROWB)
#define GEMM_SMEM_BYTES (2 * STAGE_BYTES)

__global__ __launch_bounds__(256, 2)
void mma_gemm(const __half* __restrict__ A, const __half* __restrict__ B,
              const float* __restrict__ bias, float* __restrict__ C,
              int M, int N, int K) {
    extern __shared__ char smc[];
    const uint32_t sb = smem_u32(smc);
    const int tid = threadIdx.x;
    const int w = tid >> 5, lane = tid & 31;
    const int wm = w >> 2;
    const int wn = w & 3;
    const int m0 = blockIdx.y * 128;
    const int n0 = blockIdx.x * 128;

    size_t ga[4], gb[4];
    uint32_t so[4];
#pragma unroll
    for (int t = 0; t < 4; t++) {
        int i = tid + t * 256;
        int row = i >> 3, u = i & 7;
        ga[t] = (size_t)(m0 + row) * K + u * 8;
        gb[t] = (size_t)(n0 + row) * K + u * 8;
        so[t] = (uint32_t)(row * ROWB + u * 16);
    }

    const int NC = K >> 6;
    {
#pragma unroll
        for (int t = 0; t < 4; t++) {
            CP_ASYNC16(sb + so[t],              (const char*)(A + ga[t]));
            CP_ASYNC16(sb + 128 * ROWB + so[t], (const char*)(B + gb[t]));
        }
        CP_COMMIT();
    }

    float acc[4][4][4];
#pragma unroll
    for (int mi = 0; mi < 4; mi++)
#pragma unroll
        for (int ni = 0; ni < 4; ni++)
#pragma unroll
            for (int j = 0; j < 4; j++) acc[mi][ni][j] = 0.f;

    const int lr = lane & 15, lc = lane >> 4;
    const uint32_t a_lane_off = (uint32_t)((wm * 64 + lr) * ROWB + lc * 16);
    const uint32_t b_lane_off = (uint32_t)((wn * 32 + lr) * ROWB + lc * 16);

    for (int c = 0; c < NC; c++) {
        const int buf = c & 1;
        if (c + 1 < NC) {
            const size_t kc = (size_t)(c + 1) << 6;
            const uint32_t dst = sb + (uint32_t)((c + 1) & 1) * STAGE_BYTES;
#pragma unroll
            for (int t = 0; t < 4; t++) {
                CP_ASYNC16(dst + so[t],              (const char*)(A + ga[t] + kc));
                CP_ASYNC16(dst + 128 * ROWB + so[t], (const char*)(B + gb[t] + kc));
            }
            CP_COMMIT();
            CP_WAIT1();
        } else {
            CP_WAIT0();
        }
        __syncthreads();

        const uint32_t base = sb + (uint32_t)buf * STAGE_BYTES;
#pragma unroll
        for (int ks = 0; ks < 4; ks++) {
            const uint32_t koff = (uint32_t)(ks * 32);
            uint32_t bfr[4][2];
#pragma unroll
            for (int ni16 = 0; ni16 < 2; ni16++) {
                uint32_t r0, r1, r2, r3;
                ldsm4(r0, r1, r2, r3,
                      base + 128 * ROWB + b_lane_off + (uint32_t)(ni16 * 16 * ROWB) + koff);
                bfr[ni16 * 2][0] = r0; bfr[ni16 * 2][1] = r2;
                bfr[ni16 * 2 + 1][0] = r1; bfr[ni16 * 2 + 1][1] = r3;
            }
#pragma unroll
            for (int mi = 0; mi < 4; mi++) {
                uint32_t a0, a1, a2, a3;
                ldsm4(a0, a1, a2, a3,
                      base + a_lane_off + (uint32_t)(mi * 16 * ROWB) + koff);
#pragma unroll
                for (int ni = 0; ni < 4; ni++)
                    mma16816(acc[mi][ni], a0, a1, a2, a3, bfr[ni][0], bfr[ni][1]);
            }
        }
        __syncthreads();
    }

#pragma unroll
    for (int mi = 0; mi < 4; mi++) {
#pragma unroll
        for (int ni = 0; ni < 4; ni++) {
            int m = m0 + wm * 64 + mi * 16 + (lane >> 2);
            int n = n0 + wn * 32 + ni * 8 + 2 * (lane & 3);
            float2 bv = *(const float2*)&bias[n];
            float2 o0 = make_float2(acc[mi][ni][0] + bv.x, acc[mi][ni][1] + bv.y);
            float2 o1 = make_float2(acc[mi][ni][2] + bv.x, acc[mi][ni][3] + bv.y);
            *(float2*)&C[(size_t)m * N + n]       = o0;
            *(float2*)&C[(size_t)(m + 8) * N + n] = o1;
        }
    }
}

// ---------------------------------------------------------------------------
// RoPE + fp16 convert, fused for q, k AND v (reads fused qkv, stride 6144).
// ---------------------------------------------------------------------------
__global__ void rope_cvt(const float* __restrict__ qkv,
                         __half* __restrict__ qh, __half* __restrict__ kh,
                         __half* __restrict__ vh) {
    int idx = blockIdx.x * blockDim.x + threadIdx.x;
    if (idx >= S_LEN * 64) return;
    int j = idx & 63;
    int s = idx >> 6;
    float inv = (float)exp(-(double)j * (9.210340371976184 / 64.0));
    float ang = (float)s * inv;
    float sn, cs;
    sincosf(ang, &sn, &cs);
    const float* row = qkv + (size_t)s * NQKV;

    __half* qo = qh + (size_t)s * (NH * DH) + j;
#pragma unroll
    for (int h = 0; h < NH; h++) {
        float x1 = row[h * DH + j];
        float x2 = row[h * DH + j + 64];
        qo[h * DH]      = __float2half_rn(x1 * cs - x2 * sn);
        qo[h * DH + 64] = __float2half_rn(x1 * sn + x2 * cs);
    }
    const float* krow = row + HID;
    __half* ko = kh + (size_t)s * (NG * DH) + j;
#pragma unroll
    for (int g = 0; g < NG; g++) {
        float x1 = krow[g * DH + j];
        float x2 = krow[g * DH + j + 64];
        ko[g * DH]      = __float2half_rn(x1 * cs - x2 * sn);
        ko[g * DH + 64] = __float2half_rn(x1 * sn + x2 * cs);
    }
    const float* vrow = row + HID + 1024;
    __half* vo = vh + (size_t)s * (NG * DH) + j;
#pragma unroll
    for (int g = 0; g < NG; g++) {
        vo[g * DH]      = __float2half_rn(vrow[g * DH + j]);
        vo[g * DH + 64] = __float2half_rn(vrow[g * DH + j + 64]);
    }
}

// ---------------------------------------------------------------------------
// Tensorized flash attention (fp16 HMMA, causal, GQA).
// NEW: BM=64, 128 threads (4 warps), 2 CTAs/SM for cross-CTA phase overlap.
// Per-row math identical to round 8/10 (same 64-key tile sequence).
// Grid (S/64, NH), heavy-first qb mapping. smem 87040 B.
// ---------------------------------------------------------------------------
#define AP 272
#define ATTN_KV (64 * AP)                       // Q region: 64 rows
#define ATTN_KVBUF (128 * AP)                   // K 64 rows + V 64 rows
#define ATTN_SMEM (ATTN_KV + 2 * ATTN_KVBUF)    // 87040 B

__global__ __launch_bounds__(128, 2)
void attn_mma(const __half* __restrict__ qh, const __half* __restrict__ kh,
              const __half* __restrict__ vh, __half* __restrict__ ch) {
    extern __shared__ char smc[];
    const uint32_t sb = smem_u32(smc);
    const int tid = threadIdx.x, w = tid >> 5, lane = tid & 31;
    const int qb = (int)gridDim.x - 1 - (int)blockIdx.x;   // heavy tiles first
    const int h = blockIdx.y, g = h >> 2;
    const int q0 = qb * 64;
    const int R = q0 + w * 16;

    // Load Q tile: 64 rows x 16 chunks of 16B
    for (int c = tid; c < 1024; c += 128) {
        int row = c >> 4, u = c & 15;
        size_t go = (size_t)(q0 + row) * (NH * DH) + h * DH + u * 8;
        CP_ASYNC16(sb + row * AP + u * 16, (const char*)(qh + go));
    }
    CP_COMMIT();

    const int ntiles = qb + 1;

    // Prologue: KV tile 0 into buffer 0
    {
        uint32_t b0 = sb + ATTN_KV;
        for (int c = tid; c < 1024; c += 128) {
            int row = c >> 4, u = c & 15;
            size_t go = (size_t)row * (NG * DH) + g * DH + u * 8;
            uint32_t s = b0 + row * AP + u * 16;
            CP_ASYNC16(s,           (const char*)(kh + go));
            CP_ASYNC16(s + 64 * AP, (const char*)(vh + go));
        }
        CP_COMMIT();
    }

    float o[16][4];
#pragma unroll
    for (int t = 0; t < 16; t++)
#pragma unroll
        for (int j = 0; j < 4; j++) o[t][j] = 0.f;
    float m_run[2] = {-1e30f, -1e30f};
    float l_run[2] = {0.f, 0.f};

    const float SC = 0.12751879523171918f;   // (1/sqrt(128)) * log2(e)

    for (int kt = 0; kt < ntiles; kt++) {
        const int k0 = kt * 64;
        const int buf = kt & 1;
        if (kt + 1 < ntiles) {
            uint32_t b0 = sb + ATTN_KV + (uint32_t)(buf ^ 1) * ATTN_KVBUF;
            const int kn = (kt + 1) * 64;
            for (int c = tid; c < 1024; c += 128) {
                int row = c >> 4, u = c & 15;
                size_t go = (size_t)(kn + row) * (NG * DH) + g * DH + u * 8;
                uint32_t s = b0 + row * AP + u * 16;
                CP_ASYNC16(s,           (const char*)(kh + go));
                CP_ASYNC16(s + 64 * AP, (const char*)(vh + go));
            }
            CP_COMMIT();
            CP_WAIT1();
        } else {
            CP_WAIT0();
        }
        __syncthreads();

        {
            const uint32_t kb = sb + ATTN_KV + (uint32_t)buf * ATTN_KVBUF;

            // ---- S = Q K^T ----
            float sS[8][4];
#pragma unroll
            for (int t = 0; t < 8; t++)
#pragma unroll
                for (int j = 0; j < 4; j++) sS[t][j] = 0.f;

            const uint32_t q_lane = (uint32_t)((w * 16 + (lane & 7) + ((lane >> 3) & 1) * 8) * AP);
            const uint32_t q_col  = (uint32_t)((lane >> 4) * 16);
#pragma unroll
            for (int kc8 = 0; kc8 < 8; kc8++) {
                uint32_t a0, a1, a2, a3;
                ldsm4(a0, a1, a2, a3, sb + q_lane + (uint32_t)(kc8 * 32) + q_col);
#pragma unroll
                for (int kg = 0; kg < 4; kg++) {
                    uint32_t ka = kb
                        + (uint32_t)((kg * 16 + ((lane >> 4) & 1) * 8 + (lane & 7)) * AP)
                        + (uint32_t)(kc8 * 32 + ((lane >> 3) & 1) * 16);
                    uint32_t b0, b1, b2, b3;
                    ldsm4(b0, b1, b2, b3, ka);
                    mma16816(sS[2 * kg],     a0, a1, a2, a3, b0, b1);
                    mma16816(sS[2 * kg + 1], a0, a1, a2, a3, b2, b3);
                }
            }

            // ---- softmax (exp2 space) ----
            const int r0 = R + (lane >> 2), r1 = r0 + 8;
            const bool diag = (k0 + 63 > R);
            float mt0 = -1e30f, mt1 = -1e30f;
#pragma unroll
            for (int t = 0; t < 8; t++) {
                int cb = k0 + t * 8 + 2 * (lane & 3);
                float s0 = sS[t][0] * SC, s1 = sS[t][1] * SC;
                float s2 = sS[t][2] * SC, s3 = sS[t][3] * SC;
                if (diag) {
                    if (cb     > r0) s0 = -1e30f;
                    if (cb + 1 > r0) s1 = -1e30f;
                    if (cb     > r1) s2 = -1e30f;
                    if (cb + 1 > r1) s3 = -1e30f;
                }
                sS[t][0] = s0; sS[t][1] = s1; sS[t][2] = s2; sS[t][3] = s3;
                mt0 = fmaxf(mt0, fmaxf(s0, s1));
                mt1 = fmaxf(mt1, fmaxf(s2, s3));
            }
            mt0 = fmaxf(mt0, __shfl_xor_sync(0xffffffffu, mt0, 1));
            mt0 = fmaxf(mt0, __shfl_xor_sync(0xffffffffu, mt0, 2));
            mt1 = fmaxf(mt1, __shfl_xor_sync(0xffffffffu, mt1, 1));
            mt1 = fmaxf(mt1, __shfl_xor_sync(0xffffffffu, mt1, 2));
            float mn0 = fmaxf(m_run[0], mt0), mn1 = fmaxf(m_run[1], mt1);
            float corr0 = ex2f(m_run[0] - mn0), corr1 = ex2f(m_run[1] - mn1);
            m_run[0] = mn0; m_run[1] = mn1;
            float ls0 = 0.f, ls1 = 0.f;
#pragma unroll
            for (int t = 0; t < 8; t++) {
                float p0 = ex2f(sS[t][0] - mn0), p1 = ex2f(sS[t][1] - mn0);
                float p2 = ex2f(sS[t][2] - mn1), p3 = ex2f(sS[t][3] - mn1);
                ls0 += p0 + p1; ls1 += p2 + p3;
                sS[t][0] = p0; sS[t][1] = p1; sS[t][2] = p2; sS[t][3] = p3;
            }
            ls0 += __shfl_xor_sync(0xffffffffu, ls0, 1);
            ls0 += __shfl_xor_sync(0xffffffffu, ls0, 2);
            ls1 += __shfl_xor_sync(0xffffffffu, ls1, 1);
            ls1 += __shfl_xor_sync(0xffffffffu, ls1, 2);
            l_run[0] = l_run[0] * corr0 + ls0;
            l_run[1] = l_run[1] * corr1 + ls1;
#pragma unroll
            for (int t = 0; t < 16; t++) {
                o[t][0] *= corr0; o[t][1] *= corr0;
                o[t][2] *= corr1; o[t][3] *= corr1;
            }

            // ---- pack P into fp16 A fragments ----
            uint32_t pa[4][4];
#pragma unroll
            for (int kc = 0; kc < 4; kc++) {
                pa[kc][0] = pack_half2(sS[2 * kc][0],     sS[2 * kc][1]);
                pa[kc][1] = pack_half2(sS[2 * kc][2],     sS[2 * kc][3]);
                pa[kc][2] = pack_half2(sS[2 * kc + 1][0], sS[2 * kc + 1][1]);
                pa[kc][3] = pack_half2(sS[2 * kc + 1][2], sS[2 * kc + 1][3]);
            }

            // ---- O += P V ----
#pragma unroll
            for (int kc = 0; kc < 4; kc++) {
#pragma unroll
                for (int dp = 0; dp < 8; dp++) {
                    uint32_t va = kb + 64 * AP
                        + (uint32_t)((kc * 16 + ((lane >> 3) & 1) * 8 + (lane & 7)) * AP)
                        + (uint32_t)(dp * 32 + ((lane >> 4) & 1) * 16);
                    uint32_t v0, v1, v2, v3;
                    ldsm4t(v0, v1, v2, v3, va);
                    mma16816(o[2 * dp],     pa[kc][0], pa[kc][1], pa[kc][2], pa[kc][3], v0, v1);
                    mma16816(o[2 * dp + 1], pa[kc][0], pa[kc][1], pa[kc][2], pa[kc][3], v2, v3);
                }
            }
        }
        __syncthreads();
    }

    // ---- epilogue: normalize + write fp16 ctx ----
    float inv0 = 1.f / l_run[0], inv1 = 1.f / l_run[1];
    int r0 = R + (lane >> 2);
#pragma unroll
    for (int t = 0; t < 16; t++) {
        int col = t * 8 + 2 * (lane & 3);
        size_t o0 = (size_t)r0 * (NH * DH) + h * DH + col;
        size_t o1 = (size_t)(r0 + 8) * (NH * DH) + h * DH + col;
        *(uint32_t*)(ch + o0) = pack_half2(o[t][0] * inv0, o[t][1] * inv0);
        *(uint32_t*)(ch + o1) = pack_half2(o[t][2] * inv1, o[t][3] * inv1);
    }
}

// ---------------------------------------------------------------------------
// Launch  (order: launch index 5 = fused QKV mma_gemm for ncu -s 5 -c 1)
// ---------------------------------------------------------------------------
extern "C" void kernel_launch(void* const* d_in, const int* in_sizes, int n_in,
                              void* d_out, int out_size) {
    const float* X  = (const float*)d_in[0];
    const float* Wq = (const float*)d_in[1];
    const float* bq = (const float*)d_in[2];
    const float* Wk = (const float*)d_in[3];
    const float* bk = (const float*)d_in[4];
    const float* Wv = (const float*)d_in[5];
    const float* bv = (const float*)d_in[6];
    const float* Wo = (const float*)d_in[7];
    const float* bo = (const float*)d_in[8];
    float* out = (float*)d_out;

    void* p;
    cudaGetSymbolAddress(&p, g_qkv);   float* qkv = (float*)p;
    cudaGetSymbolAddress(&p, g_bqkv);  float* bqkv = (float*)p;
    cudaGetSymbolAddress(&p, g_xh);    __half* xh = (__half*)p;
    cudaGetSymbolAddress(&p, g_ch);    __half* chp = (__half*)p;
    cudaGetSymbolAddress(&p, g_qh);    __half* qhp = (__half*)p;
    cudaGetSymbolAddress(&p, g_kh);    __half* khp = (__half*)p;
    cudaGetSymbolAddress(&p, g_vh);    __half* vhp = (__half*)p;
    cudaGetSymbolAddress(&p, g_wqkvt); __half* wqkvt = (__half*)p;
    cudaGetSymbolAddress(&p, g_wot);   __half* wot = (__half*)p;

    cudaFuncSetAttribute(mma_gemm, cudaFuncAttributeMaxDynamicSharedMemorySize,
                         GEMM_SMEM_BYTES);
    cudaFuncSetAttribute(attn_mma, cudaFuncAttributeMaxDynamicSharedMemorySize,
                         ATTN_SMEM);

    // Launches 0-4: bias concat, QKV weight transposes, X convert
    bias_concat<<<(NQKV + 255) / 256, 256>>>(bq, bk, bv, bqkv);
    cvt_transpose<<<dim3(HID / 32, HID / 32), dim3(32, 8)>>>(
        Wq, wqkvt, HID, HID);
    cvt_transpose<<<dim3(NG * DH / 32, HID / 32), dim3(32, 8)>>>(
        Wk, wqkvt + (size_t)HID * HID, HID, NG * DH);
    cvt_transpose<<<dim3(NG * DH / 32, HID / 32), dim3(32, 8)>>>(
        Wv, wqkvt + (size_t)(HID + 1024) * HID, HID, NG * DH);
    {
        int n4 = S_LEN * HID / 4;
        cvt_half<<<(n4 + 255) / 256, 256>>>((const float4*)X, (__half2*)xh, n4);
    }

    // Launch 5 (ncu capture target): fused QKV projection, N=6144
    mma_gemm<<<dim3(NQKV / 128, S_LEN / 128), 256, GEMM_SMEM_BYTES>>>(
        xh, wqkvt, bqkv, qkv, S_LEN, NQKV, HID);

    // Wo transpose (only needed before O-projection)
    cvt_transpose<<<dim3(HID / 32, HID / 32), dim3(32, 8)>>>(
        Wo, wot, NH * DH, HID);

    // RoPE + fp16 convert for q, k, v (single fused pass)
    rope_cvt<<<(S_LEN * 64 + 255) / 256, 256>>>(qkv, qhp, khp, vhp);

    // Attention: BM=64, 4 warps, 2 CTAs/SM, heavy-first
    attn_mma<<<dim3(S_LEN / 64, NH), 128, ATTN_SMEM>>>(qhp, khp, vhp, chp);

    // Output projection
    mma_gemm<<<dim3(HID / 128, S_LEN / 128), 256, GEMM_SMEM_BYTES>>>(
        chp, wot, bo, out, S_LEN, HID, NH * DH);
}

// round 12
// speedup vs baseline: 10.7918x; 1.1376x over previous
#include <cuda.h>
#include <cuda_runtime.h>
#include <cuda_fp16.h>
#include <math.h>

// ---------------------------------------------------------------------------
// Problem constants
// ---------------------------------------------------------------------------
#define S_LEN 2048
#define HID   4096
#define NH    32
#define NG    8
#define DH    128
#define NQKV  6144   // HID + 2*NG*DH

// ---------------------------------------------------------------------------
// Device-global scratch (allocation-free rule)
// ---------------------------------------------------------------------------
__device__ __align__(16) float g_qkv[S_LEN * NQKV];     // fused QKV output (fp32)
__device__ __align__(16) float g_bqkv[NQKV];            // concat bias

__device__ __align__(16) __half g_xh[S_LEN * HID];
__device__ __align__(16) __half g_ch[S_LEN * HID];      // ctx (fp16, from attention)
__device__ __align__(16) __half g_qh[S_LEN * NH * DH];
__device__ __align__(16) __half g_kh[S_LEN * NG * DH];
__device__ __align__(16) __half g_vh[S_LEN * NG * DH];
__device__ __align__(16) __half g_wqkv[HID * NQKV];     // [Wq|Wk|Wv] [K=4096, N=6144] fp16
__device__ __align__(16) __half g_wo[HID * HID];        // Wo [K,N] fp16 (native layout)

// ---------------------------------------------------------------------------
// PTX helpers (sm_80-baseline: ldmatrix / mma.sync / cp.async)
// ---------------------------------------------------------------------------
__device__ __forceinline__ uint32_t smem_u32(const void* p) {
    uint32_t a;
    asm("{ .reg .u64 t; cvta.to.shared.u64 t, %1; cvt.u32.u64 %0, t; }"
        : "=r"(a) : "l"(p));
    return a;
}

__device__ __forceinline__ void ldsm4(uint32_t& r0, uint32_t& r1, uint32_t& r2,
                                      uint32_t& r3, uint32_t addr) {
    asm volatile("ldmatrix.sync.aligned.m8n8.x4.shared.b16 {%0,%1,%2,%3}, [%4];"
                 : "=r"(r0), "=r"(r1), "=r"(r2), "=r"(r3) : "r"(addr));
}

__device__ __forceinline__ void ldsm4t(uint32_t& r0, uint32_t& r1, uint32_t& r2,
                                       uint32_t& r3, uint32_t addr) {
    asm volatile("ldmatrix.sync.aligned.m8n8.x4.trans.shared.b16 {%0,%1,%2,%3}, [%4];"
                 : "=r"(r0), "=r"(r1), "=r"(r2), "=r"(r3) : "r"(addr));
}

__device__ __forceinline__ void mma16816(float* d, uint32_t a0, uint32_t a1,
                                         uint32_t a2, uint32_t a3,
                                         uint32_t b0, uint32_t b1) {
    asm volatile(
        "mma.sync.aligned.m16n8k16.row.col.f32.f16.f16.f32 "
        "{%0,%1,%2,%3}, {%4,%5,%6,%7}, {%8,%9}, {%0,%1,%2,%3};"
        : "+f"(d[0]), "+f"(d[1]), "+f"(d[2]), "+f"(d[3])
        : "r"(a0), "r"(a1), "r"(a2), "r"(a3), "r"(b0), "r"(b1));
}

__device__ __forceinline__ float ex2f(float x) {
    float r;
    asm("ex2.approx.ftz.f32 %0, %1;" : "=f"(r) : "f"(x));
    return r;
}

__device__ __forceinline__ uint32_t pack_half2(float a, float b) {
    __half2 h = __floats2half2_rn(a, b);
    return *(uint32_t*)&h;
}

#define CP_ASYNC16(smem_addr, gptr) \
    asm volatile("cp.async.cg.shared.global [%0], [%1], 16;" \
                 :: "r"(smem_addr), "l"(gptr))
#define CP_COMMIT() asm volatile("cp.async.commit_group;" ::: "memory")
#define CP_WAIT0()  asm volatile("cp.async.wait_group 0;" ::: "memory")
#define CP_WAIT1()  asm volatile("cp.async.wait_group 1;" ::: "memory")

// ---------------------------------------------------------------------------
// fp32 -> fp16, same layout. n4 = n/4 float4s.
// ---------------------------------------------------------------------------
__global__ void cvt_half(const float4* __restrict__ src, __half2* __restrict__ dst, int n4) {
    int i = blockIdx.x * blockDim.x + threadIdx.x;
    if (i >= n4) return;
    float4 v = src[i];
    dst[2 * i]     = __floats2half2_rn(v.x, v.y);
    dst[2 * i + 1] = __floats2half2_rn(v.z, v.w);
}

// ---------------------------------------------------------------------------
// Merged weight convert (NO transpose): Wq/Wk/Wv -> fused [K,6144] fp16,
// Wo -> [K,N] fp16. One fully-coalesced pass over all weights.
// ---------------------------------------------------------------------------
#define Q4 (HID * HID / 4)          // 4194304 float4s in Wq
#define K4 (HID * 1024 / 4)         // 1048576 float4s in Wk (= Wv)
#define WTOT4 (2 * Q4 + 2 * K4)     // 10485760

__global__ void wcvt(const float4* __restrict__ Wq, const float4* __restrict__ Wk,
                     const float4* __restrict__ Wv, const float4* __restrict__ Wo,
                     __half2* __restrict__ fused, __half2* __restrict__ wo) {
    size_t i = (size_t)blockIdx.x * blockDim.x + threadIdx.x;
    if (i >= WTOT4) return;
    float4 v;
    __half2* out;
    size_t d;   // element offset (multiple of 4)
    if (i < Q4) {
        size_t j = i * 4;
        v = Wq[i];
        d = (j >> 12) * (size_t)NQKV + (j & 4095);
        out = fused;
    } else if (i < Q4 + K4) {
        size_t j = (i - Q4) * 4;
        v = Wk[i - Q4];
        d = (j >> 10) * (size_t)NQKV + 4096 + (j & 1023);
        out = fused;
    } else if (i < Q4 + 2 * K4) {
        size_t j = (i - Q4 - K4) * 4;
        v = Wv[i - Q4 - K4];
        d = (j >> 10) * (size_t)NQKV + 5120 + (j & 1023);
        out = fused;
    } else {
        size_t ii = i - Q4 - 2 * K4;
        v = Wo[ii];
        d = ii * 4;
        out = wo;
    }
    out[d >> 1]       = __floats2half2_rn(v.x, v.y);
    out[(d >> 1) + 1] = __floats2half2_rn(v.z, v.w);
}

// ---------------------------------------------------------------------------
// Concat biases [bq | bk | bv] -> g_bqkv[6144]
// ---------------------------------------------------------------------------
__global__ void bias_concat(const float* __restrict__ bq, const float* __restrict__ bk,
                            const float* __restrict__ bv, float* __restrict__ b) {
    int i = blockIdx.x * blockDim.x + threadIdx.x;
    if (i >= NQKV) return;
    if (i < HID)             b[i] = bq[i];
    else if (i < HID + 1024) b[i] = bk[i - HID];
    else                     b[i] = bv[i - HID - 1024];
}

// ---------------------------------------------------------------------------
// HMMA fp16 GEMM: C[M,N] = A[M,K] @ B[K,N] + bias
// A: [M,K] K-contig fp16.  B: [K,N] N-contig fp16 (NATIVE layout, no transpose)
// — B fragments built via ldmatrix.trans (pattern proven in attention PV).
// CTA tile 128x128, 8 warps (2x4), warp tile 64x32, BK=64, double-buffered.
// smem stage: A 128x144B = 18432 | B 64 k-rows x 272B = 17408 -> 35840/stage.
// ---------------------------------------------------------------------------
#define AROWB 144
#define BROWB 272
#define A_BYTES (128 * AROWB)
#define STAGE_BYTES (A_BYTES + 64 * BROWB)
#define GEMM_SMEM_BYTES (2 * STAGE_BYTES)   // 71680

__global__ __launch_bounds__(256, 2)
void mma_gemm(const __half* __restrict__ A, const __half* __restrict__ B,
              const float* __restrict__ bias, float* __restrict__ C,
              int M, int N, int K) {
    extern __shared__ char smc[];
    const uint32_t sb = smem_u32(smc);
    const int tid = threadIdx.x;
    const int w = tid >> 5, lane = tid & 31;
    const int wm = w >> 2;
    const int wn = w & 3;
    const int m0 = blockIdx.y * 128;
    const int n0 = blockIdx.x * 128;

    // A: 128 rows x 8 16B-units; B: 64 k-rows x 16 16B-units. 4 each per thread.
    size_t ga[4], gb[4];
    uint32_t soA[4], soB[4];
#pragma unroll
    for (int t = 0; t < 4; t++) {
        int i = tid + t * 256;
        int arow = i >> 3, au = i & 7;
        ga[t]  = (size_t)(m0 + arow) * K + au * 8;
        soA[t] = (uint32_t)(arow * AROWB + au * 16);
        int brow = i >> 4, bu = i & 15;
        gb[t]  = (size_t)brow * N + n0 + bu * 8;
        soB[t] = (uint32_t)(A_BYTES + brow * BROWB + bu * 16);
    }

    const int NC = K >> 6;
    {
#pragma unroll
        for (int t = 0; t < 4; t++) {
            CP_ASYNC16(sb + soA[t], (const char*)(A + ga[t]));
            CP_ASYNC16(sb + soB[t], (const char*)(B + gb[t]));
        }
        CP_COMMIT();
    }

    float acc[4][4][4];
#pragma unroll
    for (int mi = 0; mi < 4; mi++)
#pragma unroll
        for (int ni = 0; ni < 4; ni++)
#pragma unroll
            for (int j = 0; j < 4; j++) acc[mi][ni][j] = 0.f;

    const int lr = lane & 15, lc = lane >> 4;
    const uint32_t a_lane_off = (uint32_t)((wm * 64 + lr) * AROWB + lc * 16);
    // B (trans) lane addressing: k-row = ks*16 + ((lane>>3)&1)*8 + (lane&7),
    // n-byte  = wn*64 + ni16*32 + ((lane>>4)&1)*16
    const uint32_t b_lane_row = (uint32_t)((((lane >> 3) & 1) * 8 + (lane & 7)) * BROWB);
    const uint32_t b_lane_col = (uint32_t)(wn * 64 + ((lane >> 4) & 1) * 16);

    for (int c = 0; c < NC; c++) {
        const int buf = c & 1;
        if (c + 1 < NC) {
            const size_t kcA = (size_t)(c + 1) << 6;          // A: +64 k elems
            const size_t kcB = (size_t)(c + 1) * 64 * N;      // B: +64 k rows
            const uint32_t dst = sb + (uint32_t)((c + 1) & 1) * STAGE_BYTES;
#pragma unroll
            for (int t = 0; t < 4; t++) {
                CP_ASYNC16(dst + soA[t], (const char*)(A + ga[t] + kcA));
                CP_ASYNC16(dst + soB[t], (const char*)(B + gb[t] + kcB));
            }
            CP_COMMIT();
            CP_WAIT1();
        } else {
            CP_WAIT0();
        }
        __syncthreads();

        const uint32_t base = sb + (uint32_t)buf * STAGE_BYTES;
#pragma unroll
        for (int ks = 0; ks < 4; ks++) {
            uint32_t bfr[4][2];
#pragma unroll
            for (int ni16 = 0; ni16 < 2; ni16++) {
                uint32_t v0, v1, v2, v3;
                ldsm4t(v0, v1, v2, v3,
                       base + A_BYTES + (uint32_t)(ks * 16) * BROWB + b_lane_row
                            + b_lane_col + (uint32_t)(ni16 * 32));
                bfr[ni16 * 2][0]     = v0; bfr[ni16 * 2][1]     = v1;
                bfr[ni16 * 2 + 1][0] = v2; bfr[ni16 * 2 + 1][1] = v3;
            }
            const uint32_t koff = (uint32_t)(ks * 32);
#pragma unroll
            for (int mi = 0; mi < 4; mi++) {
                uint32_t a0, a1, a2, a3;
                ldsm4(a0, a1, a2, a3,
                      base + a_lane_off + (uint32_t)(mi * 16 * AROWB) + koff);
#pragma unroll
                for (int ni = 0; ni < 4; ni++)
                    mma16816(acc[mi][ni], a0, a1, a2, a3, bfr[ni][0], bfr[ni][1]);
            }
        }
        __syncthreads();
    }

#pragma unroll
    for (int mi = 0; mi < 4; mi++) {
#pragma unroll
        for (int ni = 0; ni < 4; ni++) {
            int m = m0 + wm * 64 + mi * 16 + (lane >> 2);
            int n = n0 + wn * 32 + ni * 8 + 2 * (lane & 3);
            float2 bv = *(const float2*)&bias[n];
            float2 o0 = make_float2(acc[mi][ni][0] + bv.x, acc[mi][ni][1] + bv.y);
            float2 o1 = make_float2(acc[mi][ni][2] + bv.x, acc[mi][ni][3] + bv.y);
            *(float2*)&C[(size_t)m * N + n]       = o0;
            *(float2*)&C[(size_t)(m + 8) * N + n] = o1;
        }
    }
}

// ---------------------------------------------------------------------------
// RoPE + fp16 convert, fused for q, k AND v (reads fused qkv, stride 6144).
// ---------------------------------------------------------------------------
__global__ void rope_cvt(const float* __restrict__ qkv,
                         __half* __restrict__ qh, __half* __restrict__ kh,
                         __half* __restrict__ vh) {
    int idx = blockIdx.x * blockDim.x + threadIdx.x;
    if (idx >= S_LEN * 64) return;
    int j = idx & 63;
    int s = idx >> 6;
    float inv = (float)exp(-(double)j * (9.210340371976184 / 64.0));
    float ang = (float)s * inv;
    float sn, cs;
    sincosf(ang, &sn, &cs);
    const float* row = qkv + (size_t)s * NQKV;

    __half* qo = qh + (size_t)s * (NH * DH) + j;
#pragma unroll
    for (int h = 0; h < NH; h++) {
        float x1 = row[h * DH + j];
        float x2 = row[h * DH + j + 64];
        qo[h * DH]      = __float2half_rn(x1 * cs - x2 * sn);
        qo[h * DH + 64] = __float2half_rn(x1 * sn + x2 * cs);
    }
    const float* krow = row + HID;
    __half* ko = kh + (size_t)s * (NG * DH) + j;
#pragma unroll
    for (int g = 0; g < NG; g++) {
        float x1 = krow[g * DH + j];
        float x2 = krow[g * DH + j + 64];
        ko[g * DH]      = __float2half_rn(x1 * cs - x2 * sn);
        ko[g * DH + 64] = __float2half_rn(x1 * sn + x2 * cs);
    }
    const float* vrow = row + HID + 1024;
    __half* vo = vh + (size_t)s * (NG * DH) + j;
#pragma unroll
    for (int g = 0; g < NG; g++) {
        vo[g * DH]      = __float2half_rn(vrow[g * DH + j]);
        vo[g * DH + 64] = __float2half_rn(vrow[g * DH + j + 64]);
    }
}

// ---------------------------------------------------------------------------
// Tensorized flash attention (fp16 HMMA, causal, GQA) — unchanged (round 11).
// BM=64, 128 threads (4 warps), 2 CTAs/SM, heavy-first qb mapping.
// ---------------------------------------------------------------------------
#define AP 272
#define ATTN_KV (64 * AP)
#define ATTN_KVBUF (128 * AP)
#define ATTN_SMEM (ATTN_KV + 2 * ATTN_KVBUF)   // 87040 B

__global__ __launch_bounds__(128, 2)
void attn_mma(const __half* __restrict__ qh, const __half* __restrict__ kh,
              const __half* __restrict__ vh, __half* __restrict__ ch) {
    extern __shared__ char smc[];
    const uint32_t sb = smem_u32(smc);
    const int tid = threadIdx.x, w = tid >> 5, lane = tid & 31;
    const int qb = (int)gridDim.x - 1 - (int)blockIdx.x;
    const int h = blockIdx.y, g = h >> 2;
    const int q0 = qb * 64;
    const int R = q0 + w * 16;

    for (int c = tid; c < 1024; c += 128) {
        int row = c >> 4, u = c & 15;
        size_t go = (size_t)(q0 + row) * (NH * DH) + h * DH + u * 8;
        CP_ASYNC16(sb + row * AP + u * 16, (const char*)(qh + go));
    }
    CP_COMMIT();

    const int ntiles = qb + 1;

    {
        uint32_t b0 = sb + ATTN_KV;
        for (int c = tid; c < 1024; c += 128) {
            int row = c >> 4, u = c & 15;
            size_t go = (size_t)row * (NG * DH) + g * DH + u * 8;
            uint32_t s = b0 + row * AP + u * 16;
            CP_ASYNC16(s,           (const char*)(kh + go));
            CP_ASYNC16(s + 64 * AP, (const char*)(vh + go));
        }
        CP_COMMIT();
    }

    float o[16][4];
#pragma unroll
    for (int t = 0; t < 16; t++)
#pragma unroll
        for (int j = 0; j < 4; j++) o[t][j] = 0.f;
    float m_run[2] = {-1e30f, -1e30f};
    float l_run[2] = {0.f, 0.f};

    const float SC = 0.12751879523171918f;

    for (int kt = 0; kt < ntiles; kt++) {
        const int k0 = kt * 64;
        const int buf = kt & 1;
        if (kt + 1 < ntiles) {
            uint32_t b0 = sb + ATTN_KV + (uint32_t)(buf ^ 1) * ATTN_KVBUF;
            const int kn = (kt + 1) * 64;
            for (int c = tid; c < 1024; c += 128) {
                int row = c >> 4, u = c & 15;
                size_t go = (size_t)(kn + row) * (NG * DH) + g * DH + u * 8;
                uint32_t s = b0 + row * AP + u * 16;
                CP_ASYNC16(s,           (const char*)(kh + go));
                CP_ASYNC16(s + 64 * AP, (const char*)(vh + go));
            }
            CP_COMMIT();
            CP_WAIT1();
        } else {
            CP_WAIT0();
        }
        __syncthreads();

        {
            const uint32_t kb = sb + ATTN_KV + (uint32_t)buf * ATTN_KVBUF;

            float sS[8][4];
#pragma unroll
            for (int t = 0; t < 8; t++)
#pragma unroll
                for (int j = 0; j < 4; j++) sS[t][j] = 0.f;

            const uint32_t q_lane = (uint32_t)((w * 16 + (lane & 7) + ((lane >> 3) & 1) * 8) * AP);
            const uint32_t q_col  = (uint32_t)((lane >> 4) * 16);
#pragma unroll
            for (int kc8 = 0; kc8 < 8; kc8++) {
                uint32_t a0, a1, a2, a3;
                ldsm4(a0, a1, a2, a3, sb + q_lane + (uint32_t)(kc8 * 32) + q_col);
#pragma unroll
                for (int kg = 0; kg < 4; kg++) {
                    uint32_t ka = kb
                        + (uint32_t)((kg * 16 + ((lane >> 4) & 1) * 8 + (lane & 7)) * AP)
                        + (uint32_t)(kc8 * 32 + ((lane >> 3) & 1) * 16);
                    uint32_t b0, b1, b2, b3;
                    ldsm4(b0, b1, b2, b3, ka);
                    mma16816(sS[2 * kg],     a0, a1, a2, a3, b0, b1);
                    mma16816(sS[2 * kg + 1], a0, a1, a2, a3, b2, b3);
                }
            }

            const int r0 = R + (lane >> 2), r1 = r0 + 8;
            const bool diag = (k0 + 63 > R);
            float mt0 = -1e30f, mt1 = -1e30f;
#pragma unroll
            for (int t = 0; t < 8; t++) {
                int cb = k0 + t * 8 + 2 * (lane & 3);
                float s0 = sS[t][0] * SC, s1 = sS[t][1] * SC;
                float s2 = sS[t][2] * SC, s3 = sS[t][3] * SC;
                if (diag) {
                    if (cb     > r0) s0 = -1e30f;
                    if (cb + 1 > r0) s1 = -1e30f;
                    if (cb     > r1) s2 = -1e30f;
                    if (cb + 1 > r1) s3 = -1e30f;
                }
                sS[t][0] = s0; sS[t][1] = s1; sS[t][2] = s2; sS[t][3] = s3;
                mt0 = fmaxf(mt0, fmaxf(s0, s1));
                mt1 = fmaxf(mt1, fmaxf(s2, s3));
            }
            mt0 = fmaxf(mt0, __shfl_xor_sync(0xffffffffu, mt0, 1));
            mt0 = fmaxf(mt0, __shfl_xor_sync(0xffffffffu, mt0, 2));
            mt1 = fmaxf(mt1, __shfl_xor_sync(0xffffffffu, mt1, 1));
            mt1 = fmaxf(mt1, __shfl_xor_sync(0xffffffffu, mt1, 2));
            float mn0 = fmaxf(m_run[0], mt0), mn1 = fmaxf(m_run[1], mt1);
            float corr0 = ex2f(m_run[0] - mn0), corr1 = ex2f(m_run[1] - mn1);
            m_run[0] = mn0; m_run[1] = mn1;
            float ls0 = 0.f, ls1 = 0.f;
#pragma unroll
            for (int t = 0; t < 8; t++) {
                float p0 = ex2f(sS[t][0] - mn0), p1 = ex2f(sS[t][1] - mn0);
                float p2 = ex2f(sS[t][2] - mn1), p3 = ex2f(sS[t][3] - mn1);
                ls0 += p0 + p1; ls1 += p2 + p3;
                sS[t][0] = p0; sS[t][1] = p1; sS[t][2] = p2; sS[t][3] = p3;
            }
            ls0 += __shfl_xor_sync(0xffffffffu, ls0, 1);
            ls0 += __shfl_xor_sync(0xffffffffu, ls0, 2);
            ls1 += __shfl_xor_sync(0xffffffffu, ls1, 1);
            ls1 += __shfl_xor_sync(0xffffffffu, ls1, 2);
            l_run[0] = l_run[0] * corr0 + ls0;
            l_run[1] = l_run[1] * corr1 + ls1;
#pragma unroll
            for (int t = 0; t < 16; t++) {
                o[t][0] *= corr0; o[t][1] *= corr0;
                o[t][2] *= corr1; o[t][3] *= corr1;
            }

            uint32_t pa[4][4];
#pragma unroll
            for (int kc = 0; kc < 4; kc++) {
                pa[kc][0] = pack_half2(sS[2 * kc][0],     sS[2 * kc][1]);
                pa[kc][1] = pack_half2(sS[2 * kc][2],     sS[2 * kc][3]);
                pa[kc][2] = pack_half2(sS[2 * kc + 1][0], sS[2 * kc + 1][1]);
                pa[kc][3] = pack_half2(sS[2 * kc + 1][2], sS[2 * kc + 1][3]);
            }

#pragma unroll
            for (int kc = 0; kc < 4; kc++) {
#pragma unroll
                for (int dp = 0; dp < 8; dp++) {
                    uint32_t va = kb + 64 * AP
                        + (uint32_t)((kc * 16 + ((lane >> 3) & 1) * 8 + (lane & 7)) * AP)
                        + (uint32_t)(dp * 32 + ((lane >> 4) & 1) * 16);
                    uint32_t v0, v1, v2, v3;
                    ldsm4t(v0, v1, v2, v3, va);
                    mma16816(o[2 * dp],     pa[kc][0], pa[kc][1], pa[kc][2], pa[kc][3], v0, v1);
                    mma16816(o[2 * dp + 1], pa[kc][0], pa[kc][1], pa[kc][2], pa[kc][3], v2, v3);
                }
            }
        }
        __syncthreads();
    }

    float inv0 = 1.f / l_run[0], inv1 = 1.f / l_run[1];
    int r0 = R + (lane >> 2);
#pragma unroll
    for (int t = 0; t < 16; t++) {
        int col = t * 8 + 2 * (lane & 3);
        size_t o0 = (size_t)r0 * (NH * DH) + h * DH + col;
        size_t o1 = (size_t)(r0 + 8) * (NH * DH) + h * DH + col;
        *(uint32_t*)(ch + o0) = pack_half2(o[t][0] * inv0, o[t][1] * inv0);
        *(uint32_t*)(ch + o1) = pack_half2(o[t][2] * inv1, o[t][3] * inv1);
    }
}

// ---------------------------------------------------------------------------
// Launch
// ---------------------------------------------------------------------------
extern "C" void kernel_launch(void* const* d_in, const int* in_sizes, int n_in,
                              void* d_out, int out_size) {
    const float* X  = (const float*)d_in[0];
    const float* Wq = (const float*)d_in[1];
    const float* bq = (const float*)d_in[2];
    const float* Wk = (const float*)d_in[3];
    const float* bk = (const float*)d_in[4];
    const float* Wv = (const float*)d_in[5];
    const float* bv = (const float*)d_in[6];
    const float* Wo = (const float*)d_in[7];
    const float* bo = (const float*)d_in[8];
    float* out = (float*)d_out;

    void* p;
    cudaGetSymbolAddress(&p, g_qkv);  float* qkv = (float*)p;
    cudaGetSymbolAddress(&p, g_bqkv); float* bqkv = (float*)p;
    cudaGetSymbolAddress(&p, g_xh);   __half* xh = (__half*)p;
    cudaGetSymbolAddress(&p, g_ch);   __half* chp = (__half*)p;
    cudaGetSymbolAddress(&p, g_qh);   __half* qhp = (__half*)p;
    cudaGetSymbolAddress(&p, g_kh);   __half* khp = (__half*)p;
    cudaGetSymbolAddress(&p, g_vh);   __half* vhp = (__half*)p;
    cudaGetSymbolAddress(&p, g_wqkv); __half* wqkv = (__half*)p;
    cudaGetSymbolAddress(&p, g_wo);   __half* wo = (__half*)p;

    cudaFuncSetAttribute(mma_gemm, cudaFuncAttributeMaxDynamicSharedMemorySize,
                         GEMM_SMEM_BYTES);
    cudaFuncSetAttribute(attn_mma, cudaFuncAttributeMaxDynamicSharedMemorySize,
                         ATTN_SMEM);

    // 0: bias concat   1: ALL weights fp16 (native layout)   2: X fp16
    bias_concat<<<(NQKV + 255) / 256, 256>>>(bq, bk, bv, bqkv);
    wcvt<<<(WTOT4 + 255) / 256, 256>>>((const float4*)Wq, (const float4*)Wk,
                                       (const float4*)Wv, (const float4*)Wo,
                                       (__half2*)wqkv, (__half2*)wo);
    {
        int n4 = S_LEN * HID / 4;
        cvt_half<<<(n4 + 255) / 256, 256>>>((const float4*)X, (__half2*)xh, n4);
    }

    // 3: fused QKV projection (B native [K,6144])
    mma_gemm<<<dim3(NQKV / 128, S_LEN / 128), 256, GEMM_SMEM_BYTES>>>(
        xh, wqkv, bqkv, qkv, S_LEN, NQKV, HID);

    // 4: RoPE + fp16 convert for q, k, v
    rope_cvt<<<(S_LEN * 64 + 255) / 256, 256>>>(qkv, qhp, khp, vhp);

    // 5: attention
    attn_mma<<<dim3(S_LEN / 64, NH), 128, ATTN_SMEM>>>(qhp, khp, vhp, chp);

    // 6: output projection (B native [K,4096])
    mma_gemm<<<dim3(HID / 128, S_LEN / 128), 256, GEMM_SMEM_BYTES>>>(
        chp, wo, bo, out, S_LEN, HID, NH * DH);
}

// round 13
// speedup vs baseline: 10.9349x; 1.0133x over previous
#include <cuda.h>
#include <cuda_runtime.h>
#include <cuda_fp16.h>
#include <math.h>

// ---------------------------------------------------------------------------
// Problem constants
// ---------------------------------------------------------------------------
#define S_LEN 2048
#define HID   4096
#define NH    32
#define NG    8
#define DH    128
#define NQKV  6144   // HID + 2*NG*DH

// ---------------------------------------------------------------------------
// Device-global scratch (allocation-free rule)
// ---------------------------------------------------------------------------
__device__ __align__(16) float g_qkv[S_LEN * NQKV];     // fused QKV output (fp32)
__device__ __align__(16) float g_bqkv[NQKV];            // concat bias

__device__ __align__(16) __half g_xh[S_LEN * HID];
__device__ __align__(16) __half g_ch[S_LEN * HID];      // ctx (fp16, from attention)
__device__ __align__(16) __half g_qh[S_LEN * NH * DH];
__device__ __align__(16) __half g_kh[S_LEN * NG * DH];
__device__ __align__(16) __half g_vh[S_LEN * NG * DH];
__device__ __align__(16) __half g_wqkv[HID * NQKV];     // [Wq|Wk|Wv] [K=4096, N=6144] fp16
__device__ __align__(16) __half g_wo[HID * HID];        // Wo [K,N] fp16 (native layout)

// ---------------------------------------------------------------------------
// PTX helpers (sm_80-baseline: ldmatrix / mma.sync / cp.async)
// ---------------------------------------------------------------------------
__device__ __forceinline__ uint32_t smem_u32(const void* p) {
    uint32_t a;
    asm("{ .reg .u64 t; cvta.to.shared.u64 t, %1; cvt.u32.u64 %0, t; }"
        : "=r"(a) : "l"(p));
    return a;
}

__device__ __forceinline__ void ldsm4(uint32_t& r0, uint32_t& r1, uint32_t& r2,
                                      uint32_t& r3, uint32_t addr) {
    asm volatile("ldmatrix.sync.aligned.m8n8.x4.shared.b16 {%0,%1,%2,%3}, [%4];"
                 : "=r"(r0), "=r"(r1), "=r"(r2), "=r"(r3) : "r"(addr));
}

__device__ __forceinline__ void ldsm4t(uint32_t& r0, uint32_t& r1, uint32_t& r2,
                                       uint32_t& r3, uint32_t addr) {
    asm volatile("ldmatrix.sync.aligned.m8n8.x4.trans.shared.b16 {%0,%1,%2,%3}, [%4];"
                 : "=r"(r0), "=r"(r1), "=r"(r2), "=r"(r3) : "r"(addr));
}

__device__ __forceinline__ void mma16816(float* d, uint32_t a0, uint32_t a1,
                                         uint32_t a2, uint32_t a3,
                                         uint32_t b0, uint32_t b1) {
    asm volatile(
        "mma.sync.aligned.m16n8k16.row.col.f32.f16.f16.f32 "
        "{%0,%1,%2,%3}, {%4,%5,%6,%7}, {%8,%9}, {%0,%1,%2,%3};"
        : "+f"(d[0]), "+f"(d[1]), "+f"(d[2]), "+f"(d[3])
        : "r"(a0), "r"(a1), "r"(a2), "r"(a3), "r"(b0), "r"(b1));
}

__device__ __forceinline__ float ex2f(float x) {
    float r;
    asm("ex2.approx.ftz.f32 %0, %1;" : "=f"(r) : "f"(x));
    return r;
}

__device__ __forceinline__ uint32_t pack_half2(float a, float b) {
    __half2 h = __floats2half2_rn(a, b);
    return *(uint32_t*)&h;
}

#define CP_ASYNC16(smem_addr, gptr) \
    asm volatile("cp.async.cg.shared.global [%0], [%1], 16;" \
                 :: "r"(smem_addr), "l"(gptr))
#define CP_COMMIT() asm volatile("cp.async.commit_group;" ::: "memory")
#define CP_WAIT0()  asm volatile("cp.async.wait_group 0;" ::: "memory")
#define CP_WAIT1()  asm volatile("cp.async.wait_group 1;" ::: "memory")

// ---------------------------------------------------------------------------
// fp32 -> fp16, same layout. n4 = n/4 float4s.
// ---------------------------------------------------------------------------
__global__ void cvt_half(const float4* __restrict__ src, __half2* __restrict__ dst, int n4) {
    int i = blockIdx.x * blockDim.x + threadIdx.x;
    if (i >= n4) return;
    float4 v = src[i];
    dst[2 * i]     = __floats2half2_rn(v.x, v.y);
    dst[2 * i + 1] = __floats2half2_rn(v.z, v.w);
}

// ---------------------------------------------------------------------------
// Merged weight convert (NO transpose): Wq/Wk/Wv -> fused [K,6144] fp16,
// Wo -> [K,N] fp16. One fully-coalesced pass over all weights.
// ---------------------------------------------------------------------------
#define Q4 (HID * HID / 4)
#define K4 (HID * 1024 / 4)
#define WTOT4 (2 * Q4 + 2 * K4)

__global__ void wcvt(const float4* __restrict__ Wq, const float4* __restrict__ Wk,
                     const float4* __restrict__ Wv, const float4* __restrict__ Wo,
                     __half2* __restrict__ fused, __half2* __restrict__ wo) {
    size_t i = (size_t)blockIdx.x * blockDim.x + threadIdx.x;
    if (i >= WTOT4) return;
    float4 v;
    __half2* out;
    size_t d;
    if (i < Q4) {
        size_t j = i * 4;
        v = Wq[i];
        d = (j >> 12) * (size_t)NQKV + (j & 4095);
        out = fused;
    } else if (i < Q4 + K4) {
        size_t j = (i - Q4) * 4;
        v = Wk[i - Q4];
        d = (j >> 10) * (size_t)NQKV + 4096 + (j & 1023);
        out = fused;
    } else if (i < Q4 + 2 * K4) {
        size_t j = (i - Q4 - K4) * 4;
        v = Wv[i - Q4 - K4];
        d = (j >> 10) * (size_t)NQKV + 5120 + (j & 1023);
        out = fused;
    } else {
        size_t ii = i - Q4 - 2 * K4;
        v = Wo[ii];
        d = ii * 4;
        out = wo;
    }
    out[d >> 1]       = __floats2half2_rn(v.x, v.y);
    out[(d >> 1) + 1] = __floats2half2_rn(v.z, v.w);
}

// ---------------------------------------------------------------------------
// Concat biases [bq | bk | bv] -> g_bqkv[6144]
// ---------------------------------------------------------------------------
__global__ void bias_concat(const float* __restrict__ bq, const float* __restrict__ bk,
                            const float* __restrict__ bv, float* __restrict__ b) {
    int i = blockIdx.x * blockDim.x + threadIdx.x;
    if (i >= NQKV) return;
    if (i < HID)             b[i] = bq[i];
    else if (i < HID + 1024) b[i] = bk[i - HID];
    else                     b[i] = bv[i - HID - 1024];
}

// ---------------------------------------------------------------------------
// HMMA fp16 GEMM: C[M,N] = A[M,K] @ B[K,N] + bias
// A: [M,K] K-contig.  B: [K,N] N-contig (native, ldmatrix.trans fragments).
// CTA tile 128x128, 8 warps (2x4), warp tile 64x32, BK=64.
// NEW: 3-stage cp.async ring, ONE __syncthreads per K-chunk (was two).
// Per chunk c: wait(c done) -> sync -> issue c+2 (into buffer read at c-1,
// protected by the sync) -> compute c. Accumulation order unchanged.
// smem: 3 stages x 35840 B = 107520 B -> 2 CTAs/SM (215 KB < 228 KB).
// ---------------------------------------------------------------------------
#define AROWB 144
#define BROWB 272
#define A_BYTES (128 * AROWB)
#define STAGE_BYTES (A_BYTES + 64 * BROWB)
#define GEMM_SMEM_BYTES (3 * STAGE_BYTES)   // 107520

__global__ __launch_bounds__(256, 2)
void mma_gemm(const __half* __restrict__ A, const __half* __restrict__ B,
              const float* __restrict__ bias, float* __restrict__ C,
              int M, int N, int K) {
    extern __shared__ char smc[];
    const uint32_t sb = smem_u32(smc);
    const int tid = threadIdx.x;
    const int w = tid >> 5, lane = tid & 31;
    const int wm = w >> 2;
    const int wn = w & 3;
    const int m0 = blockIdx.y * 128;
    const int n0 = blockIdx.x * 128;

    size_t ga[4], gb[4];
    uint32_t soA[4], soB[4];
#pragma unroll
    for (int t = 0; t < 4; t++) {
        int i = tid + t * 256;
        int arow = i >> 3, au = i & 7;
        ga[t]  = (size_t)(m0 + arow) * K + au * 8;
        soA[t] = (uint32_t)(arow * AROWB + au * 16);
        int brow = i >> 4, bu = i & 15;
        gb[t]  = (size_t)brow * N + n0 + bu * 8;
        soB[t] = (uint32_t)(A_BYTES + brow * BROWB + bu * 16);
    }

    const int NC = K >> 6;

    // Prologue: stage chunks 0 and 1
#pragma unroll
    for (int s = 0; s < 2; s++) {
        const size_t kcA = (size_t)s << 6;
        const size_t kcB = (size_t)s * 64 * N;
        const uint32_t dst = sb + (uint32_t)s * STAGE_BYTES;
#pragma unroll
        for (int t = 0; t < 4; t++) {
            CP_ASYNC16(dst + soA[t], (const char*)(A + ga[t] + kcA));
            CP_ASYNC16(dst + soB[t], (const char*)(B + gb[t] + kcB));
        }
        CP_COMMIT();
    }

    float acc[4][4][4];
#pragma unroll
    for (int mi = 0; mi < 4; mi++)
#pragma unroll
        for (int ni = 0; ni < 4; ni++)
#pragma unroll
            for (int j = 0; j < 4; j++) acc[mi][ni][j] = 0.f;

    const int lr = lane & 15, lc = lane >> 4;
    const uint32_t a_lane_off = (uint32_t)((wm * 64 + lr) * AROWB + lc * 16);
    const uint32_t b_lane_row = (uint32_t)((((lane >> 3) & 1) * 8 + (lane & 7)) * BROWB);
    const uint32_t b_lane_col = (uint32_t)(wn * 64 + ((lane >> 4) & 1) * 16);

    int bufc = 0;   // buffer index of chunk c (mod 3)
    for (int c = 0; c < NC; c++) {
        if (c + 1 < NC) { CP_WAIT1(); } else { CP_WAIT0(); }
        __syncthreads();

        // Issue chunk c+2 into the buffer read at chunk c-1 (just fenced).
        if (c + 2 < NC) {
            int bufn = bufc + 2; if (bufn >= 3) bufn -= 3;
            const size_t kcA = (size_t)(c + 2) << 6;
            const size_t kcB = (size_t)(c + 2) * 64 * N;
            const uint32_t dst = sb + (uint32_t)bufn * STAGE_BYTES;
#pragma unroll
            for (int t = 0; t < 4; t++) {
                CP_ASYNC16(dst + soA[t], (const char*)(A + ga[t] + kcA));
                CP_ASYNC16(dst + soB[t], (const char*)(B + gb[t] + kcB));
            }
            CP_COMMIT();
        }

        const uint32_t base = sb + (uint32_t)bufc * STAGE_BYTES;
#pragma unroll
        for (int ks = 0; ks < 4; ks++) {
            uint32_t bfr[4][2];
#pragma unroll
            for (int ni16 = 0; ni16 < 2; ni16++) {
                uint32_t v0, v1, v2, v3;
                ldsm4t(v0, v1, v2, v3,
                       base + A_BYTES + (uint32_t)(ks * 16) * BROWB + b_lane_row
                            + b_lane_col + (uint32_t)(ni16 * 32));
                bfr[ni16 * 2][0]     = v0; bfr[ni16 * 2][1]     = v1;
                bfr[ni16 * 2 + 1][0] = v2; bfr[ni16 * 2 + 1][1] = v3;
            }
            const uint32_t koff = (uint32_t)(ks * 32);
#pragma unroll
            for (int mi = 0; mi < 4; mi++) {
                uint32_t a0, a1, a2, a3;
                ldsm4(a0, a1, a2, a3,
                      base + a_lane_off + (uint32_t)(mi * 16 * AROWB) + koff);
#pragma unroll
                for (int ni = 0; ni < 4; ni++)
                    mma16816(acc[mi][ni], a0, a1, a2, a3, bfr[ni][0], bfr[ni][1]);
            }
        }
        bufc++; if (bufc >= 3) bufc = 0;
    }

#pragma unroll
    for (int mi = 0; mi < 4; mi++) {
#pragma unroll
        for (int ni = 0; ni < 4; ni++) {
            int m = m0 + wm * 64 + mi * 16 + (lane >> 2);
            int n = n0 + wn * 32 + ni * 8 + 2 * (lane & 3);
            float2 bv = *(const float2*)&bias[n];
            float2 o0 = make_float2(acc[mi][ni][0] + bv.x, acc[mi][ni][1] + bv.y);
            float2 o1 = make_float2(acc[mi][ni][2] + bv.x, acc[mi][ni][3] + bv.y);
            *(float2*)&C[(size_t)m * N + n]       = o0;
            *(float2*)&C[(size_t)(m + 8) * N + n] = o1;
        }
    }
}

// ---------------------------------------------------------------------------
// RoPE + fp16 convert, fused for q, k AND v (reads fused qkv, stride 6144).
// ---------------------------------------------------------------------------
__global__ void rope_cvt(const float* __restrict__ qkv,
                         __half* __restrict__ qh, __half* __restrict__ kh,
                         __half* __restrict__ vh) {
    int idx = blockIdx.x * blockDim.x + threadIdx.x;
    if (idx >= S_LEN * 64) return;
    int j = idx & 63;
    int s = idx >> 6;
    float inv = (float)exp(-(double)j * (9.210340371976184 / 64.0));
    float ang = (float)s * inv;
    float sn, cs;
    sincosf(ang, &sn, &cs);
    const float* row = qkv + (size_t)s * NQKV;

    __half* qo = qh + (size_t)s * (NH * DH) + j;
#pragma unroll
    for (int h = 0; h < NH; h++) {
        float x1 = row[h * DH + j];
        float x2 = row[h * DH + j + 64];
        qo[h * DH]      = __float2half_rn(x1 * cs - x2 * sn);
        qo[h * DH + 64] = __float2half_rn(x1 * sn + x2 * cs);
    }
    const float* krow = row + HID;
    __half* ko = kh + (size_t)s * (NG * DH) + j;
#pragma unroll
    for (int g = 0; g < NG; g++) {
        float x1 = krow[g * DH + j];
        float x2 = krow[g * DH + j + 64];
        ko[g * DH]      = __float2half_rn(x1 * cs - x2 * sn);
        ko[g * DH + 64] = __float2half_rn(x1 * sn + x2 * cs);
    }
    const float* vrow = row + HID + 1024;
    __half* vo = vh + (size_t)s * (NG * DH) + j;
#pragma unroll
    for (int g = 0; g < NG; g++) {
        vo[g * DH]      = __float2half_rn(vrow[g * DH + j]);
        vo[g * DH + 64] = __float2half_rn(vrow[g * DH + j + 64]);
    }
}

// ---------------------------------------------------------------------------
// Tensorized flash attention (fp16 HMMA, causal, GQA) — unchanged (round 11).
// BM=64, 128 threads (4 warps), 2 CTAs/SM, heavy-first qb mapping.
// ---------------------------------------------------------------------------
#define AP 272
#define ATTN_KV (64 * AP)
#define ATTN_KVBUF (128 * AP)
#define ATTN_SMEM (ATTN_KV + 2 * ATTN_KVBUF)   // 87040 B

__global__ __launch_bounds__(128, 2)
void attn_mma(const __half* __restrict__ qh, const __half* __restrict__ kh,
              const __half* __restrict__ vh, __half* __restrict__ ch) {
    extern __shared__ char smc[];
    const uint32_t sb = smem_u32(smc);
    const int tid = threadIdx.x, w = tid >> 5, lane = tid & 31;
    const int qb = (int)gridDim.x - 1 - (int)blockIdx.x;
    const int h = blockIdx.y, g = h >> 2;
    const int q0 = qb * 64;
    const int R = q0 + w * 16;

    for (int c = tid; c < 1024; c += 128) {
        int row = c >> 4, u = c & 15;
        size_t go = (size_t)(q0 + row) * (NH * DH) + h * DH + u * 8;
        CP_ASYNC16(sb + row * AP + u * 16, (const char*)(qh + go));
    }
    CP_COMMIT();

    const int ntiles = qb + 1;

    {
        uint32_t b0 = sb + ATTN_KV;
        for (int c = tid; c < 1024; c += 128) {
            int row = c >> 4, u = c & 15;
            size_t go = (size_t)row * (NG * DH) + g * DH + u * 8;
            uint32_t s = b0 + row * AP + u * 16;
            CP_ASYNC16(s,           (const char*)(kh + go));
            CP_ASYNC16(s + 64 * AP, (const char*)(vh + go));
        }
        CP_COMMIT();
    }

    float o[16][4];
#pragma unroll
    for (int t = 0; t < 16; t++)
#pragma unroll
        for (int j = 0; j < 4; j++) o[t][j] = 0.f;
    float m_run[2] = {-1e30f, -1e30f};
    float l_run[2] = {0.f, 0.f};

    const float SC = 0.12751879523171918f;

    for (int kt = 0; kt < ntiles; kt++) {
        const int k0 = kt * 64;
        const int buf = kt & 1;
        if (kt + 1 < ntiles) {
            uint32_t b0 = sb + ATTN_KV + (uint32_t)(buf ^ 1) * ATTN_KVBUF;
            const int kn = (kt + 1) * 64;
            for (int c = tid; c < 1024; c += 128) {
                int row = c >> 4, u = c & 15;
                size_t go = (size_t)(kn + row) * (NG * DH) + g * DH + u * 8;
                uint32_t s = b0 + row * AP + u * 16;
                CP_ASYNC16(s,           (const char*)(kh + go));
                CP_ASYNC16(s + 64 * AP, (const char*)(vh + go));
            }
            CP_COMMIT();
            CP_WAIT1();
        } else {
            CP_WAIT0();
        }
        __syncthreads();

        {
            const uint32_t kb = sb + ATTN_KV + (uint32_t)buf * ATTN_KVBUF;

            float sS[8][4];
#pragma unroll
            for (int t = 0; t < 8; t++)
#pragma unroll
                for (int j = 0; j < 4; j++) sS[t][j] = 0.f;

            const uint32_t q_lane = (uint32_t)((w * 16 + (lane & 7) + ((lane >> 3) & 1) * 8) * AP);
            const uint32_t q_col  = (uint32_t)((lane >> 4) * 16);
#pragma unroll
            for (int kc8 = 0; kc8 < 8; kc8++) {
                uint32_t a0, a1, a2, a3;
                ldsm4(a0, a1, a2, a3, sb + q_lane + (uint32_t)(kc8 * 32) + q_col);
#pragma unroll
                for (int kg = 0; kg < 4; kg++) {
                    uint32_t ka = kb
                        + (uint32_t)((kg * 16 + ((lane >> 4) & 1) * 8 + (lane & 7)) * AP)
                        + (uint32_t)(kc8 * 32 + ((lane >> 3) & 1) * 16);
                    uint32_t b0, b1, b2, b3;
                    ldsm4(b0, b1, b2, b3, ka);
                    mma16816(sS[2 * kg],     a0, a1, a2, a3, b0, b1);
                    mma16816(sS[2 * kg + 1], a0, a1, a2, a3, b2, b3);
                }
            }

            const int r0 = R + (lane >> 2), r1 = r0 + 8;
            const bool diag = (k0 + 63 > R);
            float mt0 = -1e30f, mt1 = -1e30f;
#pragma unroll
            for (int t = 0; t < 8; t++) {
                int cb = k0 + t * 8 + 2 * (lane & 3);
                float s0 = sS[t][0] * SC, s1 = sS[t][1] * SC;
                float s2 = sS[t][2] * SC, s3 = sS[t][3] * SC;
                if (diag) {
                    if (cb     > r0) s0 = -1e30f;
                    if (cb + 1 > r0) s1 = -1e30f;
                    if (cb     > r1) s2 = -1e30f;
                    if (cb + 1 > r1) s3 = -1e30f;
                }
                sS[t][0] = s0; sS[t][1] = s1; sS[t][2] = s2; sS[t][3] = s3;
                mt0 = fmaxf(mt0, fmaxf(s0, s1));
                mt1 = fmaxf(mt1, fmaxf(s2, s3));
            }
            mt0 = fmaxf(mt0, __shfl_xor_sync(0xffffffffu, mt0, 1));
            mt0 = fmaxf(mt0, __shfl_xor_sync(0xffffffffu, mt0, 2));
            mt1 = fmaxf(mt1, __shfl_xor_sync(0xffffffffu, mt1, 1));
            mt1 = fmaxf(mt1, __shfl_xor_sync(0xffffffffu, mt1, 2));
            float mn0 = fmaxf(m_run[0], mt0), mn1 = fmaxf(m_run[1], mt1);
            float corr0 = ex2f(m_run[0] - mn0), corr1 = ex2f(m_run[1] - mn1);
            m_run[0] = mn0; m_run[1] = mn1;
            float ls0 = 0.f, ls1 = 0.f;
#pragma unroll
            for (int t = 0; t < 8; t++) {
                float p0 = ex2f(sS[t][0] - mn0), p1 = ex2f(sS[t][1] - mn0);
                float p2 = ex2f(sS[t][2] - mn1), p3 = ex2f(sS[t][3] - mn1);
                ls0 += p0 + p1; ls1 += p2 + p3;
                sS[t][0] = p0; sS[t][1] = p1; sS[t][2] = p2; sS[t][3] = p3;
            }
            ls0 += __shfl_xor_sync(0xffffffffu, ls0, 1);
            ls0 += __shfl_xor_sync(0xffffffffu, ls0, 2);
            ls1 += __shfl_xor_sync(0xffffffffu, ls1, 1);
            ls1 += __shfl_xor_sync(0xffffffffu, ls1, 2);
            l_run[0] = l_run[0] * corr0 + ls0;
            l_run[1] = l_run[1] * corr1 + ls1;
#pragma unroll
            for (int t = 0; t < 16; t++) {
                o[t][0] *= corr0; o[t][1] *= corr0;
                o[t][2] *= corr1; o[t][3] *= corr1;
            }

            uint32_t pa[4][4];
#pragma unroll
            for (int kc = 0; kc < 4; kc++) {
                pa[kc][0] = pack_half2(sS[2 * kc][0],     sS[2 * kc][1]);
                pa[kc][1] = pack_half2(sS[2 * kc][2],     sS[2 * kc][3]);
                pa[kc][2] = pack_half2(sS[2 * kc + 1][0], sS[2 * kc + 1][1]);
                pa[kc][3] = pack_half2(sS[2 * kc + 1][2], sS[2 * kc + 1][3]);
            }

#pragma unroll
            for (int kc = 0; kc < 4; kc++) {
#pragma unroll
                for (int dp = 0; dp < 8; dp++) {
                    uint32_t va = kb + 64 * AP
                        + (uint32_t)((kc * 16 + ((lane >> 3) & 1) * 8 + (lane & 7)) * AP)
                        + (uint32_t)(dp * 32 + ((lane >> 4) & 1) * 16);
                    uint32_t v0, v1, v2, v3;
                    ldsm4t(v0, v1, v2, v3, va);
                    mma16816(o[2 * dp],     pa[kc][0], pa[kc][1], pa[kc][2], pa[kc][3], v0, v1);
                    mma16816(o[2 * dp + 1], pa[kc][0], pa[kc][1], pa[kc][2], pa[kc][3], v2, v3);
                }
            }
        }
        __syncthreads();
    }

    float inv0 = 1.f / l_run[0], inv1 = 1.f / l_run[1];
    int r0 = R + (lane >> 2);
#pragma unroll
    for (int t = 0; t < 16; t++) {
        int col = t * 8 + 2 * (lane & 3);
        size_t o0 = (size_t)r0 * (NH * DH) + h * DH + col;
        size_t o1 = (size_t)(r0 + 8) * (NH * DH) + h * DH + col;
        *(uint32_t*)(ch + o0) = pack_half2(o[t][0] * inv0, o[t][1] * inv0);
        *(uint32_t*)(ch + o1) = pack_half2(o[t][2] * inv1, o[t][3] * inv1);
    }
}

// ---------------------------------------------------------------------------
// Launch
// ---------------------------------------------------------------------------
extern "C" void kernel_launch(void* const* d_in, const int* in_sizes, int n_in,
                              void* d_out, int out_size) {
    const float* X  = (const float*)d_in[0];
    const float* Wq = (const float*)d_in[1];
    const float* bq = (const float*)d_in[2];
    const float* Wk = (const float*)d_in[3];
    const float* bk = (const float*)d_in[4];
    const float* Wv = (const float*)d_in[5];
    const float* bv = (const float*)d_in[6];
    const float* Wo = (const float*)d_in[7];
    const float* bo = (const float*)d_in[8];
    float* out = (float*)d_out;

    void* p;
    cudaGetSymbolAddress(&p, g_qkv);  float* qkv = (float*)p;
    cudaGetSymbolAddress(&p, g_bqkv); float* bqkv = (float*)p;
    cudaGetSymbolAddress(&p, g_xh);   __half* xh = (__half*)p;
    cudaGetSymbolAddress(&p, g_ch);   __half* chp = (__half*)p;
    cudaGetSymbolAddress(&p, g_qh);   __half* qhp = (__half*)p;
    cudaGetSymbolAddress(&p, g_kh);   __half* khp = (__half*)p;
    cudaGetSymbolAddress(&p, g_vh);   __half* vhp = (__half*)p;
    cudaGetSymbolAddress(&p, g_wqkv); __half* wqkv = (__half*)p;
    cudaGetSymbolAddress(&p, g_wo);   __half* wo = (__half*)p;

    cudaFuncSetAttribute(mma_gemm, cudaFuncAttributeMaxDynamicSharedMemorySize,
                         GEMM_SMEM_BYTES);
    cudaFuncSetAttribute(attn_mma, cudaFuncAttributeMaxDynamicSharedMemorySize,
                         ATTN_SMEM);

    // 0: bias concat   1: ALL weights fp16 (native layout)   2: X fp16
    bias_concat<<<(NQKV + 255) / 256, 256>>>(bq, bk, bv, bqkv);
    wcvt<<<(WTOT4 + 255) / 256, 256>>>((const float4*)Wq, (const float4*)Wk,
                                       (const float4*)Wv, (const float4*)Wo,
                                       (__half2*)wqkv, (__half2*)wo);
    {
        int n4 = S_LEN * HID / 4;
        cvt_half<<<(n4 + 255) / 256, 256>>>((const float4*)X, (__half2*)xh, n4);
    }

    // 3: fused QKV projection (B native [K,6144])
    mma_gemm<<<dim3(NQKV / 128, S_LEN / 128), 256, GEMM_SMEM_BYTES>>>(
        xh, wqkv, bqkv, qkv, S_LEN, NQKV, HID);

    // 4: RoPE + fp16 convert for q, k, v
    rope_cvt<<<(S_LEN * 64 + 255) / 256, 256>>>(qkv, qhp, khp, vhp);

    // 5: attention
    attn_mma<<<dim3(S_LEN / 64, NH), 128, ATTN_SMEM>>>(qhp, khp, vhp, chp);

    // 6: output projection (B native [K,4096])
    mma_gemm<<<dim3(HID / 128, S_LEN / 128), 256, GEMM_SMEM_BYTES>>>(
        chp, wo, bo, out, S_LEN, HID, NH * DH);
}

// round 15
// speedup vs baseline: 11.0345x; 1.0091x over previous
#include <cuda.h>
#include <cuda_runtime.h>
#include <cuda_fp16.h>
#include <math.h>

// ---------------------------------------------------------------------------
// Problem constants
// ---------------------------------------------------------------------------
#define S_LEN 2048
#define HID   4096
#define NH    32
#define NG    8
#define DH    128
#define NQKV  6144   // HID + 2*NG*DH

// ---------------------------------------------------------------------------
// Device-global scratch (allocation-free rule)
// ---------------------------------------------------------------------------
__device__ __align__(16) float g_qkv[S_LEN * NQKV];     // fused QKV output (fp32)
__device__ __align__(16) float g_bqkv[NQKV];            // concat bias

__device__ __align__(16) __half g_xh[S_LEN * HID];
__device__ __align__(16) __half g_ch[S_LEN * HID];      // ctx (fp16, from attention)
__device__ __align__(16) __half g_qh[S_LEN * NH * DH];
__device__ __align__(16) __half g_kh[S_LEN * NG * DH];
__device__ __align__(16) __half g_vh[S_LEN * NG * DH];
__device__ __align__(16) __half g_wqkv[HID * NQKV];     // [Wq|Wk|Wv] [K=4096, N=6144] fp16
__device__ __align__(16) __half g_wo[HID * HID];        // Wo [K,N] fp16 (native layout)

// ---------------------------------------------------------------------------
// PTX helpers (sm_80-baseline: ldmatrix / mma.sync / cp.async)
// ---------------------------------------------------------------------------
__device__ __forceinline__ uint32_t smem_u32(const void* p) {
    uint32_t a;
    asm("{ .reg .u64 t; cvta.to.shared.u64 t, %1; cvt.u32.u64 %0, t; }"
        : "=r"(a) : "l"(p));
    return a;
}

__device__ __forceinline__ void ldsm4(uint32_t& r0, uint32_t& r1, uint32_t& r2,
                                      uint32_t& r3, uint32_t addr) {
    asm volatile("ldmatrix.sync.aligned.m8n8.x4.shared.b16 {%0,%1,%2,%3}, [%4];"
                 : "=r"(r0), "=r"(r1), "=r"(r2), "=r"(r3) : "r"(addr));
}

__device__ __forceinline__ void ldsm4t(uint32_t& r0, uint32_t& r1, uint32_t& r2,
                                       uint32_t& r3, uint32_t addr) {
    asm volatile("ldmatrix.sync.aligned.m8n8.x4.trans.shared.b16 {%0,%1,%2,%3}, [%4];"
                 : "=r"(r0), "=r"(r1), "=r"(r2), "=r"(r3) : "r"(addr));
}

__device__ __forceinline__ void mma16816(float* d, uint32_t a0, uint32_t a1,
                                         uint32_t a2, uint32_t a3,
                                         uint32_t b0, uint32_t b1) {
    asm volatile(
        "mma.sync.aligned.m16n8k16.row.col.f32.f16.f16.f32 "
        "{%0,%1,%2,%3}, {%4,%5,%6,%7}, {%8,%9}, {%0,%1,%2,%3};"
        : "+f"(d[0]), "+f"(d[1]), "+f"(d[2]), "+f"(d[3])
        : "r"(a0), "r"(a1), "r"(a2), "r"(a3), "r"(b0), "r"(b1));
}

__device__ __forceinline__ float ex2f(float x) {
    float r;
    asm("ex2.approx.ftz.f32 %0, %1;" : "=f"(r) : "f"(x));
    return r;
}

__device__ __forceinline__ uint32_t pack_half2(float a, float b) {
    __half2 h = __floats2half2_rn(a, b);
    return *(uint32_t*)&h;
}

#define CP_ASYNC16(smem_addr, gptr) \
    asm volatile("cp.async.cg.shared.global [%0], [%1], 16;" \
                 :: "r"(smem_addr), "l"(gptr))
#define CP_COMMIT() asm volatile("cp.async.commit_group;" ::: "memory")
#define CP_WAIT0()  asm volatile("cp.async.wait_group 0;" ::: "memory")
#define CP_WAIT1()  asm volatile("cp.async.wait_group 1;" ::: "memory")

// ---------------------------------------------------------------------------
// fp32 -> fp16, same layout. n4 = n/4 float4s.
// ---------------------------------------------------------------------------
__global__ void cvt_half(const float4* __restrict__ src, __half2* __restrict__ dst, int n4) {
    int i = blockIdx.x * blockDim.x + threadIdx.x;
    if (i >= n4) return;
    float4 v = src[i];
    dst[2 * i]     = __floats2half2_rn(v.x, v.y);
    dst[2 * i + 1] = __floats2half2_rn(v.z, v.w);
}

// ---------------------------------------------------------------------------
// Merged weight convert (NO transpose): Wq/Wk/Wv -> fused [K,6144] fp16,
// Wo -> [K,N] fp16. One fully-coalesced pass over all weights.
// ---------------------------------------------------------------------------
#define Q4 (HID * HID / 4)
#define K4 (HID * 1024 / 4)
#define WTOT4 (2 * Q4 + 2 * K4)

__global__ void wcvt(const float4* __restrict__ Wq, const float4* __restrict__ Wk,
                     const float4* __restrict__ Wv, const float4* __restrict__ Wo,
                     __half2* __restrict__ fused, __half2* __restrict__ wo) {
    size_t i = (size_t)blockIdx.x * blockDim.x + threadIdx.x;
    if (i >= WTOT4) return;
    float4 v;
    __half2* out;
    size_t d;
    if (i < Q4) {
        size_t j = i * 4;
        v = Wq[i];
        d = (j >> 12) * (size_t)NQKV + (j & 4095);
        out = fused;
    } else if (i < Q4 + K4) {
        size_t j = (i - Q4) * 4;
        v = Wk[i - Q4];
        d = (j >> 10) * (size_t)NQKV + 4096 + (j & 1023);
        out = fused;
    } else if (i < Q4 + 2 * K4) {
        size_t j = (i - Q4 - K4) * 4;
        v = Wv[i - Q4 - K4];
        d = (j >> 10) * (size_t)NQKV + 5120 + (j & 1023);
        out = fused;
    } else {
        size_t ii = i - Q4 - 2 * K4;
        v = Wo[ii];
        d = ii * 4;
        out = wo;
    }
    out[d >> 1]       = __floats2half2_rn(v.x, v.y);
    out[(d >> 1) + 1] = __floats2half2_rn(v.z, v.w);
}

// ---------------------------------------------------------------------------
// Concat biases [bq | bk | bv] -> g_bqkv[6144]
// ---------------------------------------------------------------------------
__global__ void bias_concat(const float* __restrict__ bq, const float* __restrict__ bk,
                            const float* __restrict__ bv, float* __restrict__ b) {
    int i = blockIdx.x * blockDim.x + threadIdx.x;
    if (i >= NQKV) return;
    if (i < HID)             b[i] = bq[i];
    else if (i < HID + 1024) b[i] = bk[i - HID];
    else                     b[i] = bv[i - HID - 1024];
}

// ---------------------------------------------------------------------------
// HMMA fp16 GEMM: C[M,N] = A[M,K] @ B[K,N] + bias
// A: [M,K] K-contig.  B: [K,N] N-contig (native, ldmatrix.trans fragments).
// CTA tile 128x128, 8 warps (2x4), warp tile 64x32, BK=64, 3-stage ring.
// NEW: explicit register double-buffering of fragments (CUTLASS mainloop):
// B-frags for ks+1 prefetched during ks's MMAs; A-frag for mi+1 / (ks+1,0)
// prefetched during mi's MMAs. MMA order per accumulator unchanged.
// ---------------------------------------------------------------------------
#define AROWB 144
#define BROWB 272
#define A_BYTES (128 * AROWB)
#define STAGE_BYTES (A_BYTES + 64 * BROWB)
#define GEMM_SMEM_BYTES (3 * STAGE_BYTES)   // 107520

__global__ __launch_bounds__(256, 2)
void mma_gemm(const __half* __restrict__ A, const __half* __restrict__ B,
              const float* __restrict__ bias, float* __restrict__ C,
              int M, int N, int K) {
    extern __shared__ char smc[];
    const uint32_t sb = smem_u32(smc);
    const int tid = threadIdx.x;
    const int w = tid >> 5, lane = tid & 31;
    const int wm = w >> 2;
    const int wn = w & 3;
    const int m0 = blockIdx.y * 128;
    const int n0 = blockIdx.x * 128;

    size_t ga[4], gb[4];
    uint32_t soA[4], soB[4];
#pragma unroll
    for (int t = 0; t < 4; t++) {
        int i = tid + t * 256;
        int arow = i >> 3, au = i & 7;
        ga[t]  = (size_t)(m0 + arow) * K + au * 8;
        soA[t] = (uint32_t)(arow * AROWB + au * 16);
        int brow = i >> 4, bu = i & 15;
        gb[t]  = (size_t)brow * N + n0 + bu * 8;
        soB[t] = (uint32_t)(A_BYTES + brow * BROWB + bu * 16);
    }

    const int NC = K >> 6;

    // Prologue: stage chunks 0 and 1
#pragma unroll
    for (int s = 0; s < 2; s++) {
        const size_t kcA = (size_t)s << 6;
        const size_t kcB = (size_t)s * 64 * N;
        const uint32_t dst = sb + (uint32_t)s * STAGE_BYTES;
#pragma unroll
        for (int t = 0; t < 4; t++) {
            CP_ASYNC16(dst + soA[t], (const char*)(A + ga[t] + kcA));
            CP_ASYNC16(dst + soB[t], (const char*)(B + gb[t] + kcB));
        }
        CP_COMMIT();
    }

    float acc[4][4][4];
#pragma unroll
    for (int mi = 0; mi < 4; mi++)
#pragma unroll
        for (int ni = 0; ni < 4; ni++)
#pragma unroll
            for (int j = 0; j < 4; j++) acc[mi][ni][j] = 0.f;

    const int lr = lane & 15, lc = lane >> 4;
    const uint32_t a_lane_off = (uint32_t)((wm * 64 + lr) * AROWB + lc * 16);
    const uint32_t b_lane_row = (uint32_t)((((lane >> 3) & 1) * 8 + (lane & 7)) * BROWB);
    const uint32_t b_lane_col = (uint32_t)(wn * 64 + ((lane >> 4) & 1) * 16);

    int bufc = 0;   // buffer index of chunk c (mod 3)
    for (int c = 0; c < NC; c++) {
        if (c + 1 < NC) { CP_WAIT1(); } else { CP_WAIT0(); }
        __syncthreads();

        // Issue chunk c+2 into the buffer read at chunk c-1 (just fenced).
        if (c + 2 < NC) {
            int bufn = bufc + 2; if (bufn >= 3) bufn -= 3;
            const size_t kcA = (size_t)(c + 2) << 6;
            const size_t kcB = (size_t)(c + 2) * 64 * N;
            const uint32_t dst = sb + (uint32_t)bufn * STAGE_BYTES;
#pragma unroll
            for (int t = 0; t < 4; t++) {
                CP_ASYNC16(dst + soA[t], (const char*)(A + ga[t] + kcA));
                CP_ASYNC16(dst + soB[t], (const char*)(B + gb[t] + kcB));
            }
            CP_COMMIT();
        }

        const uint32_t base  = sb + (uint32_t)bufc * STAGE_BYTES;
        const uint32_t abase = base + a_lane_off;
        const uint32_t bbase = base + A_BYTES + b_lane_row + b_lane_col;

        // Preload ks=0 B fragments and (ks=0, mi=0) A fragment
        uint32_t bcur[4][2], bnxt[4][2];
        uint32_t acur[4], anxt[4];
        {
            uint32_t v0, v1, v2, v3;
            ldsm4t(v0, v1, v2, v3, bbase);
            bcur[0][0] = v0; bcur[0][1] = v1; bcur[1][0] = v2; bcur[1][1] = v3;
            ldsm4t(v0, v1, v2, v3, bbase + 32);
            bcur[2][0] = v0; bcur[2][1] = v1; bcur[3][0] = v2; bcur[3][1] = v3;
        }
        ldsm4(acur[0], acur[1], acur[2], acur[3], abase);

#pragma unroll
        for (int ks = 0; ks < 4; ks++) {
            // Prefetch next ks's B fragments while this ks's MMAs run
            if (ks < 3) {
                const uint32_t nb = bbase + (uint32_t)((ks + 1) * 16) * BROWB;
                uint32_t v0, v1, v2, v3;
                ldsm4t(v0, v1, v2, v3, nb);
                bnxt[0][0] = v0; bnxt[0][1] = v1; bnxt[1][0] = v2; bnxt[1][1] = v3;
                ldsm4t(v0, v1, v2, v3, nb + 32);
                bnxt[2][0] = v0; bnxt[2][1] = v1; bnxt[3][0] = v2; bnxt[3][1] = v3;
            }
            const uint32_t koff = (uint32_t)(ks * 32);
#pragma unroll
            for (int mi = 0; mi < 4; mi++) {
                // Prefetch next A fragment (mi+1, or (ks+1, mi=0))
                if (mi < 3) {
                    ldsm4(anxt[0], anxt[1], anxt[2], anxt[3],
                          abase + (uint32_t)((mi + 1) * 16 * AROWB) + koff);
                } else if (ks < 3) {
                    ldsm4(anxt[0], anxt[1], anxt[2], anxt[3],
                          abase + (uint32_t)((ks + 1) * 32));
                }
#pragma unroll
                for (int ni = 0; ni < 4; ni++)
                    mma16816(acc[mi][ni], acur[0], acur[1], acur[2], acur[3],
                             bcur[ni][0], bcur[ni][1]);
                acur[0] = anxt[0]; acur[1] = anxt[1];
                acur[2] = anxt[2]; acur[3] = anxt[3];
            }
#pragma unroll
            for (int q = 0; q < 4; q++) {
                bcur[q][0] = bnxt[q][0]; bcur[q][1] = bnxt[q][1];
            }
        }
        bufc++; if (bufc >= 3) bufc = 0;
    }

#pragma unroll
    for (int mi = 0; mi < 4; mi++) {
#pragma unroll
        for (int ni = 0; ni < 4; ni++) {
            int m = m0 + wm * 64 + mi * 16 + (lane >> 2);
            int n = n0 + wn * 32 + ni * 8 + 2 * (lane & 3);
            float2 bv = *(const float2*)&bias[n];
            float2 o0 = make_float2(acc[mi][ni][0] + bv.x, acc[mi][ni][1] + bv.y);
            float2 o1 = make_float2(acc[mi][ni][2] + bv.x, acc[mi][ni][3] + bv.y);
            *(float2*)&C[(size_t)m * N + n]       = o0;
            *(float2*)&C[(size_t)(m + 8) * N + n] = o1;
        }
    }
}

// ---------------------------------------------------------------------------
// RoPE + fp16 convert, fused for q, k AND v (reads fused qkv, stride 6144).
// ---------------------------------------------------------------------------
__global__ void rope_cvt(const float* __restrict__ qkv,
                         __half* __restrict__ qh, __half* __restrict__ kh,
                         __half* __restrict__ vh) {
    int idx = blockIdx.x * blockDim.x + threadIdx.x;
    if (idx >= S_LEN * 64) return;
    int j = idx & 63;
    int s = idx >> 6;
    float inv = (float)exp(-(double)j * (9.210340371976184 / 64.0));
    float ang = (float)s * inv;
    float sn, cs;
    sincosf(ang, &sn, &cs);
    const float* row = qkv + (size_t)s * NQKV;

    __half* qo = qh + (size_t)s * (NH * DH) + j;
#pragma unroll
    for (int h = 0; h < NH; h++) {
        float x1 = row[h * DH + j];
        float x2 = row[h * DH + j + 64];
        qo[h * DH]      = __float2half_rn(x1 * cs - x2 * sn);
        qo[h * DH + 64] = __float2half_rn(x1 * sn + x2 * cs);
    }
    const float* krow = row + HID;
    __half* ko = kh + (size_t)s * (NG * DH) + j;
#pragma unroll
    for (int g = 0; g < NG; g++) {
        float x1 = krow[g * DH + j];
        float x2 = krow[g * DH + j + 64];
        ko[g * DH]      = __float2half_rn(x1 * cs - x2 * sn);
        ko[g * DH + 64] = __float2half_rn(x1 * sn + x2 * cs);
    }
    const float* vrow = row + HID + 1024;
    __half* vo = vh + (size_t)s * (NG * DH) + j;
#pragma unroll
    for (int g = 0; g < NG; g++) {
        vo[g * DH]      = __float2half_rn(vrow[g * DH + j]);
        vo[g * DH + 64] = __float2half_rn(vrow[g * DH + j + 64]);
    }
}

// ---------------------------------------------------------------------------
// Tensorized flash attention (fp16 HMMA, causal, GQA) — unchanged (round 11).
// BM=64, 128 threads (4 warps), 2 CTAs/SM, heavy-first qb mapping.
// ---------------------------------------------------------------------------
#define AP 272
#define ATTN_KV (64 * AP)
#define ATTN_KVBUF (128 * AP)
#define ATTN_SMEM (ATTN_KV + 2 * ATTN_KVBUF)   // 87040 B

__global__ __launch_bounds__(128, 2)
void attn_mma(const __half* __restrict__ qh, const __half* __restrict__ kh,
              const __half* __restrict__ vh, __half* __restrict__ ch) {
    extern __shared__ char smc[];
    const uint32_t sb = smem_u32(smc);
    const int tid = threadIdx.x, w = tid >> 5, lane = tid & 31;
    const int qb = (int)gridDim.x - 1 - (int)blockIdx.x;
    const int h = blockIdx.y, g = h >> 2;
    const int q0 = qb * 64;
    const int R = q0 + w * 16;

    for (int c = tid; c < 1024; c += 128) {
        int row = c >> 4, u = c & 15;
        size_t go = (size_t)(q0 + row) * (NH * DH) + h * DH + u * 8;
        CP_ASYNC16(sb + row * AP + u * 16, (const char*)(qh + go));
    }
    CP_COMMIT();

    const int ntiles = qb + 1;

    {
        uint32_t b0 = sb + ATTN_KV;
        for (int c = tid; c < 1024; c += 128) {
            int row = c >> 4, u = c & 15;
            size_t go = (size_t)row * (NG * DH) + g * DH + u * 8;
            uint32_t s = b0 + row * AP + u * 16;
            CP_ASYNC16(s,           (const char*)(kh + go));
            CP_ASYNC16(s + 64 * AP, (const char*)(vh + go));
        }
        CP_COMMIT();
    }

    float o[16][4];
#pragma unroll
    for (int t = 0; t < 16; t++)
#pragma unroll
        for (int j = 0; j < 4; j++) o[t][j] = 0.f;
    float m_run[2] = {-1e30f, -1e30f};
    float l_run[2] = {0.f, 0.f};

    const float SC = 0.12751879523171918f;

    for (int kt = 0; kt < ntiles; kt++) {
        const int k0 = kt * 64;
        const int buf = kt & 1;
        if (kt + 1 < ntiles) {
            uint32_t b0 = sb + ATTN_KV + (uint32_t)(buf ^ 1) * ATTN_KVBUF;
            const int kn = (kt + 1) * 64;
            for (int c = tid; c < 1024; c += 128) {
                int row = c >> 4, u = c & 15;
                size_t go = (size_t)(kn + row) * (NG * DH) + g * DH + u * 8;
                uint32_t s = b0 + row * AP + u * 16;
                CP_ASYNC16(s,           (const char*)(kh + go));
                CP_ASYNC16(s + 64 * AP, (const char*)(vh + go));
            }
            CP_COMMIT();
            CP_WAIT1();
        } else {
            CP_WAIT0();
        }
        __syncthreads();

        {
            const uint32_t kb = sb + ATTN_KV + (uint32_t)buf * ATTN_KVBUF;

            float sS[8][4];
#pragma unroll
            for (int t = 0; t < 8; t++)
#pragma unroll
                for (int j = 0; j < 4; j++) sS[t][j] = 0.f;

            const uint32_t q_lane = (uint32_t)((w * 16 + (lane & 7) + ((lane >> 3) & 1) * 8) * AP);
            const uint32_t q_col  = (uint32_t)((lane >> 4) * 16);
#pragma unroll
            for (int kc8 = 0; kc8 < 8; kc8++) {
                uint32_t a0, a1, a2, a3;
                ldsm4(a0, a1, a2, a3, sb + q_lane + (uint32_t)(kc8 * 32) + q_col);
#pragma unroll
                for (int kg = 0; kg < 4; kg++) {
                    uint32_t ka = kb
                        + (uint32_t)((kg * 16 + ((lane >> 4) & 1) * 8 + (lane & 7)) * AP)
                        + (uint32_t)(kc8 * 32 + ((lane >> 3) & 1) * 16);
                    uint32_t b0, b1, b2, b3;
                    ldsm4(b0, b1, b2, b3, ka);
                    mma16816(sS[2 * kg],     a0, a1, a2, a3, b0, b1);
                    mma16816(sS[2 * kg + 1], a0, a1, a2, a3, b2, b3);
                }
            }

            const int r0 = R + (lane >> 2), r1 = r0 + 8;
            const bool diag = (k0 + 63 > R);
            float mt0 = -1e30f, mt1 = -1e30f;
#pragma unroll
            for (int t = 0; t < 8; t++) {
                int cb = k0 + t * 8 + 2 * (lane & 3);
                float s0 = sS[t][0] * SC, s1 = sS[t][1] * SC;
                float s2 = sS[t][2] * SC, s3 = sS[t][3] * SC;
                if (diag) {
                    if (cb     > r0) s0 = -1e30f;
                    if (cb + 1 > r0) s1 = -1e30f;
                    if (cb     > r1) s2 = -1e30f;
                    if (cb + 1 > r1) s3 = -1e30f;
                }
                sS[t][0] = s0; sS[t][1] = s1; sS[t][2] = s2; sS[t][3] = s3;
                mt0 = fmaxf(mt0, fmaxf(s0, s1));
                mt1 = fmaxf(mt1, fmaxf(s2, s3));
            }
            mt0 = fmaxf(mt0, __shfl_xor_sync(0xffffffffu, mt0, 1));
            mt0 = fmaxf(mt0, __shfl_xor_sync(0xffffffffu, mt0, 2));
            mt1 = fmaxf(mt1, __shfl_xor_sync(0xffffffffu, mt1, 1));
            mt1 = fmaxf(mt1, __shfl_xor_sync(0xffffffffu, mt1, 2));
            float mn0 = fmaxf(m_run[0], mt0), mn1 = fmaxf(m_run[1], mt1);
            float corr0 = ex2f(m_run[0] - mn0), corr1 = ex2f(m_run[1] - mn1);
            m_run[0] = mn0; m_run[1] = mn1;
            float ls0 = 0.f, ls1 = 0.f;
#pragma unroll
            for (int t = 0; t < 8; t++) {
                float p0 = ex2f(sS[t][0] - mn0), p1 = ex2f(sS[t][1] - mn0);
                float p2 = ex2f(sS[t][2] - mn1), p3 = ex2f(sS[t][3] - mn1);
                ls0 += p0 + p1; ls1 += p2 + p3;
                sS[t][0] = p0; sS[t][1] = p1; sS[t][2] = p2; sS[t][3] = p3;
            }
            ls0 += __shfl_xor_sync(0xffffffffu, ls0, 1);
            ls0 += __shfl_xor_sync(0xffffffffu, ls0, 2);
            ls1 += __shfl_xor_sync(0xffffffffu, ls1, 1);
            ls1 += __shfl_xor_sync(0xffffffffu, ls1, 2);
            l_run[0] = l_run[0] * corr0 + ls0;
            l_run[1] = l_run[1] * corr1 + ls1;
#pragma unroll
            for (int t = 0; t < 16; t++) {
                o[t][0] *= corr0; o[t][1] *= corr0;
                o[t][2] *= corr1; o[t][3] *= corr1;
            }

            uint32_t pa[4][4];
#pragma unroll
            for (int kc = 0; kc < 4; kc++) {
                pa[kc][0] = pack_half2(sS[2 * kc][0],     sS[2 * kc][1]);
                pa[kc][1] = pack_half2(sS[2 * kc][2],     sS[2 * kc][3]);
                pa[kc][2] = pack_half2(sS[2 * kc + 1][0], sS[2 * kc + 1][1]);
                pa[kc][3] = pack_half2(sS[2 * kc + 1][2], sS[2 * kc + 1][3]);
            }

#pragma unroll
            for (int kc = 0; kc < 4; kc++) {
#pragma unroll
                for (int dp = 0; dp < 8; dp++) {
                    uint32_t va = kb + 64 * AP
                        + (uint32_t)((kc * 16 + ((lane >> 3) & 1) * 8 + (lane & 7)) * AP)
                        + (uint32_t)(dp * 32 + ((lane >> 4) & 1) * 16);
                    uint32_t v0, v1, v2, v3;
                    ldsm4t(v0, v1, v2, v3, va);
                    mma16816(o[2 * dp],     pa[kc][0], pa[kc][1], pa[kc][2], pa[kc][3], v0, v1);
                    mma16816(o[2 * dp + 1], pa[kc][0], pa[kc][1], pa[kc][2], pa[kc][3], v2, v3);
                }
            }
        }
        __syncthreads();
    }

    float inv0 = 1.f / l_run[0], inv1 = 1.f / l_run[1];
    int r0 = R + (lane >> 2);
#pragma unroll
    for (int t = 0; t < 16; t++) {
        int col = t * 8 + 2 * (lane & 3);
        size_t o0 = (size_t)r0 * (NH * DH) + h * DH + col;
        size_t o1 = (size_t)(r0 + 8) * (NH * DH) + h * DH + col;
        *(uint32_t*)(ch + o0) = pack_half2(o[t][0] * inv0, o[t][1] * inv0);
        *(uint32_t*)(ch + o1) = pack_half2(o[t][2] * inv1, o[t][3] * inv1);
    }
}

// ---------------------------------------------------------------------------
// Launch
// ---------------------------------------------------------------------------
extern "C" void kernel_launch(void* const* d_in, const int* in_sizes, int n_in,
                              void* d_out, int out_size) {
    const float* X  = (const float*)d_in[0];
    const float* Wq = (const float*)d_in[1];
    const float* bq = (const float*)d_in[2];
    const float* Wk = (const float*)d_in[3];
    const float* bk = (const float*)d_in[4];
    const float* Wv = (const float*)d_in[5];
    const float* bv = (const float*)d_in[6];
    const float* Wo = (const float*)d_in[7];
    const float* bo = (const float*)d_in[8];
    float* out = (float*)d_out;

    void* p;
    cudaGetSymbolAddress(&p, g_qkv);  float* qkv = (float*)p;
    cudaGetSymbolAddress(&p, g_bqkv); float* bqkv = (float*)p;
    cudaGetSymbolAddress(&p, g_xh);   __half* xh = (__half*)p;
    cudaGetSymbolAddress(&p, g_ch);   __half* chp = (__half*)p;
    cudaGetSymbolAddress(&p, g_qh);   __half* qhp = (__half*)p;
    cudaGetSymbolAddress(&p, g_kh);   __half* khp = (__half*)p;
    cudaGetSymbolAddress(&p, g_vh);   __half* vhp = (__half*)p;
    cudaGetSymbolAddress(&p, g_wqkv); __half* wqkv = (__half*)p;
    cudaGetSymbolAddress(&p, g_wo);   __half* wo = (__half*)p;

    cudaFuncSetAttribute(mma_gemm, cudaFuncAttributeMaxDynamicSharedMemorySize,
                         GEMM_SMEM_BYTES);
    cudaFuncSetAttribute(attn_mma, cudaFuncAttributeMaxDynamicSharedMemorySize,
                         ATTN_SMEM);

    // 0: bias concat   1: ALL weights fp16 (native layout)   2: X fp16
    bias_concat<<<(NQKV + 255) / 256, 256>>>(bq, bk, bv, bqkv);
    wcvt<<<(WTOT4 + 255) / 256, 256>>>((const float4*)Wq, (const float4*)Wk,
                                       (const float4*)Wv, (const float4*)Wo,
                                       (__half2*)wqkv, (__half2*)wo);
    {
        int n4 = S_LEN * HID / 4;
        cvt_half<<<(n4 + 255) / 256, 256>>>((const float4*)X, (__half2*)xh, n4);
    }

    // 3: fused QKV projection (B native [K,6144])
    mma_gemm<<<dim3(NQKV / 128, S_LEN / 128), 256, GEMM_SMEM_BYTES>>>(
        xh, wqkv, bqkv, qkv, S_LEN, NQKV, HID);

    // 4: RoPE + fp16 convert for q, k, v
    rope_cvt<<<(S_LEN * 64 + 255) / 256, 256>>>(qkv, qhp, khp, vhp);

    // 5: attention
    attn_mma<<<dim3(S_LEN / 64, NH), 128, ATTN_SMEM>>>(qhp, khp, vhp, chp);

    // 6: output projection (B native [K,4096])
    mma_gemm<<<dim3(HID / 128, S_LEN / 128), 256, GEMM_SMEM_BYTES>>>(
        chp, wo, bo, out, S_LEN, HID, NH * DH);
}

// round 16
// speedup vs baseline: 11.1439x; 1.0099x over previous
#include <cuda.h>
#include <cuda_runtime.h>
#include <cuda_fp16.h>
#include <math.h>

// ---------------------------------------------------------------------------
// Problem constants
// ---------------------------------------------------------------------------
#define S_LEN 2048
#define HID   4096
#define NH    32
#define NG    8
#define DH    128
#define NQKV  6144   // HID + 2*NG*DH

// ---------------------------------------------------------------------------
// Device-global scratch (allocation-free rule)
// ---------------------------------------------------------------------------
__device__ __align__(16) float g_qkv[S_LEN * NQKV];     // fused QKV output (fp32)
__device__ __align__(16) float g_bqkv[NQKV];            // concat bias

__device__ __align__(16) __half g_xh[S_LEN * HID];
__device__ __align__(16) __half g_ch[S_LEN * HID];      // ctx (fp16, from attention)
__device__ __align__(16) __half g_qh[S_LEN * NH * DH];
__device__ __align__(16) __half g_kh[S_LEN * NG * DH];
__device__ __align__(16) __half g_vh[S_LEN * NG * DH];
__device__ __align__(16) __half g_wqkv[HID * NQKV];     // [Wq|Wk|Wv] [K=4096, N=6144] fp16
__device__ __align__(16) __half g_wo[HID * HID];        // Wo [K,N] fp16 (native layout)

// ---------------------------------------------------------------------------
// PTX helpers (sm_80-baseline: ldmatrix / mma.sync / cp.async)
// ---------------------------------------------------------------------------
__device__ __forceinline__ uint32_t smem_u32(const void* p) {
    uint32_t a;
    asm("{ .reg .u64 t; cvta.to.shared.u64 t, %1; cvt.u32.u64 %0, t; }"
        : "=r"(a) : "l"(p));
    return a;
}

__device__ __forceinline__ void ldsm4(uint32_t& r0, uint32_t& r1, uint32_t& r2,
                                      uint32_t& r3, uint32_t addr) {
    asm volatile("ldmatrix.sync.aligned.m8n8.x4.shared.b16 {%0,%1,%2,%3}, [%4];"
                 : "=r"(r0), "=r"(r1), "=r"(r2), "=r"(r3) : "r"(addr));
}

__device__ __forceinline__ void ldsm4t(uint32_t& r0, uint32_t& r1, uint32_t& r2,
                                       uint32_t& r3, uint32_t addr) {
    asm volatile("ldmatrix.sync.aligned.m8n8.x4.trans.shared.b16 {%0,%1,%2,%3}, [%4];"
                 : "=r"(r0), "=r"(r1), "=r"(r2), "=r"(r3) : "r"(addr));
}

__device__ __forceinline__ void mma16816(float* d, uint32_t a0, uint32_t a1,
                                         uint32_t a2, uint32_t a3,
                                         uint32_t b0, uint32_t b1) {
    asm volatile(
        "mma.sync.aligned.m16n8k16.row.col.f32.f16.f16.f32 "
        "{%0,%1,%2,%3}, {%4,%5,%6,%7}, {%8,%9}, {%0,%1,%2,%3};"
        : "+f"(d[0]), "+f"(d[1]), "+f"(d[2]), "+f"(d[3])
        : "r"(a0), "r"(a1), "r"(a2), "r"(a3), "r"(b0), "r"(b1));
}

__device__ __forceinline__ float ex2f(float x) {
    float r;
    asm("ex2.approx.ftz.f32 %0, %1;" : "=f"(r) : "f"(x));
    return r;
}

__device__ __forceinline__ uint32_t pack_half2(float a, float b) {
    __half2 h = __floats2half2_rn(a, b);
    return *(uint32_t*)&h;
}

#define CP_ASYNC16(smem_addr, gptr) \
    asm volatile("cp.async.cg.shared.global [%0], [%1], 16;" \
                 :: "r"(smem_addr), "l"(gptr))
#define CP_COMMIT() asm volatile("cp.async.commit_group;" ::: "memory")
#define CP_WAIT0()  asm volatile("cp.async.wait_group 0;" ::: "memory")
#define CP_WAIT1()  asm volatile("cp.async.wait_group 1;" ::: "memory")

// ---------------------------------------------------------------------------
// fp32 -> fp16, same layout. n4 = n/4 float4s.
// ---------------------------------------------------------------------------
__global__ void cvt_half(const float4* __restrict__ src, __half2* __restrict__ dst, int n4) {
    int i = blockIdx.x * blockDim.x + threadIdx.x;
    if (i >= n4) return;
    float4 v = src[i];
    dst[2 * i]     = __floats2half2_rn(v.x, v.y);
    dst[2 * i + 1] = __floats2half2_rn(v.z, v.w);
}

// ---------------------------------------------------------------------------
// Merged weight convert (NO transpose): Wq/Wk/Wv -> fused [K,6144] fp16,
// Wo -> [K,N] fp16. One fully-coalesced pass over all weights.
// ---------------------------------------------------------------------------
#define Q4 (HID * HID / 4)
#define K4 (HID * 1024 / 4)
#define WTOT4 (2 * Q4 + 2 * K4)

__global__ void wcvt(const float4* __restrict__ Wq, const float4* __restrict__ Wk,
                     const float4* __restrict__ Wv, const float4* __restrict__ Wo,
                     __half2* __restrict__ fused, __half2* __restrict__ wo) {
    size_t i = (size_t)blockIdx.x * blockDim.x + threadIdx.x;
    if (i >= WTOT4) return;
    float4 v;
    __half2* out;
    size_t d;
    if (i < Q4) {
        size_t j = i * 4;
        v = Wq[i];
        d = (j >> 12) * (size_t)NQKV + (j & 4095);
        out = fused;
    } else if (i < Q4 + K4) {
        size_t j = (i - Q4) * 4;
        v = Wk[i - Q4];
        d = (j >> 10) * (size_t)NQKV + 4096 + (j & 1023);
        out = fused;
    } else if (i < Q4 + 2 * K4) {
        size_t j = (i - Q4 - K4) * 4;
        v = Wv[i - Q4 - K4];
        d = (j >> 10) * (size_t)NQKV + 5120 + (j & 1023);
        out = fused;
    } else {
        size_t ii = i - Q4 - 2 * K4;
        v = Wo[ii];
        d = ii * 4;
        out = wo;
    }
    out[d >> 1]       = __floats2half2_rn(v.x, v.y);
    out[(d >> 1) + 1] = __floats2half2_rn(v.z, v.w);
}

// ---------------------------------------------------------------------------
// Concat biases [bq | bk | bv] -> g_bqkv[6144]
// ---------------------------------------------------------------------------
__global__ void bias_concat(const float* __restrict__ bq, const float* __restrict__ bk,
                            const float* __restrict__ bv, float* __restrict__ b) {
    int i = blockIdx.x * blockDim.x + threadIdx.x;
    if (i >= NQKV) return;
    if (i < HID)             b[i] = bq[i];
    else if (i < HID + 1024) b[i] = bk[i - HID];
    else                     b[i] = bv[i - HID - 1024];
}

// ---------------------------------------------------------------------------
// HMMA fp16 GEMM: C[M,N] = A[M,K] @ B[K,N] + bias
// A: [M,K] K-contig.  B: [K,N] N-contig (native, ldmatrix.trans fragments).
// NEW: 4 warps (128 thr), warp tile 64x64 (2x2 grid) -> LDSM:HMMA 0.375->0.25
// (dispatch-slot model). CTA tile 128x128, BK=64, 3-stage ring, reg
// double-buffered fragments. Per-accumulator MMA order over K unchanged.
// ---------------------------------------------------------------------------
#define AROWB 144
#define BROWB 272
#define A_BYTES (128 * AROWB)
#define STAGE_BYTES (A_BYTES + 64 * BROWB)
#define GEMM_SMEM_BYTES (3 * STAGE_BYTES)   // 107520

__global__ __launch_bounds__(128, 2)
void mma_gemm(const __half* __restrict__ A, const __half* __restrict__ B,
              const float* __restrict__ bias, float* __restrict__ C,
              int M, int N, int K) {
    extern __shared__ char smc[];
    const uint32_t sb = smem_u32(smc);
    const int tid = threadIdx.x;
    const int w = tid >> 5, lane = tid & 31;
    const int wm = w >> 1;            // 0..1 -> 64-row strip
    const int wn = w & 1;             // 0..1 -> 64-col strip
    const int m0 = blockIdx.y * 128;
    const int n0 = blockIdx.x * 128;

    // cp.async: A 128 rows x 8 units, B 64 rows x 16 units; 8 each per thread.
    size_t ga[8], gb[8];
    uint32_t soA[8], soB[8];
#pragma unroll
    for (int t = 0; t < 8; t++) {
        int i = tid + t * 128;
        int arow = i >> 3, au = i & 7;
        ga[t]  = (size_t)(m0 + arow) * K + au * 8;
        soA[t] = (uint32_t)(arow * AROWB + au * 16);
        int brow = i >> 4, bu = i & 15;
        gb[t]  = (size_t)brow * N + n0 + bu * 8;
        soB[t] = (uint32_t)(A_BYTES + brow * BROWB + bu * 16);
    }

    const int NC = K >> 6;

    // Prologue: stage chunks 0 and 1
#pragma unroll
    for (int s = 0; s < 2; s++) {
        const size_t kcA = (size_t)s << 6;
        const size_t kcB = (size_t)s * 64 * N;
        const uint32_t dst = sb + (uint32_t)s * STAGE_BYTES;
#pragma unroll
        for (int t = 0; t < 8; t++) {
            CP_ASYNC16(dst + soA[t], (const char*)(A + ga[t] + kcA));
            CP_ASYNC16(dst + soB[t], (const char*)(B + gb[t] + kcB));
        }
        CP_COMMIT();
    }

    float acc[4][8][4];
#pragma unroll
    for (int mi = 0; mi < 4; mi++)
#pragma unroll
        for (int ni = 0; ni < 8; ni++)
#pragma unroll
            for (int j = 0; j < 4; j++) acc[mi][ni][j] = 0.f;

    const int lr = lane & 15, lc = lane >> 4;
    const uint32_t a_lane_off = (uint32_t)((wm * 64 + lr) * AROWB + lc * 16);
    const uint32_t b_lane_row = (uint32_t)((((lane >> 3) & 1) * 8 + (lane & 7)) * BROWB);
    const uint32_t b_lane_col = (uint32_t)(wn * 128 + ((lane >> 4) & 1) * 16);

    int bufc = 0;   // buffer index of chunk c (mod 3)
    for (int c = 0; c < NC; c++) {
        if (c + 1 < NC) { CP_WAIT1(); } else { CP_WAIT0(); }
        __syncthreads();

        // Issue chunk c+2 into the buffer read at chunk c-1 (just fenced).
        if (c + 2 < NC) {
            int bufn = bufc + 2; if (bufn >= 3) bufn -= 3;
            const size_t kcA = (size_t)(c + 2) << 6;
            const size_t kcB = (size_t)(c + 2) * 64 * N;
            const uint32_t dst = sb + (uint32_t)bufn * STAGE_BYTES;
#pragma unroll
            for (int t = 0; t < 8; t++) {
                CP_ASYNC16(dst + soA[t], (const char*)(A + ga[t] + kcA));
                CP_ASYNC16(dst + soB[t], (const char*)(B + gb[t] + kcB));
            }
            CP_COMMIT();
        }

        const uint32_t base  = sb + (uint32_t)bufc * STAGE_BYTES;
        const uint32_t abase = base + a_lane_off;
        const uint32_t bbase = base + A_BYTES + b_lane_row + b_lane_col;

        // Preload ks=0 B fragments (8 n-groups) and (ks=0, mi=0) A fragment
        uint32_t bcur[8][2], bnxt[8][2];
        uint32_t acur[4], anxt[4];
#pragma unroll
        for (int ni16 = 0; ni16 < 4; ni16++) {
            uint32_t v0, v1, v2, v3;
            ldsm4t(v0, v1, v2, v3, bbase + (uint32_t)(ni16 * 32));
            bcur[ni16 * 2][0] = v0; bcur[ni16 * 2][1] = v1;
            bcur[ni16 * 2 + 1][0] = v2; bcur[ni16 * 2 + 1][1] = v3;
        }
        ldsm4(acur[0], acur[1], acur[2], acur[3], abase);

#pragma unroll
        for (int ks = 0; ks < 4; ks++) {
            // Prefetch next ks's B fragments while this ks's MMAs run
            if (ks < 3) {
                const uint32_t nb = bbase + (uint32_t)((ks + 1) * 16) * BROWB;
#pragma unroll
                for (int ni16 = 0; ni16 < 4; ni16++) {
                    uint32_t v0, v1, v2, v3;
                    ldsm4t(v0, v1, v2, v3, nb + (uint32_t)(ni16 * 32));
                    bnxt[ni16 * 2][0] = v0; bnxt[ni16 * 2][1] = v1;
                    bnxt[ni16 * 2 + 1][0] = v2; bnxt[ni16 * 2 + 1][1] = v3;
                }
            }
            const uint32_t koff = (uint32_t)(ks * 32);
#pragma unroll
            for (int mi = 0; mi < 4; mi++) {
                if (mi < 3) {
                    ldsm4(anxt[0], anxt[1], anxt[2], anxt[3],
                          abase + (uint32_t)((mi + 1) * 16 * AROWB) + koff);
                } else if (ks < 3) {
                    ldsm4(anxt[0], anxt[1], anxt[2], anxt[3],
                          abase + (uint32_t)((ks + 1) * 32));
                }
#pragma unroll
                for (int ni = 0; ni < 8; ni++)
                    mma16816(acc[mi][ni], acur[0], acur[1], acur[2], acur[3],
                             bcur[ni][0], bcur[ni][1]);
                acur[0] = anxt[0]; acur[1] = anxt[1];
                acur[2] = anxt[2]; acur[3] = anxt[3];
            }
#pragma unroll
            for (int q = 0; q < 8; q++) {
                bcur[q][0] = bnxt[q][0]; bcur[q][1] = bnxt[q][1];
            }
        }
        bufc++; if (bufc >= 3) bufc = 0;
    }

#pragma unroll
    for (int mi = 0; mi < 4; mi++) {
#pragma unroll
        for (int ni = 0; ni < 8; ni++) {
            int m = m0 + wm * 64 + mi * 16 + (lane >> 2);
            int n = n0 + wn * 64 + ni * 8 + 2 * (lane & 3);
            float2 bv = *(const float2*)&bias[n];
            float2 o0 = make_float2(acc[mi][ni][0] + bv.x, acc[mi][ni][1] + bv.y);
            float2 o1 = make_float2(acc[mi][ni][2] + bv.x, acc[mi][ni][3] + bv.y);
            *(float2*)&C[(size_t)m * N + n]       = o0;
            *(float2*)&C[(size_t)(m + 8) * N + n] = o1;
        }
    }
}

// ---------------------------------------------------------------------------
// RoPE + fp16 convert, fused for q, k AND v (reads fused qkv, stride 6144).
// ---------------------------------------------------------------------------
__global__ void rope_cvt(const float* __restrict__ qkv,
                         __half* __restrict__ qh, __half* __restrict__ kh,
                         __half* __restrict__ vh) {
    int idx = blockIdx.x * blockDim.x + threadIdx.x;
    if (idx >= S_LEN * 64) return;
    int j = idx & 63;
    int s = idx >> 6;
    float inv = (float)exp(-(double)j * (9.210340371976184 / 64.0));
    float ang = (float)s * inv;
    float sn, cs;
    sincosf(ang, &sn, &cs);
    const float* row = qkv + (size_t)s * NQKV;

    __half* qo = qh + (size_t)s * (NH * DH) + j;
#pragma unroll
    for (int h = 0; h < NH; h++) {
        float x1 = row[h * DH + j];
        float x2 = row[h * DH + j + 64];
        qo[h * DH]      = __float2half_rn(x1 * cs - x2 * sn);
        qo[h * DH + 64] = __float2half_rn(x1 * sn + x2 * cs);
    }
    const float* krow = row + HID;
    __half* ko = kh + (size_t)s * (NG * DH) + j;
#pragma unroll
    for (int g = 0; g < NG; g++) {
        float x1 = krow[g * DH + j];
        float x2 = krow[g * DH + j + 64];
        ko[g * DH]      = __float2half_rn(x1 * cs - x2 * sn);
        ko[g * DH + 64] = __float2half_rn(x1 * sn + x2 * cs);
    }
    const float* vrow = row + HID + 1024;
    __half* vo = vh + (size_t)s * (NG * DH) + j;
#pragma unroll
    for (int g = 0; g < NG; g++) {
        vo[g * DH]      = __float2half_rn(vrow[g * DH + j]);
        vo[g * DH + 64] = __float2half_rn(vrow[g * DH + j + 64]);
    }
}

// ---------------------------------------------------------------------------
// Tensorized flash attention (fp16 HMMA, causal, GQA) — unchanged (round 11).
// BM=64, 128 threads (4 warps), 2 CTAs/SM, heavy-first qb mapping.
// ---------------------------------------------------------------------------
#define AP 272
#define ATTN_KV (64 * AP)
#define ATTN_KVBUF (128 * AP)
#define ATTN_SMEM (ATTN_KV + 2 * ATTN_KVBUF)   // 87040 B

__global__ __launch_bounds__(128, 2)
void attn_mma(const __half* __restrict__ qh, const __half* __restrict__ kh,
              const __half* __restrict__ vh, __half* __restrict__ ch) {
    extern __shared__ char smc[];
    const uint32_t sb = smem_u32(smc);
    const int tid = threadIdx.x, w = tid >> 5, lane = tid & 31;
    const int qb = (int)gridDim.x - 1 - (int)blockIdx.x;
    const int h = blockIdx.y, g = h >> 2;
    const int q0 = qb * 64;
    const int R = q0 + w * 16;

    for (int c = tid; c < 1024; c += 128) {
        int row = c >> 4, u = c & 15;
        size_t go = (size_t)(q0 + row) * (NH * DH) + h * DH + u * 8;
        CP_ASYNC16(sb + row * AP + u * 16, (const char*)(qh + go));
    }
    CP_COMMIT();

    const int ntiles = qb + 1;

    {
        uint32_t b0 = sb + ATTN_KV;
        for (int c = tid; c < 1024; c += 128) {
            int row = c >> 4, u = c & 15;
            size_t go = (size_t)row * (NG * DH) + g * DH + u * 8;
            uint32_t s = b0 + row * AP + u * 16;
            CP_ASYNC16(s,           (const char*)(kh + go));
            CP_ASYNC16(s + 64 * AP, (const char*)(vh + go));
        }
        CP_COMMIT();
    }

    float o[16][4];
#pragma unroll
    for (int t = 0; t < 16; t++)
#pragma unroll
        for (int j = 0; j < 4; j++) o[t][j] = 0.f;
    float m_run[2] = {-1e30f, -1e30f};
    float l_run[2] = {0.f, 0.f};

    const float SC = 0.12751879523171918f;

    for (int kt = 0; kt < ntiles; kt++) {
        const int k0 = kt * 64;
        const int buf = kt & 1;
        if (kt + 1 < ntiles) {
            uint32_t b0 = sb + ATTN_KV + (uint32_t)(buf ^ 1) * ATTN_KVBUF;
            const int kn = (kt + 1) * 64;
            for (int c = tid; c < 1024; c += 128) {
                int row = c >> 4, u = c & 15;
                size_t go = (size_t)(kn + row) * (NG * DH) + g * DH + u * 8;
                uint32_t s = b0 + row * AP + u * 16;
                CP_ASYNC16(s,           (const char*)(kh + go));
                CP_ASYNC16(s + 64 * AP, (const char*)(vh + go));
            }
            CP_COMMIT();
            CP_WAIT1();
        } else {
            CP_WAIT0();
        }
        __syncthreads();

        {
            const uint32_t kb = sb + ATTN_KV + (uint32_t)buf * ATTN_KVBUF;

            float sS[8][4];
#pragma unroll
            for (int t = 0; t < 8; t++)
#pragma unroll
                for (int j = 0; j < 4; j++) sS[t][j] = 0.f;

            const uint32_t q_lane = (uint32_t)((w * 16 + (lane & 7) + ((lane >> 3) & 1) * 8) * AP);
            const uint32_t q_col  = (uint32_t)((lane >> 4) * 16);
#pragma unroll
            for (int kc8 = 0; kc8 < 8; kc8++) {
                uint32_t a0, a1, a2, a3;
                ldsm4(a0, a1, a2, a3, sb + q_lane + (uint32_t)(kc8 * 32) + q_col);
#pragma unroll
                for (int kg = 0; kg < 4; kg++) {
                    uint32_t ka = kb
                        + (uint32_t)((kg * 16 + ((lane >> 4) & 1) * 8 + (lane & 7)) * AP)
                        + (uint32_t)(kc8 * 32 + ((lane >> 3) & 1) * 16);
                    uint32_t b0, b1, b2, b3;
                    ldsm4(b0, b1, b2, b3, ka);
                    mma16816(sS[2 * kg],     a0, a1, a2, a3, b0, b1);
                    mma16816(sS[2 * kg + 1], a0, a1, a2, a3, b2, b3);
                }
            }

            const int r0 = R + (lane >> 2), r1 = r0 + 8;
            const bool diag = (k0 + 63 > R);
            float mt0 = -1e30f, mt1 = -1e30f;
#pragma unroll
            for (int t = 0; t < 8; t++) {
                int cb = k0 + t * 8 + 2 * (lane & 3);
                float s0 = sS[t][0] * SC, s1 = sS[t][1] * SC;
                float s2 = sS[t][2] * SC, s3 = sS[t][3] * SC;
                if (diag) {
                    if (cb     > r0) s0 = -1e30f;
                    if (cb + 1 > r0) s1 = -1e30f;
                    if (cb     > r1) s2 = -1e30f;
                    if (cb + 1 > r1) s3 = -1e30f;
                }
                sS[t][0] = s0; sS[t][1] = s1; sS[t][2] = s2; sS[t][3] = s3;
                mt0 = fmaxf(mt0, fmaxf(s0, s1));
                mt1 = fmaxf(mt1, fmaxf(s2, s3));
            }
            mt0 = fmaxf(mt0, __shfl_xor_sync(0xffffffffu, mt0, 1));
            mt0 = fmaxf(mt0, __shfl_xor_sync(0xffffffffu, mt0, 2));
            mt1 = fmaxf(mt1, __shfl_xor_sync(0xffffffffu, mt1, 1));
            mt1 = fmaxf(mt1, __shfl_xor_sync(0xffffffffu, mt1, 2));
            float mn0 = fmaxf(m_run[0], mt0), mn1 = fmaxf(m_run[1], mt1);
            float corr0 = ex2f(m_run[0] - mn0), corr1 = ex2f(m_run[1] - mn1);
            m_run[0] = mn0; m_run[1] = mn1;
            float ls0 = 0.f, ls1 = 0.f;
#pragma unroll
            for (int t = 0; t < 8; t++) {
                float p0 = ex2f(sS[t][0] - mn0), p1 = ex2f(sS[t][1] - mn0);
                float p2 = ex2f(sS[t][2] - mn1), p3 = ex2f(sS[t][3] - mn1);
                ls0 += p0 + p1; ls1 += p2 + p3;
                sS[t][0] = p0; sS[t][1] = p1; sS[t][2] = p2; sS[t][3] = p3;
            }
            ls0 += __shfl_xor_sync(0xffffffffu, ls0, 1);
            ls0 += __shfl_xor_sync(0xffffffffu, ls0, 2);
            ls1 += __shfl_xor_sync(0xffffffffu, ls1, 1);
            ls1 += __shfl_xor_sync(0xffffffffu, ls1, 2);
            l_run[0] = l_run[0] * corr0 + ls0;
            l_run[1] = l_run[1] * corr1 + ls1;
#pragma unroll
            for (int t = 0; t < 16; t++) {
                o[t][0] *= corr0; o[t][1] *= corr0;
                o[t][2] *= corr1; o[t][3] *= corr1;
            }

            uint32_t pa[4][4];
#pragma unroll
            for (int kc = 0; kc < 4; kc++) {
                pa[kc][0] = pack_half2(sS[2 * kc][0],     sS[2 * kc][1]);
                pa[kc][1] = pack_half2(sS[2 * kc][2],     sS[2 * kc][3]);
                pa[kc][2] = pack_half2(sS[2 * kc + 1][0], sS[2 * kc + 1][1]);
                pa[kc][3] = pack_half2(sS[2 * kc + 1][2], sS[2 * kc + 1][3]);
            }

#pragma unroll
            for (int kc = 0; kc < 4; kc++) {
#pragma unroll
                for (int dp = 0; dp < 8; dp++) {
                    uint32_t va = kb + 64 * AP
                        + (uint32_t)((kc * 16 + ((lane >> 3) & 1) * 8 + (lane & 7)) * AP)
                        + (uint32_t)(dp * 32 + ((lane >> 4) & 1) * 16);
                    uint32_t v0, v1, v2, v3;
                    ldsm4t(v0, v1, v2, v3, va);
                    mma16816(o[2 * dp],     pa[kc][0], pa[kc][1], pa[kc][2], pa[kc][3], v0, v1);
                    mma16816(o[2 * dp + 1], pa[kc][0], pa[kc][1], pa[kc][2], pa[kc][3], v2, v3);
                }
            }
        }
        __syncthreads();
    }

    float inv0 = 1.f / l_run[0], inv1 = 1.f / l_run[1];
    int r0 = R + (lane >> 2);
#pragma unroll
    for (int t = 0; t < 16; t++) {
        int col = t * 8 + 2 * (lane & 3);
        size_t o0 = (size_t)r0 * (NH * DH) + h * DH + col;
        size_t o1 = (size_t)(r0 + 8) * (NH * DH) + h * DH + col;
        *(uint32_t*)(ch + o0) = pack_half2(o[t][0] * inv0, o[t][1] * inv0);
        *(uint32_t*)(ch + o1) = pack_half2(o[t][2] * inv1, o[t][3] * inv1);
    }
}

// ---------------------------------------------------------------------------
// Launch
// ---------------------------------------------------------------------------
extern "C" void kernel_launch(void* const* d_in, const int* in_sizes, int n_in,
                              void* d_out, int out_size) {
    const float* X  = (const float*)d_in[0];
    const float* Wq = (const float*)d_in[1];
    const float* bq = (const float*)d_in[2];
    const float* Wk = (const float*)d_in[3];
    const float* bk = (const float*)d_in[4];
    const float* Wv = (const float*)d_in[5];
    const float* bv = (const float*)d_in[6];
    const float* Wo = (const float*)d_in[7];
    const float* bo = (const float*)d_in[8];
    float* out = (float*)d_out;

    void* p;
    cudaGetSymbolAddress(&p, g_qkv);  float* qkv = (float*)p;
    cudaGetSymbolAddress(&p, g_bqkv); float* bqkv = (float*)p;
    cudaGetSymbolAddress(&p, g_xh);   __half* xh = (__half*)p;
    cudaGetSymbolAddress(&p, g_ch);   __half* chp = (__half*)p;
    cudaGetSymbolAddress(&p, g_qh);   __half* qhp = (__half*)p;
    cudaGetSymbolAddress(&p, g_kh);   __half* khp = (__half*)p;
    cudaGetSymbolAddress(&p, g_vh);   __half* vhp = (__half*)p;
    cudaGetSymbolAddress(&p, g_wqkv); __half* wqkv = (__half*)p;
    cudaGetSymbolAddress(&p, g_wo);   __half* wo = (__half*)p;

    cudaFuncSetAttribute(mma_gemm, cudaFuncAttributeMaxDynamicSharedMemorySize,
                         GEMM_SMEM_BYTES);
    cudaFuncSetAttribute(attn_mma, cudaFuncAttributeMaxDynamicSharedMemorySize,
                         ATTN_SMEM);

    // 0: bias concat   1: ALL weights fp16 (native layout)   2: X fp16
    bias_concat<<<(NQKV + 255) / 256, 256>>>(bq, bk, bv, bqkv);
    wcvt<<<(WTOT4 + 255) / 256, 256>>>((const float4*)Wq, (const float4*)Wk,
                                       (const float4*)Wv, (const float4*)Wo,
                                       (__half2*)wqkv, (__half2*)wo);
    {
        int n4 = S_LEN * HID / 4;
        cvt_half<<<(n4 + 255) / 256, 256>>>((const float4*)X, (__half2*)xh, n4);
    }

    // 3: fused QKV projection (B native [K,6144])
    mma_gemm<<<dim3(NQKV / 128, S_LEN / 128), 128, GEMM_SMEM_BYTES>>>(
        xh, wqkv, bqkv, qkv, S_LEN, NQKV, HID);

    // 4: RoPE + fp16 convert for q, k, v
    rope_cvt<<<(S_LEN * 64 + 255) / 256, 256>>>(qkv, qhp, khp, vhp);

    // 5: attention
    attn_mma<<<dim3(S_LEN / 64, NH), 128, ATTN_SMEM>>>(qhp, khp, vhp, chp);

    // 6: output projection (B native [K,4096])
    mma_gemm<<<dim3(HID / 128, S_LEN / 128), 128, GEMM_SMEM_BYTES>>>(
        chp, wo, bo, out, S_LEN, HID, NH * DH);
}

// round 17
// speedup vs baseline: 11.7695x; 1.0561x over previous
#include <cuda.h>
#include <cuda_runtime.h>
#include <cuda_fp16.h>
#include <math.h>

// ---------------------------------------------------------------------------
// Problem constants
// ---------------------------------------------------------------------------
#define S_LEN 2048
#define HID   4096
#define NH    32
#define NG    8
#define DH    128
#define NQKV  6144   // HID + 2*NG*DH

// ---------------------------------------------------------------------------
// Device-global scratch (allocation-free rule)
// ---------------------------------------------------------------------------
__device__ __align__(16) float g_bqkv[NQKV];            // concat bias

__device__ __align__(16) __half g_xh[S_LEN * HID];
__device__ __align__(16) __half g_ch[S_LEN * HID];      // ctx (fp16, from attention)
__device__ __align__(16) __half g_qh[S_LEN * NH * DH];
__device__ __align__(16) __half g_kh[S_LEN * NG * DH];
__device__ __align__(16) __half g_vh[S_LEN * NG * DH];
__device__ __align__(16) __half g_wqkv[HID * NQKV];     // [Wq|Wk|Wv] [K=4096, N=6144] fp16
__device__ __align__(16) __half g_wo[HID * HID];        // Wo [K,N] fp16 (native layout)

// ---------------------------------------------------------------------------
// PTX helpers (sm_80-baseline: ldmatrix / mma.sync / cp.async)
// ---------------------------------------------------------------------------
__device__ __forceinline__ uint32_t smem_u32(const void* p) {
    uint32_t a;
    asm("{ .reg .u64 t; cvta.to.shared.u64 t, %1; cvt.u32.u64 %0, t; }"
        : "=r"(a) : "l"(p));
    return a;
}

__device__ __forceinline__ void ldsm4(uint32_t& r0, uint32_t& r1, uint32_t& r2,
                                      uint32_t& r3, uint32_t addr) {
    asm volatile("ldmatrix.sync.aligned.m8n8.x4.shared.b16 {%0,%1,%2,%3}, [%4];"
                 : "=r"(r0), "=r"(r1), "=r"(r2), "=r"(r3) : "r"(addr));
}

__device__ __forceinline__ void ldsm4t(uint32_t& r0, uint32_t& r1, uint32_t& r2,
                                       uint32_t& r3, uint32_t addr) {
    asm volatile("ldmatrix.sync.aligned.m8n8.x4.trans.shared.b16 {%0,%1,%2,%3}, [%4];"
                 : "=r"(r0), "=r"(r1), "=r"(r2), "=r"(r3) : "r"(addr));
}

__device__ __forceinline__ void mma16816(float* d, uint32_t a0, uint32_t a1,
                                         uint32_t a2, uint32_t a3,
                                         uint32_t b0, uint32_t b1) {
    asm volatile(
        "mma.sync.aligned.m16n8k16.row.col.f32.f16.f16.f32 "
        "{%0,%1,%2,%3}, {%4,%5,%6,%7}, {%8,%9}, {%0,%1,%2,%3};"
        : "+f"(d[0]), "+f"(d[1]), "+f"(d[2]), "+f"(d[3])
        : "r"(a0), "r"(a1), "r"(a2), "r"(a3), "r"(b0), "r"(b1));
}

__device__ __forceinline__ float ex2f(float x) {
    float r;
    asm("ex2.approx.ftz.f32 %0, %1;" : "=f"(r) : "f"(x));
    return r;
}

__device__ __forceinline__ uint32_t pack_half2(float a, float b) {
    __half2 h = __floats2half2_rn(a, b);
    return *(uint32_t*)&h;
}

#define CP_ASYNC16(smem_addr, gptr) \
    asm volatile("cp.async.cg.shared.global [%0], [%1], 16;" \
                 :: "r"(smem_addr), "l"(gptr))
#define CP_COMMIT() asm volatile("cp.async.commit_group;" ::: "memory")
#define CP_WAIT0()  asm volatile("cp.async.wait_group 0;" ::: "memory")
#define CP_WAIT1()  asm volatile("cp.async.wait_group 1;" ::: "memory")

// ---------------------------------------------------------------------------
// fp32 -> fp16, same layout. n4 = n/4 float4s.
// ---------------------------------------------------------------------------
__global__ void cvt_half(const float4* __restrict__ src, __half2* __restrict__ dst, int n4) {
    int i = blockIdx.x * blockDim.x + threadIdx.x;
    if (i >= n4) return;
    float4 v = src[i];
    dst[2 * i]     = __floats2half2_rn(v.x, v.y);
    dst[2 * i + 1] = __floats2half2_rn(v.z, v.w);
}

// ---------------------------------------------------------------------------
// Merged weight convert (NO transpose): Wq/Wk/Wv -> fused [K,6144] fp16,
// Wo -> [K,N] fp16. One fully-coalesced pass over all weights.
// ---------------------------------------------------------------------------
#define Q4 (HID * HID / 4)
#define K4 (HID * 1024 / 4)
#define WTOT4 (2 * Q4 + 2 * K4)

__global__ void wcvt(const float4* __restrict__ Wq, const float4* __restrict__ Wk,
                     const float4* __restrict__ Wv, const float4* __restrict__ Wo,
                     __half2* __restrict__ fused, __half2* __restrict__ wo) {
    size_t i = (size_t)blockIdx.x * blockDim.x + threadIdx.x;
    if (i >= WTOT4) return;
    float4 v;
    __half2* out;
    size_t d;
    if (i < Q4) {
        size_t j = i * 4;
        v = Wq[i];
        d = (j >> 12) * (size_t)NQKV + (j & 4095);
        out = fused;
    } else if (i < Q4 + K4) {
        size_t j = (i - Q4) * 4;
        v = Wk[i - Q4];
        d = (j >> 10) * (size_t)NQKV + 4096 + (j & 1023);
        out = fused;
    } else if (i < Q4 + 2 * K4) {
        size_t j = (i - Q4 - K4) * 4;
        v = Wv[i - Q4 - K4];
        d = (j >> 10) * (size_t)NQKV + 5120 + (j & 1023);
        out = fused;
    } else {
        size_t ii = i - Q4 - 2 * K4;
        v = Wo[ii];
        d = ii * 4;
        out = wo;
    }
    out[d >> 1]       = __floats2half2_rn(v.x, v.y);
    out[(d >> 1) + 1] = __floats2half2_rn(v.z, v.w);
}

// ---------------------------------------------------------------------------
// Concat biases [bq | bk | bv] -> g_bqkv[6144]
// ---------------------------------------------------------------------------
__global__ void bias_concat(const float* __restrict__ bq, const float* __restrict__ bk,
                            const float* __restrict__ bv, float* __restrict__ b) {
    int i = blockIdx.x * blockDim.x + threadIdx.x;
    if (i >= NQKV) return;
    if (i < HID)             b[i] = bq[i];
    else if (i < HID + 1024) b[i] = bk[i - HID];
    else                     b[i] = bv[i - HID - 1024];
}

// ---------------------------------------------------------------------------
// HMMA fp16 GEMM: C[M,N] = A[M,K] @ B[K,N] + bias
// Mainloop unchanged (round 16; at the legacy-HMMA ceiling).
// NEW mode=1 epilogue (QKV only): stage fp32 tile (+bias) in smem, apply
// RoPE in-register (identical formula to old rope_cvt -> bit-exact), write
// fp16 qh/kh/vh directly. mode=0: plain fp32 C + bias (O projection).
// ---------------------------------------------------------------------------
#define AROWB 144
#define BROWB 272
#define A_BYTES (128 * AROWB)
#define STAGE_BYTES (A_BYTES + 64 * BROWB)
#define GEMM_SMEM_BYTES (3 * STAGE_BYTES)   // 107520

__global__ __launch_bounds__(128, 2)
void mma_gemm(const __half* __restrict__ A, const __half* __restrict__ B,
              const float* __restrict__ bias, float* __restrict__ C,
              __half* __restrict__ qh, __half* __restrict__ kh,
              __half* __restrict__ vh,
              int M, int N, int K, int mode) {
    extern __shared__ char smc[];
    const uint32_t sb = smem_u32(smc);
    const int tid = threadIdx.x;
    const int w = tid >> 5, lane = tid & 31;
    const int wm = w >> 1;            // 0..1 -> 64-row strip
    const int wn = w & 1;             // 0..1 -> 64-col strip
    const int m0 = blockIdx.y * 128;
    const int n0 = blockIdx.x * 128;

    size_t ga[8], gb[8];
    uint32_t soA[8], soB[8];
#pragma unroll
    for (int t = 0; t < 8; t++) {
        int i = tid + t * 128;
        int arow = i >> 3, au = i & 7;
        ga[t]  = (size_t)(m0 + arow) * K + au * 8;
        soA[t] = (uint32_t)(arow * AROWB + au * 16);
        int brow = i >> 4, bu = i & 15;
        gb[t]  = (size_t)brow * N + n0 + bu * 8;
        soB[t] = (uint32_t)(A_BYTES + brow * BROWB + bu * 16);
    }

    const int NC = K >> 6;

    // Prologue: stage chunks 0 and 1
#pragma unroll
    for (int s = 0; s < 2; s++) {
        const size_t kcA = (size_t)s << 6;
        const size_t kcB = (size_t)s * 64 * N;
        const uint32_t dst = sb + (uint32_t)s * STAGE_BYTES;
#pragma unroll
        for (int t = 0; t < 8; t++) {
            CP_ASYNC16(dst + soA[t], (const char*)(A + ga[t] + kcA));
            CP_ASYNC16(dst + soB[t], (const char*)(B + gb[t] + kcB));
        }
        CP_COMMIT();
    }

    float acc[4][8][4];
#pragma unroll
    for (int mi = 0; mi < 4; mi++)
#pragma unroll
        for (int ni = 0; ni < 8; ni++)
#pragma unroll
            for (int j = 0; j < 4; j++) acc[mi][ni][j] = 0.f;

    const int lr = lane & 15, lc = lane >> 4;
    const uint32_t a_lane_off = (uint32_t)((wm * 64 + lr) * AROWB + lc * 16);
    const uint32_t b_lane_row = (uint32_t)((((lane >> 3) & 1) * 8 + (lane & 7)) * BROWB);
    const uint32_t b_lane_col = (uint32_t)(wn * 128 + ((lane >> 4) & 1) * 16);

    int bufc = 0;   // buffer index of chunk c (mod 3)
    for (int c = 0; c < NC; c++) {
        if (c + 1 < NC) { CP_WAIT1(); } else { CP_WAIT0(); }
        __syncthreads();

        if (c + 2 < NC) {
            int bufn = bufc + 2; if (bufn >= 3) bufn -= 3;
            const size_t kcA = (size_t)(c + 2) << 6;
            const size_t kcB = (size_t)(c + 2) * 64 * N;
            const uint32_t dst = sb + (uint32_t)bufn * STAGE_BYTES;
#pragma unroll
            for (int t = 0; t < 8; t++) {
                CP_ASYNC16(dst + soA[t], (const char*)(A + ga[t] + kcA));
                CP_ASYNC16(dst + soB[t], (const char*)(B + gb[t] + kcB));
            }
            CP_COMMIT();
        }

        const uint32_t base  = sb + (uint32_t)bufc * STAGE_BYTES;
        const uint32_t abase = base + a_lane_off;
        const uint32_t bbase = base + A_BYTES + b_lane_row + b_lane_col;

        uint32_t bcur[8][2], bnxt[8][2];
        uint32_t acur[4], anxt[4];
#pragma unroll
        for (int ni16 = 0; ni16 < 4; ni16++) {
            uint32_t v0, v1, v2, v3;
            ldsm4t(v0, v1, v2, v3, bbase + (uint32_t)(ni16 * 32));
            bcur[ni16 * 2][0] = v0; bcur[ni16 * 2][1] = v1;
            bcur[ni16 * 2 + 1][0] = v2; bcur[ni16 * 2 + 1][1] = v3;
        }
        ldsm4(acur[0], acur[1], acur[2], acur[3], abase);

#pragma unroll
        for (int ks = 0; ks < 4; ks++) {
            if (ks < 3) {
                const uint32_t nb = bbase + (uint32_t)((ks + 1) * 16) * BROWB;
#pragma unroll
                for (int ni16 = 0; ni16 < 4; ni16++) {
                    uint32_t v0, v1, v2, v3;
                    ldsm4t(v0, v1, v2, v3, nb + (uint32_t)(ni16 * 32));
                    bnxt[ni16 * 2][0] = v0; bnxt[ni16 * 2][1] = v1;
                    bnxt[ni16 * 2 + 1][0] = v2; bnxt[ni16 * 2 + 1][1] = v3;
                }
            }
            const uint32_t koff = (uint32_t)(ks * 32);
#pragma unroll
            for (int mi = 0; mi < 4; mi++) {
                if (mi < 3) {
                    ldsm4(anxt[0], anxt[1], anxt[2], anxt[3],
                          abase + (uint32_t)((mi + 1) * 16 * AROWB) + koff);
                } else if (ks < 3) {
                    ldsm4(anxt[0], anxt[1], anxt[2], anxt[3],
                          abase + (uint32_t)((ks + 1) * 32));
                }
#pragma unroll
                for (int ni = 0; ni < 8; ni++)
                    mma16816(acc[mi][ni], acur[0], acur[1], acur[2], acur[3],
                             bcur[ni][0], bcur[ni][1]);
                acur[0] = anxt[0]; acur[1] = anxt[1];
                acur[2] = anxt[2]; acur[3] = anxt[3];
            }
#pragma unroll
            for (int q = 0; q < 8; q++) {
                bcur[q][0] = bnxt[q][0]; bcur[q][1] = bnxt[q][1];
            }
        }
        bufc++; if (bufc >= 3) bufc = 0;
    }

    if (mode == 0) {
        // Plain epilogue: C = acc + bias (fp32)
#pragma unroll
        for (int mi = 0; mi < 4; mi++) {
#pragma unroll
            for (int ni = 0; ni < 8; ni++) {
                int m = m0 + wm * 64 + mi * 16 + (lane >> 2);
                int n = n0 + wn * 64 + ni * 8 + 2 * (lane & 3);
                float2 bv = *(const float2*)&bias[n];
                float2 o0 = make_float2(acc[mi][ni][0] + bv.x, acc[mi][ni][1] + bv.y);
                float2 o1 = make_float2(acc[mi][ni][2] + bv.x, acc[mi][ni][3] + bv.y);
                *(float2*)&C[(size_t)m * N + n]       = o0;
                *(float2*)&C[(size_t)(m + 8) * N + n] = o1;
            }
        }
    } else {
        // QKV epilogue: stage fp32 tile, apply RoPE (q,k) / convert (v),
        // write fp16 directly. Bit-exact with the old rope_cvt pass.
        __syncthreads();    // mainloop smem reads done in all warps
        float* st = (float*)smc;   // [128][130] padded fp32 staging
#pragma unroll
        for (int mi = 0; mi < 4; mi++) {
#pragma unroll
            for (int ni = 0; ni < 8; ni++) {
                int ml = wm * 64 + mi * 16 + (lane >> 2);
                int nl = wn * 64 + ni * 8 + 2 * (lane & 3);
                float2 bv = *(const float2*)&bias[n0 + nl];
                st[ml * 130 + nl]           = acc[mi][ni][0] + bv.x;
                st[ml * 130 + nl + 1]       = acc[mi][ni][1] + bv.y;
                st[(ml + 8) * 130 + nl]     = acc[mi][ni][2] + bv.x;
                st[(ml + 8) * 130 + nl + 1] = acc[mi][ni][3] + bv.y;
            }
        }
        __syncthreads();

        const int j = tid & 63;
        float inv = (float)exp(-(double)j * (9.210340371976184 / 64.0));
        __half* outp;
        int rowstride, colbase, do_rope;
        if (n0 < HID)             { outp = qh; rowstride = NH * DH; colbase = n0;               do_rope = 1; }
        else if (n0 < HID + 1024) { outp = kh; rowstride = NG * DH; colbase = n0 - HID;         do_rope = 1; }
        else                      { outp = vh; rowstride = NG * DH; colbase = n0 - HID - 1024;  do_rope = 0; }

        for (int p = tid; p < 8192; p += 128) {
            int r = p >> 6;
            float x1 = st[r * 130 + j];
            float x2 = st[r * 130 + j + 64];
            size_t o = (size_t)(m0 + r) * rowstride + colbase + j;
            if (do_rope) {
                float ang = (float)(m0 + r) * inv;
                float sn, cs;
                sincosf(ang, &sn, &cs);
                outp[o]      = __float2half_rn(x1 * cs - x2 * sn);
                outp[o + 64] = __float2half_rn(x1 * sn + x2 * cs);
            } else {
                outp[o]      = __float2half_rn(x1);
                outp[o + 64] = __float2half_rn(x2);
            }
        }
    }
}

// ---------------------------------------------------------------------------
// Tensorized flash attention (fp16 HMMA, causal, GQA) — unchanged (round 11).
// BM=64, 128 threads (4 warps), 2 CTAs/SM, heavy-first qb mapping.
// ---------------------------------------------------------------------------
#define AP 272
#define ATTN_KV (64 * AP)
#define ATTN_KVBUF (128 * AP)
#define ATTN_SMEM (ATTN_KV + 2 * ATTN_KVBUF)   // 87040 B

__global__ __launch_bounds__(128, 2)
void attn_mma(const __half* __restrict__ qh, const __half* __restrict__ kh,
              const __half* __restrict__ vh, __half* __restrict__ ch) {
    extern __shared__ char smc[];
    const uint32_t sb = smem_u32(smc);
    const int tid = threadIdx.x, w = tid >> 5, lane = tid & 31;
    const int qb = (int)gridDim.x - 1 - (int)blockIdx.x;
    const int h = blockIdx.y, g = h >> 2;
    const int q0 = qb * 64;
    const int R = q0 + w * 16;

    for (int c = tid; c < 1024; c += 128) {
        int row = c >> 4, u = c & 15;
        size_t go = (size_t)(q0 + row) * (NH * DH) + h * DH + u * 8;
        CP_ASYNC16(sb + row * AP + u * 16, (const char*)(qh + go));
    }
    CP_COMMIT();

    const int ntiles = qb + 1;

    {
        uint32_t b0 = sb + ATTN_KV;
        for (int c = tid; c < 1024; c += 128) {
            int row = c >> 4, u = c & 15;
            size_t go = (size_t)row * (NG * DH) + g * DH + u * 8;
            uint32_t s = b0 + row * AP + u * 16;
            CP_ASYNC16(s,           (const char*)(kh + go));
            CP_ASYNC16(s + 64 * AP, (const char*)(vh + go));
        }
        CP_COMMIT();
    }

    float o[16][4];
#pragma unroll
    for (int t = 0; t < 16; t++)
#pragma unroll
        for (int j = 0; j < 4; j++) o[t][j] = 0.f;
    float m_run[2] = {-1e30f, -1e30f};
    float l_run[2] = {0.f, 0.f};

    const float SC = 0.12751879523171918f;

    for (int kt = 0; kt < ntiles; kt++) {
        const int k0 = kt * 64;
        const int buf = kt & 1;
        if (kt + 1 < ntiles) {
            uint32_t b0 = sb + ATTN_KV + (uint32_t)(buf ^ 1) * ATTN_KVBUF;
            const int kn = (kt + 1) * 64;
            for (int c = tid; c < 1024; c += 128) {
                int row = c >> 4, u = c & 15;
                size_t go = (size_t)(kn + row) * (NG * DH) + g * DH + u * 8;
                uint32_t s = b0 + row * AP + u * 16;
                CP_ASYNC16(s,           (const char*)(kh + go));
                CP_ASYNC16(s + 64 * AP, (const char*)(vh + go));
            }
            CP_COMMIT();
            CP_WAIT1();
        } else {
            CP_WAIT0();
        }
        __syncthreads();

        {
            const uint32_t kb = sb + ATTN_KV + (uint32_t)buf * ATTN_KVBUF;

            float sS[8][4];
#pragma unroll
            for (int t = 0; t < 8; t++)
#pragma unroll
                for (int j = 0; j < 4; j++) sS[t][j] = 0.f;

            const uint32_t q_lane = (uint32_t)((w * 16 + (lane & 7) + ((lane >> 3) & 1) * 8) * AP);
            const uint32_t q_col  = (uint32_t)((lane >> 4) * 16);
#pragma unroll
            for (int kc8 = 0; kc8 < 8; kc8++) {
                uint32_t a0, a1, a2, a3;
                ldsm4(a0, a1, a2, a3, sb + q_lane + (uint32_t)(kc8 * 32) + q_col);
#pragma unroll
                for (int kg = 0; kg < 4; kg++) {
                    uint32_t ka = kb
                        + (uint32_t)((kg * 16 + ((lane >> 4) & 1) * 8 + (lane & 7)) * AP)
                        + (uint32_t)(kc8 * 32 + ((lane >> 3) & 1) * 16);
                    uint32_t b0, b1, b2, b3;
                    ldsm4(b0, b1, b2, b3, ka);
                    mma16816(sS[2 * kg],     a0, a1, a2, a3, b0, b1);
                    mma16816(sS[2 * kg + 1], a0, a1, a2, a3, b2, b3);
                }
            }

            const int r0 = R + (lane >> 2), r1 = r0 + 8;
            const bool diag = (k0 + 63 > R);
            float mt0 = -1e30f, mt1 = -1e30f;
#pragma unroll
            for (int t = 0; t < 8; t++) {
                int cb = k0 + t * 8 + 2 * (lane & 3);
                float s0 = sS[t][0] * SC, s1 = sS[t][1] * SC;
                float s2 = sS[t][2] * SC, s3 = sS[t][3] * SC;
                if (diag) {
                    if (cb     > r0) s0 = -1e30f;
                    if (cb + 1 > r0) s1 = -1e30f;
                    if (cb     > r1) s2 = -1e30f;
                    if (cb + 1 > r1) s3 = -1e30f;
                }
                sS[t][0] = s0; sS[t][1] = s1; sS[t][2] = s2; sS[t][3] = s3;
                mt0 = fmaxf(mt0, fmaxf(s0, s1));
                mt1 = fmaxf(mt1, fmaxf(s2, s3));
            }
            mt0 = fmaxf(mt0, __shfl_xor_sync(0xffffffffu, mt0, 1));
            mt0 = fmaxf(mt0, __shfl_xor_sync(0xffffffffu, mt0, 2));
            mt1 = fmaxf(mt1, __shfl_xor_sync(0xffffffffu, mt1, 1));
            mt1 = fmaxf(mt1, __shfl_xor_sync(0xffffffffu, mt1, 2));
            float mn0 = fmaxf(m_run[0], mt0), mn1 = fmaxf(m_run[1], mt1);
            float corr0 = ex2f(m_run[0] - mn0), corr1 = ex2f(m_run[1] - mn1);
            m_run[0] = mn0; m_run[1] = mn1;
            float ls0 = 0.f, ls1 = 0.f;
#pragma unroll
            for (int t = 0; t < 8; t++) {
                float p0 = ex2f(sS[t][0] - mn0), p1 = ex2f(sS[t][1] - mn0);
                float p2 = ex2f(sS[t][2] - mn1), p3 = ex2f(sS[t][3] - mn1);
                ls0 += p0 + p1; ls1 += p2 + p3;
                sS[t][0] = p0; sS[t][1] = p1; sS[t][2] = p2; sS[t][3] = p3;
            }
            ls0 += __shfl_xor_sync(0xffffffffu, ls0, 1);
            ls0 += __shfl_xor_sync(0xffffffffu, ls0, 2);
            ls1 += __shfl_xor_sync(0xffffffffu, ls1, 1);
            ls1 += __shfl_xor_sync(0xffffffffu, ls1, 2);
            l_run[0] = l_run[0] * corr0 + ls0;
            l_run[1] = l_run[1] * corr1 + ls1;
#pragma unroll
            for (int t = 0; t < 16; t++) {
                o[t][0] *= corr0; o[t][1] *= corr0;
                o[t][2] *= corr1; o[t][3] *= corr1;
            }

            uint32_t pa[4][4];
#pragma unroll
            for (int kc = 0; kc < 4; kc++) {
                pa[kc][0] = pack_half2(sS[2 * kc][0],     sS[2 * kc][1]);
                pa[kc][1] = pack_half2(sS[2 * kc][2],     sS[2 * kc][3]);
                pa[kc][2] = pack_half2(sS[2 * kc + 1][0], sS[2 * kc + 1][1]);
                pa[kc][3] = pack_half2(sS[2 * kc + 1][2], sS[2 * kc + 1][3]);
            }

#pragma unroll
            for (int kc = 0; kc < 4; kc++) {
#pragma unroll
                for (int dp = 0; dp < 8; dp++) {
                    uint32_t va = kb + 64 * AP
                        + (uint32_t)((kc * 16 + ((lane >> 3) & 1) * 8 + (lane & 7)) * AP)
                        + (uint32_t)(dp * 32 + ((lane >> 4) & 1) * 16);
                    uint32_t v0, v1, v2, v3;
                    ldsm4t(v0, v1, v2, v3, va);
                    mma16816(o[2 * dp],     pa[kc][0], pa[kc][1], pa[kc][2], pa[kc][3], v0, v1);
                    mma16816(o[2 * dp + 1], pa[kc][0], pa[kc][1], pa[kc][2], pa[kc][3], v2, v3);
                }
            }
        }
        __syncthreads();
    }

    float inv0 = 1.f / l_run[0], inv1 = 1.f / l_run[1];
    int r0 = R + (lane >> 2);
#pragma unroll
    for (int t = 0; t < 16; t++) {
        int col = t * 8 + 2 * (lane & 3);
        size_t o0 = (size_t)r0 * (NH * DH) + h * DH + col;
        size_t o1 = (size_t)(r0 + 8) * (NH * DH) + h * DH + col;
        *(uint32_t*)(ch + o0) = pack_half2(o[t][0] * inv0, o[t][1] * inv0);
        *(uint32_t*)(ch + o1) = pack_half2(o[t][2] * inv1, o[t][3] * inv1);
    }
}

// ---------------------------------------------------------------------------
// Launch
// ---------------------------------------------------------------------------
extern "C" void kernel_launch(void* const* d_in, const int* in_sizes, int n_in,
                              void* d_out, int out_size) {
    const float* X  = (const float*)d_in[0];
    const float* Wq = (const float*)d_in[1];
    const float* bq = (const float*)d_in[2];
    const float* Wk = (const float*)d_in[3];
    const float* bk = (const float*)d_in[4];
    const float* Wv = (const float*)d_in[5];
    const float* bv = (const float*)d_in[6];
    const float* Wo = (const float*)d_in[7];
    const float* bo = (const float*)d_in[8];
    float* out = (float*)d_out;

    void* p;
    cudaGetSymbolAddress(&p, g_bqkv); float* bqkv = (float*)p;
    cudaGetSymbolAddress(&p, g_xh);   __half* xh = (__half*)p;
    cudaGetSymbolAddress(&p, g_ch);   __half* chp = (__half*)p;
    cudaGetSymbolAddress(&p, g_qh);   __half* qhp = (__half*)p;
    cudaGetSymbolAddress(&p, g_kh);   __half* khp = (__half*)p;
    cudaGetSymbolAddress(&p, g_vh);   __half* vhp = (__half*)p;
    cudaGetSymbolAddress(&p, g_wqkv); __half* wqkv = (__half*)p;
    cudaGetSymbolAddress(&p, g_wo);   __half* wo = (__half*)p;

    cudaFuncSetAttribute(mma_gemm, cudaFuncAttributeMaxDynamicSharedMemorySize,
                         GEMM_SMEM_BYTES);
    cudaFuncSetAttribute(attn_mma, cudaFuncAttributeMaxDynamicSharedMemorySize,
                         ATTN_SMEM);

    // 0: bias concat   1: ALL weights fp16 (native layout)   2: X fp16
    bias_concat<<<(NQKV + 255) / 256, 256>>>(bq, bk, bv, bqkv);
    wcvt<<<(WTOT4 + 255) / 256, 256>>>((const float4*)Wq, (const float4*)Wk,
                                       (const float4*)Wv, (const float4*)Wo,
                                       (__half2*)wqkv, (__half2*)wo);
    {
        int n4 = S_LEN * HID / 4;
        cvt_half<<<(n4 + 255) / 256, 256>>>((const float4*)X, (__half2*)xh, n4);
    }

    // 3: fused QKV projection + RoPE + fp16 convert (mode 1)
    mma_gemm<<<dim3(NQKV / 128, S_LEN / 128), 128, GEMM_SMEM_BYTES>>>(
        xh, wqkv, bqkv, (float*)nullptr, qhp, khp, vhp, S_LEN, NQKV, HID, 1);

    // 4: attention
    attn_mma<<<dim3(S_LEN / 64, NH), 128, ATTN_SMEM>>>(qhp, khp, vhp, chp);

    // 5: output projection (mode 0)
    mma_gemm<<<dim3(HID / 128, S_LEN / 128), 128, GEMM_SMEM_BYTES>>>(
        chp, wo, bo, out, (__half*)nullptr, (__half*)nullptr, (__half*)nullptr,
        S_LEN, HID, NH * DH, 0);
}